// round 1
// baseline (speedup 1.0000x reference)
#include <cuda_runtime.h>
#include <math.h>

// Problem constants
#define Bn 16
#define Nn 512
#define Dn 256
#define Hn 8
#define Ln 4
#define DKn 32

#define BND (Bn*Nn*Dn)   // 2,097,152
#define BNN (Bn*Nn*Nn)   // 4,194,304

// Scratch (no cudaMalloc allowed)
static __device__ float g_x[BND];
static __device__ float g_h[BND];
static __device__ float g_q[BND];
static __device__ float g_k[BND];
static __device__ float g_v[BND];
static __device__ float g_att[BND];
static __device__ float g_t1[BND];
static __device__ float g_base[BNN];

// ---------------------------------------------------------------------------
// Block reductions (256 threads)
// ---------------------------------------------------------------------------
__device__ __forceinline__ float blockSum256(float v) {
    __shared__ float sm[8];
    __syncthreads();                       // protect smem reuse across calls
    #pragma unroll
    for (int o = 16; o; o >>= 1) v += __shfl_xor_sync(0xffffffffu, v, o);
    if ((threadIdx.x & 31) == 0) sm[threadIdx.x >> 5] = v;
    __syncthreads();
    float t = 0.f;
    #pragma unroll
    for (int i = 0; i < 8; i++) t += sm[i];
    return t;
}

__device__ __forceinline__ float blockMax256(float v) {
    __shared__ float sm[8];
    __syncthreads();
    #pragma unroll
    for (int o = 16; o; o >>= 1) v = fmaxf(v, __shfl_xor_sync(0xffffffffu, v, o));
    if ((threadIdx.x & 31) == 0) sm[threadIdx.x >> 5] = v;
    __syncthreads();
    float t = sm[0];
    #pragma unroll
    for (int i = 1; i < 8; i++) t = fmaxf(t, sm[i]);
    return t;
}

// ---------------------------------------------------------------------------
// base[b,i,j] = 0.3 * softmax_j(mask ? -dist : -inf) + 0.4 * adj / (sum_adj+eps)
// one block per (b,i); 256 threads, 2 columns each
// ---------------------------------------------------------------------------
__global__ void base_kernel(const float* __restrict__ dist,
                            const float* __restrict__ adj,
                            const int*   __restrict__ mask,
                            float* __restrict__ base) {
    const int bi = blockIdx.x;
    const int b  = bi >> 9;                 // / Nn
    const float* dr = dist + (size_t)bi * Nn;
    const float* ar = adj  + (size_t)bi * Nn;
    float*       br = base + (size_t)bi * Nn;
    const int t = threadIdx.x;

    const int m0 = mask[b * Nn + t];
    const int m1 = mask[b * Nn + t + 256];
    float v0 = m0 ? -dr[t]       : -INFINITY;
    float v1 = m1 ? -dr[t + 256] : -INFINITY;

    float mx = blockMax256(fmaxf(v0, v1));
    float e0 = __expf(v0 - mx);
    float e1 = __expf(v1 - mx);
    float ssum = blockSum256(e0 + e1);

    float a0 = ar[t], a1 = ar[t + 256];
    float asum = blockSum256(a0 + a1);

    float cs = 0.3f / ssum;
    float ca = 0.4f / (asum + 1e-6f);
    br[t]       = e0 * cs + a0 * ca;
    br[t + 256] = e1 * cs + a1 * ca;
}

// ---------------------------------------------------------------------------
// LayerNorm with ddof=1: out = a*(x-m)/(std+1e-6)+b ; one block per row (D=256)
// ---------------------------------------------------------------------------
__global__ void ln_kernel(const float* __restrict__ x,
                          const float* __restrict__ a,
                          const float* __restrict__ bb,
                          float* __restrict__ out) {
    const size_t row = blockIdx.x;
    const int d = threadIdx.x;
    float v = x[row * Dn + d];
    float mean = blockSum256(v) * (1.f / Dn);
    float c = v - mean;
    float var = blockSum256(c * c) * (1.f / (Dn - 1));
    float s = sqrtf(var);
    out[row * Dn + d] = a[d] * c / (s + 1e-6f) + bb[d];
}

// ---------------------------------------------------------------------------
// Generic tiled SGEMM: C = act(A@W + bias) (+ res), batched via blockIdx.z.
// A: (M,K) row-major, W: (K,Nc) row-major. BM=BN=64, BK=16, 256 thr, 4x4 micro.
// act: 0 none, 1 leaky(0.1)
// ---------------------------------------------------------------------------
__global__ void sgemm_kernel(const float* __restrict__ A,
                             const float* __restrict__ W,
                             const float* __restrict__ bias,
                             const float* __restrict__ res,
                             float* __restrict__ C,
                             int M, int Nc, int K,
                             long sA, long sW, long sC, int act) {
    A += (size_t)blockIdx.z * sA;
    W += (size_t)blockIdx.z * sW;
    C += (size_t)blockIdx.z * sC;
    if (res) res += (size_t)blockIdx.z * sC;

    const int tm = blockIdx.y * 64;
    const int tn = blockIdx.x * 64;

    __shared__ float As[16][64];   // [k][m]
    __shared__ float Bs[16][64];   // [k][n]

    const int tid  = threadIdx.x;
    const int tr   = (tid >> 4) << 2;   // 0..60 step 4
    const int tc   = (tid & 15) << 2;
    const int arow = tid >> 2;          // 0..63
    const int acol = (tid & 3) << 2;    // 0,4,8,12
    const int brow = tid >> 4;          // 0..15
    const int bcol = (tid & 15) << 2;

    float acc[4][4] = {};

    for (int k0 = 0; k0 < K; k0 += 16) {
        float4 av = *(const float4*)(A + (size_t)(tm + arow) * K + k0 + acol);
        float4 bv = *(const float4*)(W + (size_t)(k0 + brow) * Nc + tn + bcol);
        __syncthreads();
        As[acol + 0][arow] = av.x;
        As[acol + 1][arow] = av.y;
        As[acol + 2][arow] = av.z;
        As[acol + 3][arow] = av.w;
        *(float4*)&Bs[brow][bcol] = bv;
        __syncthreads();
        #pragma unroll
        for (int kk = 0; kk < 16; kk++) {
            float4 a4 = *(const float4*)&As[kk][tr];
            float4 b4 = *(const float4*)&Bs[kk][tc];
            float ai[4] = {a4.x, a4.y, a4.z, a4.w};
            float bj[4] = {b4.x, b4.y, b4.z, b4.w};
            #pragma unroll
            for (int i = 0; i < 4; i++)
                #pragma unroll
                for (int j = 0; j < 4; j++)
                    acc[i][j] += ai[i] * bj[j];
        }
    }

    #pragma unroll
    for (int i = 0; i < 4; i++) {
        const size_t row = tm + tr + i;
        #pragma unroll
        for (int j = 0; j < 4; j++) {
            const int col = tn + tc + j;
            float v = acc[i][j];
            if (bias) v += bias[col];
            if (act)  v = v > 0.f ? v : 0.1f * v;
            if (res)  v += res[row * Nc + col];
            C[row * Nc + col] = v;
        }
    }
}

// ---------------------------------------------------------------------------
// Flash attention (softmax part only): att += 0.3 * softmax(mask(qk^T/s)) @ v
// thread = one query row of one (b,h); 128 threads/block; kv tiles of 64 in smem
// ---------------------------------------------------------------------------
__global__ void attn_kernel(const float* __restrict__ q,
                            const float* __restrict__ k,
                            const float* __restrict__ v,
                            const int*   __restrict__ mask,
                            float* __restrict__ att) {
    const int b = blockIdx.z, h = blockIdx.y;
    const int row = blockIdx.x * 128 + threadIdx.x;

    __shared__ float ks[64][32];
    __shared__ float vs[64][32];
    __shared__ int   ms[64];

    const size_t qoff = ((size_t)(b * Nn) + row) * Dn + h * DKn;
    float qr[32];
    #pragma unroll
    for (int c = 0; c < 8; c++) {
        float4 t = *(const float4*)(q + qoff + c * 4);
        qr[c*4+0] = t.x; qr[c*4+1] = t.y; qr[c*4+2] = t.z; qr[c*4+3] = t.w;
    }

    float acc[32];
    #pragma unroll
    for (int d = 0; d < 32; d++) acc[d] = 0.f;
    float m = -INFINITY, l = 0.f;
    const float scale = 0.17677669529663687f;   // 1/sqrt(32)

    for (int kt = 0; kt < Nn / 64; kt++) {
        __syncthreads();
        for (int t = threadIdx.x; t < 512; t += 128) {
            int r = t >> 3, c = (t & 7) << 2;
            size_t off = ((size_t)(b * Nn) + kt * 64 + r) * Dn + h * DKn + c;
            *(float4*)&ks[r][c] = *(const float4*)(k + off);
            *(float4*)&vs[r][c] = *(const float4*)(v + off);
        }
        if (threadIdx.x < 64) ms[threadIdx.x] = mask[b * Nn + kt * 64 + threadIdx.x];
        __syncthreads();

        for (int j = 0; j < 64; j++) {
            float s = 0.f;
            #pragma unroll
            for (int d = 0; d < 32; d++) s += qr[d] * ks[j][d];
            s = ms[j] ? s * scale : -1e12f;
            float nm = fmaxf(m, s);
            float sc = __expf(m - nm);
            float p  = __expf(s - nm);
            l = l * sc + p;
            #pragma unroll
            for (int d = 0; d < 32; d++) acc[d] = acc[d] * sc + p * vs[j][d];
            m = nm;
        }
    }

    const float inv = 0.3f / l;
    float* o = att + qoff;
    #pragma unroll
    for (int d = 0; d < 32; d++) o[d] += acc[d] * inv;
}

// ---------------------------------------------------------------------------
// Launch
// ---------------------------------------------------------------------------
extern "C" void kernel_launch(void* const* d_in, const int* in_sizes, int n_in,
                              void* d_out, int out_size) {
    const float* x_in  = (const float*)d_in[0];
    const int*   mask  = (const int*)  d_in[1];
    const float* adj   = (const float*)d_in[2];
    const float* dist  = (const float*)d_in[3];
    const float* Wq    = (const float*)d_in[5];
    const float* bq    = (const float*)d_in[6];
    const float* Wk    = (const float*)d_in[7];
    const float* bk    = (const float*)d_in[8];
    const float* Wv    = (const float*)d_in[9];
    const float* bv    = (const float*)d_in[10];
    const float* Wo    = (const float*)d_in[11];
    const float* bo    = (const float*)d_in[12];
    const float* Wf1   = (const float*)d_in[13];
    const float* bf1   = (const float*)d_in[14];
    const float* Wf2   = (const float*)d_in[15];
    const float* bf2   = (const float*)d_in[16];
    const float* ln1a  = (const float*)d_in[17];
    const float* ln1b  = (const float*)d_in[18];
    const float* ln2a  = (const float*)d_in[19];
    const float* ln2b  = (const float*)d_in[20];
    const float* lnfa  = (const float*)d_in[21];
    const float* lnfb  = (const float*)d_in[22];

    float *px, *ph, *pq, *pk, *pv, *patt, *pt1, *pbase;
    cudaGetSymbolAddress((void**)&px,    g_x);
    cudaGetSymbolAddress((void**)&ph,    g_h);
    cudaGetSymbolAddress((void**)&pq,    g_q);
    cudaGetSymbolAddress((void**)&pk,    g_k);
    cudaGetSymbolAddress((void**)&pv,    g_v);
    cudaGetSymbolAddress((void**)&patt,  g_att);
    cudaGetSymbolAddress((void**)&pt1,   g_t1);
    cudaGetSymbolAddress((void**)&pbase, g_base);

    cudaMemcpyAsync(px, x_in, sizeof(float) * BND, cudaMemcpyDeviceToDevice, 0);

    base_kernel<<<Bn * Nn, 256>>>(dist, adj, mask, pbase);

    const dim3 gProj(Dn / 64, (Bn * Nn) / 64, 1);   // (4,128,1)
    const dim3 gBaseV(Dn / 64, Nn / 64, Bn);        // (4,8,16)
    const dim3 gAttn(Nn / 128, Hn, Bn);             // (4,8,16)
    const int M = Bn * Nn;

    for (int i = 0; i < Ln; i++) {
        const size_t wOff = (size_t)i * Dn * Dn;
        const size_t vOff = (size_t)i * Dn;

        ln_kernel<<<Bn * Nn, 256>>>(px, ln1a + vOff, ln1b + vOff, ph);

        sgemm_kernel<<<gProj, 256>>>(ph, Wq + wOff, bq + vOff, nullptr, pq,
                                     M, Dn, Dn, 0, 0, 0, 0);
        sgemm_kernel<<<gProj, 256>>>(ph, Wk + wOff, bk + vOff, nullptr, pk,
                                     M, Dn, Dn, 0, 0, 0, 0);
        sgemm_kernel<<<gProj, 256>>>(ph, Wv + wOff, bv + vOff, nullptr, pv,
                                     M, Dn, Dn, 0, 0, 0, 0);

        // att = base @ V  (head-independent part of p, pre-scaled)
        sgemm_kernel<<<gBaseV, 256>>>(pbase, pv, nullptr, nullptr, patt,
                                      Nn, Dn, Nn,
                                      (long)Nn * Nn, (long)Nn * Dn, (long)Nn * Dn, 0);

        // att += 0.3 * softmax_attn @ V   (per head)
        attn_kernel<<<gAttn, 128>>>(pq, pk, pv, mask, patt);

        // x = x + att @ Wo + bo
        sgemm_kernel<<<gProj, 256>>>(patt, Wo + wOff, bo + vOff, px, px,
                                     M, Dn, Dn, 0, 0, 0, 0);

        // FFN
        ln_kernel<<<Bn * Nn, 256>>>(px, ln2a + vOff, ln2b + vOff, ph);
        sgemm_kernel<<<gProj, 256>>>(ph, Wf1 + wOff, bf1 + vOff, nullptr, pt1,
                                     M, Dn, Dn, 0, 0, 0, 1);
        sgemm_kernel<<<gProj, 256>>>(pt1, Wf2 + wOff, bf2 + vOff, px, px,
                                     M, Dn, Dn, 0, 0, 0, 1);
    }

    ln_kernel<<<Bn * Nn, 256>>>(px, lnfa, lnfb, (float*)d_out);
}

// round 2
// speedup vs baseline: 1.2907x; 1.2907x over previous
#include <cuda_runtime.h>
#include <math.h>

// Problem constants
#define Bn 16
#define Nn 512
#define Dn 256
#define Hn 8
#define Ln 4
#define DKn 32

#define BND (Bn*Nn*Dn)   // 2,097,152
#define BNN (Bn*Nn*Nn)   // 4,194,304

static __device__ float g_x[BND];
static __device__ float g_h[BND];
static __device__ float g_q[BND];
static __device__ float g_k[BND];
static __device__ float g_v[BND];
static __device__ float g_att[BND];
static __device__ float g_t1[BND];
static __device__ float g_base[BNN];

// ---------------------------------------------------------------------------
// block reductions for base_kernel (256 threads)
// ---------------------------------------------------------------------------
__device__ __forceinline__ float blockSum256(float v) {
    __shared__ float sm[8];
    __syncthreads();
    #pragma unroll
    for (int o = 16; o; o >>= 1) v += __shfl_xor_sync(0xffffffffu, v, o);
    if ((threadIdx.x & 31) == 0) sm[threadIdx.x >> 5] = v;
    __syncthreads();
    float t = 0.f;
    #pragma unroll
    for (int i = 0; i < 8; i++) t += sm[i];
    return t;
}

__device__ __forceinline__ float blockMax256(float v) {
    __shared__ float sm[8];
    __syncthreads();
    #pragma unroll
    for (int o = 16; o; o >>= 1) v = fmaxf(v, __shfl_xor_sync(0xffffffffu, v, o));
    if ((threadIdx.x & 31) == 0) sm[threadIdx.x >> 5] = v;
    __syncthreads();
    float t = sm[0];
    #pragma unroll
    for (int i = 1; i < 8; i++) t = fmaxf(t, sm[i]);
    return t;
}

// ---------------------------------------------------------------------------
// base[b,i,j] = 0.3*softmax_j(mask ? -dist : -inf) + 0.4*adj/(sum_adj+eps)
// ---------------------------------------------------------------------------
__global__ void base_kernel(const float* __restrict__ dist,
                            const float* __restrict__ adj,
                            const int*   __restrict__ mask,
                            float* __restrict__ base) {
    const int bi = blockIdx.x;
    const int b  = bi >> 9;
    const float* dr = dist + (size_t)bi * Nn;
    const float* ar = adj  + (size_t)bi * Nn;
    float*       br = base + (size_t)bi * Nn;
    const int t = threadIdx.x;

    const int m0 = mask[b * Nn + t];
    const int m1 = mask[b * Nn + t + 256];
    float v0 = m0 ? -dr[t]       : -INFINITY;
    float v1 = m1 ? -dr[t + 256] : -INFINITY;

    float mx = blockMax256(fmaxf(v0, v1));
    float e0 = __expf(v0 - mx);
    float e1 = __expf(v1 - mx);
    float ssum = blockSum256(e0 + e1);

    float a0 = ar[t], a1 = ar[t + 256];
    float asum = blockSum256(a0 + a1);

    float cs = 0.3f / ssum;
    float ca = 0.4f / (asum + 1e-6f);
    br[t]       = e0 * cs + a0 * ca;
    br[t + 256] = e1 * cs + a1 * ca;
}

// ---------------------------------------------------------------------------
// LayerNorm (ddof=1), warp per row, shfl-only. grid = rows/8, 256 threads.
// ---------------------------------------------------------------------------
__global__ void ln_kernel(const float* __restrict__ x,
                          const float* __restrict__ a,
                          const float* __restrict__ bb,
                          float* __restrict__ out) {
    const int warp = threadIdx.x >> 5;
    const int lane = threadIdx.x & 31;
    const size_t row = (size_t)blockIdx.x * 8 + warp;
    const float* xr = x + row * Dn;
    const int c = lane * 8;

    float4 v0 = *(const float4*)(xr + c);
    float4 v1 = *(const float4*)(xr + c + 4);
    float s = v0.x+v0.y+v0.z+v0.w + v1.x+v1.y+v1.z+v1.w;
    #pragma unroll
    for (int o = 16; o; o >>= 1) s += __shfl_xor_sync(0xffffffffu, s, o);
    float mean = s * (1.f / Dn);

    float c0[8] = {v0.x-mean, v0.y-mean, v0.z-mean, v0.w-mean,
                   v1.x-mean, v1.y-mean, v1.z-mean, v1.w-mean};
    float sq = 0.f;
    #pragma unroll
    for (int i = 0; i < 8; i++) sq += c0[i]*c0[i];
    #pragma unroll
    for (int o = 16; o; o >>= 1) sq += __shfl_xor_sync(0xffffffffu, sq, o);
    float inv = 1.f / (sqrtf(sq * (1.f / (Dn - 1))) + 1e-6f);

    float4 a0 = *(const float4*)(a + c);
    float4 a1 = *(const float4*)(a + c + 4);
    float4 b0 = *(const float4*)(bb + c);
    float4 b1 = *(const float4*)(bb + c + 4);
    float4 o0, o1;
    o0.x = a0.x*c0[0]*inv + b0.x;  o0.y = a0.y*c0[1]*inv + b0.y;
    o0.z = a0.z*c0[2]*inv + b0.z;  o0.w = a0.w*c0[3]*inv + b0.w;
    o1.x = a1.x*c0[4]*inv + b1.x;  o1.y = a1.y*c0[5]*inv + b1.y;
    o1.z = a1.z*c0[6]*inv + b1.z;  o1.w = a1.w*c0[7]*inv + b1.w;
    *(float4*)(out + row * Dn + c)     = o0;
    *(float4*)(out + row * Dn + c + 4) = o1;
}

// ---------------------------------------------------------------------------
// SGEMM v2: 128x128 block tile, BK=8, 256 threads, double-buffered.
// Warp w owns M-rows [w*16, w*16+16); lane owns N-cols [lane*4, lane*4+4).
// C = act(A@W + bias) (+ res). Batched via blockIdx.z.
// ---------------------------------------------------------------------------
__global__ void __launch_bounds__(256, 1)
sgemm_kernel(const float* __restrict__ A,
             const float* __restrict__ W,
             const float* __restrict__ bias,
             const float* __restrict__ res,
             float* __restrict__ C,
             int M, int Nc, int K,
             long sA, long sW, long sC, int act) {
    A += (size_t)blockIdx.z * sA;
    W += (size_t)blockIdx.z * sW;
    C += (size_t)blockIdx.z * sC;
    if (res) res += (size_t)blockIdx.z * sC;

    const int tm = blockIdx.y * 128;
    const int tn = blockIdx.x * 128;
    const int tid = threadIdx.x;
    const int warp = tid >> 5;
    const int lane = tid & 31;
    const int mBase = warp * 16;
    const int nBase = lane * 4;

    __shared__ float As[2][8][132];   // [buf][k][m] padded
    __shared__ float Bs[2][8][128];   // [buf][k][n]

    // global load mapping
    const int arow = tid >> 1;            // 0..127
    const int acol = (tid & 1) << 2;      // 0 or 4
    const int brow = tid >> 5;            // 0..7
    const int bcol = (tid & 31) << 2;     // 0..124

    const float* pA = A + (size_t)(tm + arow) * K + acol;
    const float* pB = W + (size_t)brow * Nc + tn + bcol;

    float acc[16][4];
    #pragma unroll
    for (int i = 0; i < 16; i++)
        #pragma unroll
        for (int j = 0; j < 4; j++) acc[i][j] = 0.f;

    float4 ra = *(const float4*)(pA);
    float4 rb = *(const float4*)(pB);
    int buf = 0;
    As[0][acol+0][arow] = ra.x;
    As[0][acol+1][arow] = ra.y;
    As[0][acol+2][arow] = ra.z;
    As[0][acol+3][arow] = ra.w;
    *(float4*)&Bs[0][brow][bcol] = rb;
    __syncthreads();

    for (int k0 = 8; k0 < K; k0 += 8) {
        ra = *(const float4*)(pA + k0);
        rb = *(const float4*)(pB + (size_t)k0 * Nc);

        #pragma unroll
        for (int kk = 0; kk < 8; kk++) {
            float4 b4 = *(const float4*)&Bs[buf][kk][nBase];
            #pragma unroll
            for (int u = 0; u < 4; u++) {
                float4 a4 = *(const float4*)&As[buf][kk][mBase + u*4];
                float am[4] = {a4.x, a4.y, a4.z, a4.w};
                #pragma unroll
                for (int i = 0; i < 4; i++) {
                    acc[u*4+i][0] += am[i] * b4.x;
                    acc[u*4+i][1] += am[i] * b4.y;
                    acc[u*4+i][2] += am[i] * b4.z;
                    acc[u*4+i][3] += am[i] * b4.w;
                }
            }
        }

        const int nb = buf ^ 1;
        As[nb][acol+0][arow] = ra.x;
        As[nb][acol+1][arow] = ra.y;
        As[nb][acol+2][arow] = ra.z;
        As[nb][acol+3][arow] = ra.w;
        *(float4*)&Bs[nb][brow][bcol] = rb;
        __syncthreads();
        buf = nb;
    }

    #pragma unroll
    for (int kk = 0; kk < 8; kk++) {
        float4 b4 = *(const float4*)&Bs[buf][kk][nBase];
        #pragma unroll
        for (int u = 0; u < 4; u++) {
            float4 a4 = *(const float4*)&As[buf][kk][mBase + u*4];
            float am[4] = {a4.x, a4.y, a4.z, a4.w};
            #pragma unroll
            for (int i = 0; i < 4; i++) {
                acc[u*4+i][0] += am[i] * b4.x;
                acc[u*4+i][1] += am[i] * b4.y;
                acc[u*4+i][2] += am[i] * b4.z;
                acc[u*4+i][3] += am[i] * b4.w;
            }
        }
    }

    float4 bi4 = make_float4(0.f, 0.f, 0.f, 0.f);
    if (bias) bi4 = *(const float4*)(bias + tn + nBase);

    #pragma unroll
    for (int i = 0; i < 16; i++) {
        const size_t row = (size_t)(tm + mBase + i);
        float4 v;
        v.x = acc[i][0] + bi4.x;
        v.y = acc[i][1] + bi4.y;
        v.z = acc[i][2] + bi4.z;
        v.w = acc[i][3] + bi4.w;
        if (act) {
            v.x = v.x > 0.f ? v.x : 0.1f * v.x;
            v.y = v.y > 0.f ? v.y : 0.1f * v.y;
            v.z = v.z > 0.f ? v.z : 0.1f * v.z;
            v.w = v.w > 0.f ? v.w : 0.1f * v.w;
        }
        if (res) {
            float4 r4 = *(const float4*)(res + row * Nc + tn + nBase);
            v.x += r4.x; v.y += r4.y; v.z += r4.z; v.w += r4.w;
        }
        *(float4*)(C + row * Nc + tn + nBase) = v;
    }
}

// ---------------------------------------------------------------------------
// Flash attention: att += 0.3 * softmax(mask(qk^T/s)) @ v
// thread = one query row; tiles of 8 scores in regs -> one rescale per 8 keys
// ---------------------------------------------------------------------------
__global__ void __launch_bounds__(128)
attn_kernel(const float* __restrict__ q,
            const float* __restrict__ k,
            const float* __restrict__ v,
            const int*   __restrict__ mask,
            float* __restrict__ att) {
    const int b = blockIdx.z, h = blockIdx.y;
    const int row = blockIdx.x * 128 + threadIdx.x;

    __shared__ float ks[64][32];
    __shared__ float vs[64][32];
    __shared__ int   ms[64];

    const size_t qoff = ((size_t)(b * Nn) + row) * Dn + h * DKn;
    float qr[32];
    #pragma unroll
    for (int c = 0; c < 8; c++) {
        float4 t = *(const float4*)(q + qoff + c * 4);
        qr[c*4+0] = t.x; qr[c*4+1] = t.y; qr[c*4+2] = t.z; qr[c*4+3] = t.w;
    }

    float acc[32];
    #pragma unroll
    for (int d = 0; d < 32; d++) acc[d] = 0.f;
    float m = -INFINITY, l = 0.f;
    const float scale = 0.17677669529663687f;   // 1/sqrt(32)

    for (int kt = 0; kt < Nn / 64; kt++) {
        __syncthreads();
        for (int t = threadIdx.x; t < 512; t += 128) {
            int r = t >> 3, c = (t & 7) << 2;
            size_t off = ((size_t)(b * Nn) + kt * 64 + r) * Dn + h * DKn + c;
            *(float4*)&ks[r][c] = *(const float4*)(k + off);
            *(float4*)&vs[r][c] = *(const float4*)(v + off);
        }
        if (threadIdx.x < 64) ms[threadIdx.x] = mask[b * Nn + kt * 64 + threadIdx.x];
        __syncthreads();

        #pragma unroll 1
        for (int j0 = 0; j0 < 64; j0 += 8) {
            float s[8];
            #pragma unroll
            for (int jj = 0; jj < 8; jj++) {
                const float* kr = &ks[j0 + jj][0];
                float d0 = 0.f;
                #pragma unroll
                for (int c = 0; c < 8; c++) {
                    float4 k4 = *(const float4*)(kr + c * 4);
                    d0 += qr[c*4+0]*k4.x + qr[c*4+1]*k4.y
                        + qr[c*4+2]*k4.z + qr[c*4+3]*k4.w;
                }
                s[jj] = ms[j0 + jj] ? d0 * scale : -1e12f;
            }
            float tm = s[0];
            #pragma unroll
            for (int jj = 1; jj < 8; jj++) tm = fmaxf(tm, s[jj]);
            float nm = fmaxf(m, tm);
            float sc = __expf(m - nm);
            l *= sc;
            #pragma unroll
            for (int d = 0; d < 32; d++) acc[d] *= sc;
            #pragma unroll
            for (int jj = 0; jj < 8; jj++) {
                float p = __expf(s[jj] - nm);
                l += p;
                const float* vr = &vs[j0 + jj][0];
                #pragma unroll
                for (int c = 0; c < 8; c++) {
                    float4 v4 = *(const float4*)(vr + c * 4);
                    acc[c*4+0] += p * v4.x;
                    acc[c*4+1] += p * v4.y;
                    acc[c*4+2] += p * v4.z;
                    acc[c*4+3] += p * v4.w;
                }
            }
            m = nm;
        }
    }

    const float inv = 0.3f / l;
    float* o = att + qoff;
    #pragma unroll
    for (int c = 0; c < 8; c++) {
        float4 t = *(const float4*)(o + c * 4);
        t.x += acc[c*4+0] * inv;
        t.y += acc[c*4+1] * inv;
        t.z += acc[c*4+2] * inv;
        t.w += acc[c*4+3] * inv;
        *(float4*)(o + c * 4) = t;
    }
}

// ---------------------------------------------------------------------------
// Launch
// ---------------------------------------------------------------------------
extern "C" void kernel_launch(void* const* d_in, const int* in_sizes, int n_in,
                              void* d_out, int out_size) {
    const float* x_in  = (const float*)d_in[0];
    const int*   mask  = (const int*)  d_in[1];
    const float* adj   = (const float*)d_in[2];
    const float* dist  = (const float*)d_in[3];
    const float* Wq    = (const float*)d_in[5];
    const float* bq    = (const float*)d_in[6];
    const float* Wk    = (const float*)d_in[7];
    const float* bk    = (const float*)d_in[8];
    const float* Wv    = (const float*)d_in[9];
    const float* bv    = (const float*)d_in[10];
    const float* Wo    = (const float*)d_in[11];
    const float* bo    = (const float*)d_in[12];
    const float* Wf1   = (const float*)d_in[13];
    const float* bf1   = (const float*)d_in[14];
    const float* Wf2   = (const float*)d_in[15];
    const float* bf2   = (const float*)d_in[16];
    const float* ln1a  = (const float*)d_in[17];
    const float* ln1b  = (const float*)d_in[18];
    const float* ln2a  = (const float*)d_in[19];
    const float* ln2b  = (const float*)d_in[20];
    const float* lnfa  = (const float*)d_in[21];
    const float* lnfb  = (const float*)d_in[22];

    float *px, *ph, *pq, *pk, *pv, *patt, *pt1, *pbase;
    cudaGetSymbolAddress((void**)&px,    g_x);
    cudaGetSymbolAddress((void**)&ph,    g_h);
    cudaGetSymbolAddress((void**)&pq,    g_q);
    cudaGetSymbolAddress((void**)&pk,    g_k);
    cudaGetSymbolAddress((void**)&pv,    g_v);
    cudaGetSymbolAddress((void**)&patt,  g_att);
    cudaGetSymbolAddress((void**)&pt1,   g_t1);
    cudaGetSymbolAddress((void**)&pbase, g_base);

    cudaMemcpyAsync(px, x_in, sizeof(float) * BND, cudaMemcpyDeviceToDevice, 0);

    base_kernel<<<Bn * Nn, 256>>>(dist, adj, mask, pbase);

    const dim3 gProj(Dn / 128, (Bn * Nn) / 128, 1);   // (2,64,1) = 128 blocks
    const dim3 gBaseV(Dn / 128, Nn / 128, Bn);        // (2,4,16) = 128 blocks
    const dim3 gAttn(Nn / 128, Hn, Bn);               // (4,8,16)
    const dim3 gLN(Bn * Nn / 8, 1, 1);                // 1024 blocks
    const int M = Bn * Nn;

    for (int i = 0; i < Ln; i++) {
        const size_t wOff = (size_t)i * Dn * Dn;
        const size_t vOff = (size_t)i * Dn;

        ln_kernel<<<gLN, 256>>>(px, ln1a + vOff, ln1b + vOff, ph);

        sgemm_kernel<<<gProj, 256>>>(ph, Wq + wOff, bq + vOff, nullptr, pq,
                                     M, Dn, Dn, 0, 0, 0, 0);
        sgemm_kernel<<<gProj, 256>>>(ph, Wk + wOff, bk + vOff, nullptr, pk,
                                     M, Dn, Dn, 0, 0, 0, 0);
        sgemm_kernel<<<gProj, 256>>>(ph, Wv + wOff, bv + vOff, nullptr, pv,
                                     M, Dn, Dn, 0, 0, 0, 0);

        // att = base @ V  (head-independent part of p, pre-scaled)
        sgemm_kernel<<<gBaseV, 256>>>(pbase, pv, nullptr, nullptr, patt,
                                      Nn, Dn, Nn,
                                      (long)Nn * Nn, (long)Nn * Dn, (long)Nn * Dn, 0);

        // att += 0.3 * softmax_attn @ V   (per head)
        attn_kernel<<<gAttn, 128>>>(pq, pk, pv, mask, patt);

        // x = x + att @ Wo + bo
        sgemm_kernel<<<gProj, 256>>>(patt, Wo + wOff, bo + vOff, px, px,
                                     M, Dn, Dn, 0, 0, 0, 0);

        // FFN
        ln_kernel<<<gLN, 256>>>(px, ln2a + vOff, ln2b + vOff, ph);
        sgemm_kernel<<<gProj, 256>>>(ph, Wf1 + wOff, bf1 + vOff, nullptr, pt1,
                                     M, Dn, Dn, 0, 0, 0, 1);
        sgemm_kernel<<<gProj, 256>>>(pt1, Wf2 + wOff, bf2 + vOff, px, px,
                                     M, Dn, Dn, 0, 0, 0, 1);
    }

    ln_kernel<<<gLN, 256>>>(px, lnfa, lnfb, (float*)d_out);
}

// round 3
// speedup vs baseline: 1.4213x; 1.1012x over previous
#include <cuda_runtime.h>
#include <math.h>
#include <mma.h>

using namespace nvcuda;

// Problem constants
#define Bn 16
#define Nn 512
#define Dn 256
#define Hn 8
#define Ln 4
#define DKn 32

#define BND (Bn*Nn*Dn)   // 2,097,152
#define BNN (Bn*Nn*Nn)   // 4,194,304

static __device__ float g_x[BND];
static __device__ float g_h[BND];
static __device__ float g_q[BND];
static __device__ float g_k[BND];
static __device__ float g_v[BND];
static __device__ float g_att[BND];
static __device__ float g_t1[BND];
static __device__ float g_base[BNN];

// ---------------------------------------------------------------------------
// block reductions for base_kernel (256 threads)
// ---------------------------------------------------------------------------
__device__ __forceinline__ float blockSum256(float v) {
    __shared__ float sm[8];
    __syncthreads();
    #pragma unroll
    for (int o = 16; o; o >>= 1) v += __shfl_xor_sync(0xffffffffu, v, o);
    if ((threadIdx.x & 31) == 0) sm[threadIdx.x >> 5] = v;
    __syncthreads();
    float t = 0.f;
    #pragma unroll
    for (int i = 0; i < 8; i++) t += sm[i];
    return t;
}

__device__ __forceinline__ float blockMax256(float v) {
    __shared__ float sm[8];
    __syncthreads();
    #pragma unroll
    for (int o = 16; o; o >>= 1) v = fmaxf(v, __shfl_xor_sync(0xffffffffu, v, o));
    if ((threadIdx.x & 31) == 0) sm[threadIdx.x >> 5] = v;
    __syncthreads();
    float t = sm[0];
    #pragma unroll
    for (int i = 1; i < 8; i++) t = fmaxf(t, sm[i]);
    return t;
}

// ---------------------------------------------------------------------------
// base[b,i,j] = 0.3*softmax_j(mask ? -dist : -inf) + 0.4*adj/(sum_adj+eps)
// ---------------------------------------------------------------------------
__global__ void base_kernel(const float* __restrict__ dist,
                            const float* __restrict__ adj,
                            const int*   __restrict__ mask,
                            float* __restrict__ base) {
    const int bi = blockIdx.x;
    const int b  = bi >> 9;
    const float* dr = dist + (size_t)bi * Nn;
    const float* ar = adj  + (size_t)bi * Nn;
    float*       br = base + (size_t)bi * Nn;
    const int t = threadIdx.x;

    const int m0 = mask[b * Nn + t];
    const int m1 = mask[b * Nn + t + 256];
    float v0 = m0 ? -dr[t]       : -INFINITY;
    float v1 = m1 ? -dr[t + 256] : -INFINITY;

    float mx = blockMax256(fmaxf(v0, v1));
    float e0 = __expf(v0 - mx);
    float e1 = __expf(v1 - mx);
    float ssum = blockSum256(e0 + e1);

    float a0 = ar[t], a1 = ar[t + 256];
    float asum = blockSum256(a0 + a1);

    float cs = 0.3f / ssum;
    float ca = 0.4f / (asum + 1e-6f);
    br[t]       = e0 * cs + a0 * ca;
    br[t + 256] = e1 * cs + a1 * ca;
}

// ---------------------------------------------------------------------------
// LayerNorm (ddof=1), warp per row, shfl-only. grid = rows/8, 256 threads.
// ---------------------------------------------------------------------------
__global__ void ln_kernel(const float* __restrict__ x,
                          const float* __restrict__ a,
                          const float* __restrict__ bb,
                          float* __restrict__ out) {
    const int warp = threadIdx.x >> 5;
    const int lane = threadIdx.x & 31;
    const size_t row = (size_t)blockIdx.x * 8 + warp;
    const float* xr = x + row * Dn;
    const int c = lane * 8;

    float4 v0 = *(const float4*)(xr + c);
    float4 v1 = *(const float4*)(xr + c + 4);
    float s = v0.x+v0.y+v0.z+v0.w + v1.x+v1.y+v1.z+v1.w;
    #pragma unroll
    for (int o = 16; o; o >>= 1) s += __shfl_xor_sync(0xffffffffu, s, o);
    float mean = s * (1.f / Dn);

    float c0[8] = {v0.x-mean, v0.y-mean, v0.z-mean, v0.w-mean,
                   v1.x-mean, v1.y-mean, v1.z-mean, v1.w-mean};
    float sq = 0.f;
    #pragma unroll
    for (int i = 0; i < 8; i++) sq += c0[i]*c0[i];
    #pragma unroll
    for (int o = 16; o; o >>= 1) sq += __shfl_xor_sync(0xffffffffu, sq, o);
    float inv = 1.f / (sqrtf(sq * (1.f / (Dn - 1))) + 1e-6f);

    float4 a0 = *(const float4*)(a + c);
    float4 a1 = *(const float4*)(a + c + 4);
    float4 b0 = *(const float4*)(bb + c);
    float4 b1 = *(const float4*)(bb + c + 4);
    float4 o0, o1;
    o0.x = a0.x*c0[0]*inv + b0.x;  o0.y = a0.y*c0[1]*inv + b0.y;
    o0.z = a0.z*c0[2]*inv + b0.z;  o0.w = a0.w*c0[3]*inv + b0.w;
    o1.x = a1.x*c0[4]*inv + b1.x;  o1.y = a1.y*c0[5]*inv + b1.y;
    o1.z = a1.z*c0[6]*inv + b1.z;  o1.w = a1.w*c0[7]*inv + b1.w;
    *(float4*)(out + row * Dn + c)     = o0;
    *(float4*)(out + row * Dn + c + 4) = o1;
}

// ---------------------------------------------------------------------------
// TF32 tensor-core GEMM: C = act(A@W + bias) (+ res). Batched via blockIdx.z.
// Block tile 128x128, BK=16, 8 warps (4x2), warp tile 32x64 (wmma m16n16k8).
// Double-buffered smem; tf32 conversion at smem store; staged epilogue.
// ---------------------------------------------------------------------------
#define LDA 20
#define LDB 132
#define LDS_ 68

__device__ __forceinline__ float4 cvt_tf32_4(float4 v) {
    v.x = wmma::__float_to_tf32(v.x);
    v.y = wmma::__float_to_tf32(v.y);
    v.z = wmma::__float_to_tf32(v.z);
    v.w = wmma::__float_to_tf32(v.w);
    return v;
}

__global__ void __launch_bounds__(256)
gemm_tc(const float* __restrict__ A, const float* __restrict__ W,
        const float* __restrict__ bias, const float* __restrict__ res,
        float* __restrict__ C, int M, int Nc, int K,
        long sA, long sW, long sC, int act) {
    A += (size_t)blockIdx.z * sA;
    W += (size_t)blockIdx.z * sW;
    C += (size_t)blockIdx.z * sC;
    if (res) res += (size_t)blockIdx.z * sC;

    const int tm = blockIdx.y * 128;
    const int tn = blockIdx.x * 128;
    const int tid = threadIdx.x;
    const int warp = tid >> 5;
    const int lane = tid & 31;
    const int wm = warp >> 1;        // 0..3 -> 32-row band
    const int wn = warp & 1;         // 0..1 -> 64-col band

    // smem: As[2][128][LDA] (5120) + Bs[2][16][LDB] (4224) = 9344 floats
    // stage (epilogue) 8*16*LDS_ = 8704 floats, unioned over same buffer
    __shared__ __align__(16) float smem[9344];
    #define AS(buf,r,c) smem[(buf)*2560 + (r)*LDA + (c)]
    #define BS(buf,r,c) smem[5120 + (buf)*2112 + (r)*LDB + (c)]

    const int arow = tid >> 1;            // 0..127
    const int acol = (tid & 1) * 8;       // 0 or 8
    const int brow = tid >> 4;            // 0..15
    const int bcol = (tid & 15) * 8;      // 0..120

    const float* pA = A + (size_t)(tm + arow) * K + acol;
    const float* pB = W + (size_t)brow * Nc + tn + bcol;

    wmma::fragment<wmma::accumulator, 16, 16, 8, float> cfr[2][4];
    #pragma unroll
    for (int mm = 0; mm < 2; mm++)
        #pragma unroll
        for (int nn = 0; nn < 4; nn++)
            wmma::fill_fragment(cfr[mm][nn], 0.f);

    // prologue: load tile 0
    float4 a0 = cvt_tf32_4(*(const float4*)(pA));
    float4 a1 = cvt_tf32_4(*(const float4*)(pA + 4));
    float4 b0 = cvt_tf32_4(*(const float4*)(pB));
    float4 b1 = cvt_tf32_4(*(const float4*)(pB + 4));
    int buf = 0;
    *(float4*)&AS(0, arow, acol)     = a0;
    *(float4*)&AS(0, arow, acol + 4) = a1;
    *(float4*)&BS(0, brow, bcol)     = b0;
    *(float4*)&BS(0, brow, bcol + 4) = b1;
    __syncthreads();

    for (int k0 = 16; k0 < K; k0 += 16) {
        a0 = cvt_tf32_4(*(const float4*)(pA + k0));
        a1 = cvt_tf32_4(*(const float4*)(pA + k0 + 4));
        b0 = cvt_tf32_4(*(const float4*)(pB + (size_t)k0 * Nc));
        b1 = cvt_tf32_4(*(const float4*)(pB + (size_t)k0 * Nc + 4));

        #pragma unroll
        for (int ks = 0; ks < 2; ks++) {
            wmma::fragment<wmma::matrix_a, 16, 16, 8, wmma::precision::tf32, wmma::row_major> af[2];
            wmma::load_matrix_sync(af[0], &AS(buf, wm * 32,      ks * 8), LDA);
            wmma::load_matrix_sync(af[1], &AS(buf, wm * 32 + 16, ks * 8), LDA);
            #pragma unroll
            for (int nn = 0; nn < 4; nn++) {
                wmma::fragment<wmma::matrix_b, 16, 16, 8, wmma::precision::tf32, wmma::row_major> bf;
                wmma::load_matrix_sync(bf, &BS(buf, ks * 8, wn * 64 + nn * 16), LDB);
                wmma::mma_sync(cfr[0][nn], af[0], bf, cfr[0][nn]);
                wmma::mma_sync(cfr[1][nn], af[1], bf, cfr[1][nn]);
            }
        }

        buf ^= 1;
        *(float4*)&AS(buf, arow, acol)     = a0;
        *(float4*)&AS(buf, arow, acol + 4) = a1;
        *(float4*)&BS(buf, brow, bcol)     = b0;
        *(float4*)&BS(buf, brow, bcol + 4) = b1;
        __syncthreads();
    }

    #pragma unroll
    for (int ks = 0; ks < 2; ks++) {
        wmma::fragment<wmma::matrix_a, 16, 16, 8, wmma::precision::tf32, wmma::row_major> af[2];
        wmma::load_matrix_sync(af[0], &AS(buf, wm * 32,      ks * 8), LDA);
        wmma::load_matrix_sync(af[1], &AS(buf, wm * 32 + 16, ks * 8), LDA);
        #pragma unroll
        for (int nn = 0; nn < 4; nn++) {
            wmma::fragment<wmma::matrix_b, 16, 16, 8, wmma::precision::tf32, wmma::row_major> bf;
            wmma::load_matrix_sync(bf, &BS(buf, ks * 8, wn * 64 + nn * 16), LDB);
            wmma::mma_sync(cfr[0][nn], af[0], bf, cfr[0][nn]);
            wmma::mma_sync(cfr[1][nn], af[1], bf, cfr[1][nn]);
        }
    }
    __syncthreads();   // protect smem before stage reuse

    // epilogue via per-warp stage buffer
    float* stg = smem + warp * 16 * LDS_;
    #pragma unroll
    for (int mm = 0; mm < 2; mm++) {
        #pragma unroll
        for (int nn = 0; nn < 4; nn++)
            wmma::store_matrix_sync(stg + nn * 16, cfr[mm][nn], LDS_, wmma::mem_row_major);
        __syncwarp();
        const int growb = tm + wm * 32 + mm * 16;
        const int gcolb = tn + wn * 64;
        #pragma unroll
        for (int it = 0; it < 8; it++) {
            int e = lane + it * 32;              // 0..255
            int rr = e >> 4;
            int cc = e & 15;
            int col = gcolb + cc * 4;
            float4 v = *(float4*)(stg + rr * LDS_ + cc * 4);
            if (bias) {
                float4 bb4 = *(const float4*)(bias + col);
                v.x += bb4.x; v.y += bb4.y; v.z += bb4.z; v.w += bb4.w;
            }
            if (act) {
                v.x = v.x > 0.f ? v.x : 0.1f * v.x;
                v.y = v.y > 0.f ? v.y : 0.1f * v.y;
                v.z = v.z > 0.f ? v.z : 0.1f * v.z;
                v.w = v.w > 0.f ? v.w : 0.1f * v.w;
            }
            size_t row = (size_t)(growb + rr);
            if (res) {
                float4 r4 = *(const float4*)(res + row * Nc + col);
                v.x += r4.x; v.y += r4.y; v.z += r4.z; v.w += r4.w;
            }
            *(float4*)(C + row * Nc + col) = v;
        }
        __syncwarp();
    }
    #undef AS
    #undef BS
}

// ---------------------------------------------------------------------------
// Flash attention: att += 0.3 * softmax(mask(qk^T/s)) @ v
// ---------------------------------------------------------------------------
__global__ void __launch_bounds__(128)
attn_kernel(const float* __restrict__ q,
            const float* __restrict__ k,
            const float* __restrict__ v,
            const int*   __restrict__ mask,
            float* __restrict__ att) {
    const int b = blockIdx.z, h = blockIdx.y;
    const int row = blockIdx.x * 128 + threadIdx.x;

    __shared__ float ks[64][32];
    __shared__ float vs[64][32];
    __shared__ int   ms[64];

    const size_t qoff = ((size_t)(b * Nn) + row) * Dn + h * DKn;
    float qr[32];
    #pragma unroll
    for (int c = 0; c < 8; c++) {
        float4 t = *(const float4*)(q + qoff + c * 4);
        qr[c*4+0] = t.x; qr[c*4+1] = t.y; qr[c*4+2] = t.z; qr[c*4+3] = t.w;
    }

    float acc[32];
    #pragma unroll
    for (int d = 0; d < 32; d++) acc[d] = 0.f;
    float m = -INFINITY, l = 0.f;
    const float scale = 0.17677669529663687f;

    for (int kt = 0; kt < Nn / 64; kt++) {
        __syncthreads();
        for (int t = threadIdx.x; t < 512; t += 128) {
            int r = t >> 3, c = (t & 7) << 2;
            size_t off = ((size_t)(b * Nn) + kt * 64 + r) * Dn + h * DKn + c;
            *(float4*)&ks[r][c] = *(const float4*)(k + off);
            *(float4*)&vs[r][c] = *(const float4*)(v + off);
        }
        if (threadIdx.x < 64) ms[threadIdx.x] = mask[b * Nn + kt * 64 + threadIdx.x];
        __syncthreads();

        #pragma unroll 1
        for (int j0 = 0; j0 < 64; j0 += 8) {
            float s[8];
            #pragma unroll
            for (int jj = 0; jj < 8; jj++) {
                const float* kr = &ks[j0 + jj][0];
                float d0 = 0.f;
                #pragma unroll
                for (int c = 0; c < 8; c++) {
                    float4 k4 = *(const float4*)(kr + c * 4);
                    d0 += qr[c*4+0]*k4.x + qr[c*4+1]*k4.y
                        + qr[c*4+2]*k4.z + qr[c*4+3]*k4.w;
                }
                s[jj] = ms[j0 + jj] ? d0 * scale : -1e12f;
            }
            float tm = s[0];
            #pragma unroll
            for (int jj = 1; jj < 8; jj++) tm = fmaxf(tm, s[jj]);
            float nm = fmaxf(m, tm);
            float sc = __expf(m - nm);
            l *= sc;
            #pragma unroll
            for (int d = 0; d < 32; d++) acc[d] *= sc;
            #pragma unroll
            for (int jj = 0; jj < 8; jj++) {
                float p = __expf(s[jj] - nm);
                l += p;
                const float* vr = &vs[j0 + jj][0];
                #pragma unroll
                for (int c = 0; c < 8; c++) {
                    float4 v4 = *(const float4*)(vr + c * 4);
                    acc[c*4+0] += p * v4.x;
                    acc[c*4+1] += p * v4.y;
                    acc[c*4+2] += p * v4.z;
                    acc[c*4+3] += p * v4.w;
                }
            }
            m = nm;
        }
    }

    const float inv = 0.3f / l;
    float* o = att + qoff;
    #pragma unroll
    for (int c = 0; c < 8; c++) {
        float4 t = *(const float4*)(o + c * 4);
        t.x += acc[c*4+0] * inv;
        t.y += acc[c*4+1] * inv;
        t.z += acc[c*4+2] * inv;
        t.w += acc[c*4+3] * inv;
        *(float4*)(o + c * 4) = t;
    }
}

// ---------------------------------------------------------------------------
// Launch
// ---------------------------------------------------------------------------
extern "C" void kernel_launch(void* const* d_in, const int* in_sizes, int n_in,
                              void* d_out, int out_size) {
    const float* x_in  = (const float*)d_in[0];
    const int*   mask  = (const int*)  d_in[1];
    const float* adj   = (const float*)d_in[2];
    const float* dist  = (const float*)d_in[3];
    const float* Wq    = (const float*)d_in[5];
    const float* bq    = (const float*)d_in[6];
    const float* Wk    = (const float*)d_in[7];
    const float* bk    = (const float*)d_in[8];
    const float* Wv    = (const float*)d_in[9];
    const float* bv    = (const float*)d_in[10];
    const float* Wo    = (const float*)d_in[11];
    const float* bo    = (const float*)d_in[12];
    const float* Wf1   = (const float*)d_in[13];
    const float* bf1   = (const float*)d_in[14];
    const float* Wf2   = (const float*)d_in[15];
    const float* bf2   = (const float*)d_in[16];
    const float* ln1a  = (const float*)d_in[17];
    const float* ln1b  = (const float*)d_in[18];
    const float* ln2a  = (const float*)d_in[19];
    const float* ln2b  = (const float*)d_in[20];
    const float* lnfa  = (const float*)d_in[21];
    const float* lnfb  = (const float*)d_in[22];

    float *px, *ph, *pq, *pk, *pv, *patt, *pt1, *pbase;
    cudaGetSymbolAddress((void**)&px,    g_x);
    cudaGetSymbolAddress((void**)&ph,    g_h);
    cudaGetSymbolAddress((void**)&pq,    g_q);
    cudaGetSymbolAddress((void**)&pk,    g_k);
    cudaGetSymbolAddress((void**)&pv,    g_v);
    cudaGetSymbolAddress((void**)&patt,  g_att);
    cudaGetSymbolAddress((void**)&pt1,   g_t1);
    cudaGetSymbolAddress((void**)&pbase, g_base);

    cudaMemcpyAsync(px, x_in, sizeof(float) * BND, cudaMemcpyDeviceToDevice, 0);

    base_kernel<<<Bn * Nn, 256>>>(dist, adj, mask, pbase);

    const dim3 gProj(Dn / 128, (Bn * Nn) / 128, 1);   // (2,64,1) = 128 blocks
    const dim3 gBaseV(Dn / 128, Nn / 128, Bn);        // (2,4,16) = 128 blocks
    const dim3 gAttn(Nn / 128, Hn, Bn);               // (4,8,16)
    const dim3 gLN(Bn * Nn / 8, 1, 1);
    const int M = Bn * Nn;

    for (int i = 0; i < Ln; i++) {
        const size_t wOff = (size_t)i * Dn * Dn;
        const size_t vOff = (size_t)i * Dn;

        ln_kernel<<<gLN, 256>>>(px, ln1a + vOff, ln1b + vOff, ph);

        gemm_tc<<<gProj, 256>>>(ph, Wq + wOff, bq + vOff, nullptr, pq,
                                M, Dn, Dn, 0, 0, 0, 0);
        gemm_tc<<<gProj, 256>>>(ph, Wk + wOff, bk + vOff, nullptr, pk,
                                M, Dn, Dn, 0, 0, 0, 0);
        gemm_tc<<<gProj, 256>>>(ph, Wv + wOff, bv + vOff, nullptr, pv,
                                M, Dn, Dn, 0, 0, 0, 0);

        // att = base @ V  (head-independent part of p, pre-scaled)
        gemm_tc<<<gBaseV, 256>>>(pbase, pv, nullptr, nullptr, patt,
                                 Nn, Dn, Nn,
                                 (long)Nn * Nn, (long)Nn * Dn, (long)Nn * Dn, 0);

        // att += 0.3 * softmax_attn @ V   (per head)
        attn_kernel<<<gAttn, 128>>>(pq, pk, pv, mask, patt);

        // x = x + att @ Wo + bo
        gemm_tc<<<gProj, 256>>>(patt, Wo + wOff, bo + vOff, px, px,
                                M, Dn, Dn, 0, 0, 0, 0);

        // FFN
        ln_kernel<<<gLN, 256>>>(px, ln2a + vOff, ln2b + vOff, ph);
        gemm_tc<<<gProj, 256>>>(ph, Wf1 + wOff, bf1 + vOff, nullptr, pt1,
                                M, Dn, Dn, 0, 0, 0, 1);
        gemm_tc<<<gProj, 256>>>(pt1, Wf2 + wOff, bf2 + vOff, px, px,
                                M, Dn, Dn, 0, 0, 0, 1);
    }

    ln_kernel<<<gLN, 256>>>(px, lnfa, lnfb, (float*)d_out);
}

// round 4
// speedup vs baseline: 1.5626x; 1.0994x over previous
#include <cuda_runtime.h>
#include <math.h>
#include <mma.h>

using namespace nvcuda;

// Problem constants
#define Bn 16
#define Nn 512
#define Dn 256
#define Hn 8
#define Ln 4
#define DKn 32

#define BND (Bn*Nn*Dn)   // 2,097,152
#define BNN (Bn*Nn*Nn)   // 4,194,304

static __device__ float g_x[BND];
static __device__ float g_h[BND];
static __device__ float g_q[BND];
static __device__ float g_k[BND];
static __device__ float g_v[BND];
static __device__ float g_att[BND];
static __device__ float g_t1[BND];
static __device__ float g_base[BNN];

// ---------------------------------------------------------------------------
// block reductions for base_kernel (256 threads)
// ---------------------------------------------------------------------------
__device__ __forceinline__ float blockSum256(float v) {
    __shared__ float sm[8];
    __syncthreads();
    #pragma unroll
    for (int o = 16; o; o >>= 1) v += __shfl_xor_sync(0xffffffffu, v, o);
    if ((threadIdx.x & 31) == 0) sm[threadIdx.x >> 5] = v;
    __syncthreads();
    float t = 0.f;
    #pragma unroll
    for (int i = 0; i < 8; i++) t += sm[i];
    return t;
}

__device__ __forceinline__ float blockMax256(float v) {
    __shared__ float sm[8];
    __syncthreads();
    #pragma unroll
    for (int o = 16; o; o >>= 1) v = fmaxf(v, __shfl_xor_sync(0xffffffffu, v, o));
    if ((threadIdx.x & 31) == 0) sm[threadIdx.x >> 5] = v;
    __syncthreads();
    float t = sm[0];
    #pragma unroll
    for (int i = 1; i < 8; i++) t = fmaxf(t, sm[i]);
    return t;
}

// ---------------------------------------------------------------------------
// base[b,i,j] = 0.3*softmax_j(mask ? -dist : -inf) + 0.4*adj/(sum_adj+eps)
// ---------------------------------------------------------------------------
__global__ void base_kernel(const float* __restrict__ dist,
                            const float* __restrict__ adj,
                            const int*   __restrict__ mask,
                            float* __restrict__ base) {
    const int bi = blockIdx.x;
    const int b  = bi >> 9;
    const float* dr = dist + (size_t)bi * Nn;
    const float* ar = adj  + (size_t)bi * Nn;
    float*       br = base + (size_t)bi * Nn;
    const int t = threadIdx.x;

    const int m0 = mask[b * Nn + t];
    const int m1 = mask[b * Nn + t + 256];
    float v0 = m0 ? -dr[t]       : -INFINITY;
    float v1 = m1 ? -dr[t + 256] : -INFINITY;

    float mx = blockMax256(fmaxf(v0, v1));
    float e0 = __expf(v0 - mx);
    float e1 = __expf(v1 - mx);
    float ssum = blockSum256(e0 + e1);

    float a0 = ar[t], a1 = ar[t + 256];
    float asum = blockSum256(a0 + a1);

    float cs = 0.3f / ssum;
    float ca = 0.4f / (asum + 1e-6f);
    br[t]       = e0 * cs + a0 * ca;
    br[t + 256] = e1 * cs + a1 * ca;
}

// ---------------------------------------------------------------------------
// LayerNorm (ddof=1), warp per row, shfl-only.
// ---------------------------------------------------------------------------
__global__ void ln_kernel(const float* __restrict__ x,
                          const float* __restrict__ a,
                          const float* __restrict__ bb,
                          float* __restrict__ out) {
    const int warp = threadIdx.x >> 5;
    const int lane = threadIdx.x & 31;
    const size_t row = (size_t)blockIdx.x * 8 + warp;
    const float* xr = x + row * Dn;
    const int c = lane * 8;

    float4 v0 = *(const float4*)(xr + c);
    float4 v1 = *(const float4*)(xr + c + 4);
    float s = v0.x+v0.y+v0.z+v0.w + v1.x+v1.y+v1.z+v1.w;
    #pragma unroll
    for (int o = 16; o; o >>= 1) s += __shfl_xor_sync(0xffffffffu, s, o);
    float mean = s * (1.f / Dn);

    float c0[8] = {v0.x-mean, v0.y-mean, v0.z-mean, v0.w-mean,
                   v1.x-mean, v1.y-mean, v1.z-mean, v1.w-mean};
    float sq = 0.f;
    #pragma unroll
    for (int i = 0; i < 8; i++) sq += c0[i]*c0[i];
    #pragma unroll
    for (int o = 16; o; o >>= 1) sq += __shfl_xor_sync(0xffffffffu, sq, o);
    float inv = 1.f / (sqrtf(sq * (1.f / (Dn - 1))) + 1e-6f);

    float4 a0 = *(const float4*)(a + c);
    float4 a1 = *(const float4*)(a + c + 4);
    float4 b0 = *(const float4*)(bb + c);
    float4 b1 = *(const float4*)(bb + c + 4);
    float4 o0, o1;
    o0.x = a0.x*c0[0]*inv + b0.x;  o0.y = a0.y*c0[1]*inv + b0.y;
    o0.z = a0.z*c0[2]*inv + b0.z;  o0.w = a0.w*c0[3]*inv + b0.w;
    o1.x = a1.x*c0[4]*inv + b1.x;  o1.y = a1.y*c0[5]*inv + b1.y;
    o1.z = a1.z*c0[6]*inv + b1.z;  o1.w = a1.w*c0[7]*inv + b1.w;
    *(float4*)(out + row * Dn + c)     = o0;
    *(float4*)(out + row * Dn + c + 4) = o1;
}

// ---------------------------------------------------------------------------
// TF32 tensor-core GEMM body: 64x128 block tile, BK=16, 8 warps (2x4),
// warp tile 32x32 (wmma m16n16k8), double-buffered.
// ---------------------------------------------------------------------------
#define LDA 20
#define LDB 132
#define LDS_ 36
#define SMEM_FLOATS 9216   // max(mainloop 6784, stage 8*32*36=9216)

__device__ __forceinline__ float4 cvt_tf32_4(float4 v) {
    v.x = wmma::__float_to_tf32(v.x);
    v.y = wmma::__float_to_tf32(v.y);
    v.z = wmma::__float_to_tf32(v.z);
    v.w = wmma::__float_to_tf32(v.w);
    return v;
}

__device__ __forceinline__ void gemm_body(
    const float* __restrict__ A, const float* __restrict__ W,
    const float* __restrict__ bias, const float* __restrict__ res,
    float* __restrict__ C, int Nc, int K, int act, float* smem) {

    const int tm = blockIdx.y * 64;
    const int tn = blockIdx.x * 128;
    const int tid = threadIdx.x;
    const int warp = tid >> 5;
    const int lane = tid & 31;
    const int wm = warp >> 2;        // 0..1 -> 32-row band
    const int wn = warp & 3;         // 0..3 -> 32-col band

    #define AS(buf,r,c) smem[(buf)*1280 + (r)*LDA + (c)]
    #define BS(buf,r,c) smem[2560 + (buf)*2112 + (r)*LDB + (c)]

    const int arow = tid >> 2;            // 0..63
    const int acol = (tid & 3) * 4;       // 0,4,8,12
    const int brow = tid >> 4;            // 0..15
    const int bcol = (tid & 15) * 8;      // 0..120

    const float* pA = A + (size_t)(tm + arow) * K + acol;
    const float* pB = W + (size_t)brow * Nc + tn + bcol;

    wmma::fragment<wmma::accumulator, 16, 16, 8, float> acc[2][2];
    #pragma unroll
    for (int mm = 0; mm < 2; mm++)
        #pragma unroll
        for (int nn = 0; nn < 2; nn++)
            wmma::fill_fragment(acc[mm][nn], 0.f);

    float4 ra = cvt_tf32_4(*(const float4*)(pA));
    float4 b0 = cvt_tf32_4(*(const float4*)(pB));
    float4 b1 = cvt_tf32_4(*(const float4*)(pB + 4));
    int buf = 0;
    *(float4*)&AS(0, arow, acol) = ra;
    *(float4*)&BS(0, brow, bcol)     = b0;
    *(float4*)&BS(0, brow, bcol + 4) = b1;
    __syncthreads();

    for (int k0 = 16; k0 < K; k0 += 16) {
        ra = cvt_tf32_4(*(const float4*)(pA + k0));
        b0 = cvt_tf32_4(*(const float4*)(pB + (size_t)k0 * Nc));
        b1 = cvt_tf32_4(*(const float4*)(pB + (size_t)k0 * Nc + 4));

        #pragma unroll
        for (int ks = 0; ks < 2; ks++) {
            wmma::fragment<wmma::matrix_a, 16, 16, 8, wmma::precision::tf32, wmma::row_major> af[2];
            wmma::fragment<wmma::matrix_b, 16, 16, 8, wmma::precision::tf32, wmma::row_major> bf[2];
            wmma::load_matrix_sync(af[0], &AS(buf, wm * 32,      ks * 8), LDA);
            wmma::load_matrix_sync(af[1], &AS(buf, wm * 32 + 16, ks * 8), LDA);
            wmma::load_matrix_sync(bf[0], &BS(buf, ks * 8, wn * 32),      LDB);
            wmma::load_matrix_sync(bf[1], &BS(buf, ks * 8, wn * 32 + 16), LDB);
            wmma::mma_sync(acc[0][0], af[0], bf[0], acc[0][0]);
            wmma::mma_sync(acc[0][1], af[0], bf[1], acc[0][1]);
            wmma::mma_sync(acc[1][0], af[1], bf[0], acc[1][0]);
            wmma::mma_sync(acc[1][1], af[1], bf[1], acc[1][1]);
        }

        buf ^= 1;
        *(float4*)&AS(buf, arow, acol) = ra;
        *(float4*)&BS(buf, brow, bcol)     = b0;
        *(float4*)&BS(buf, brow, bcol + 4) = b1;
        __syncthreads();
    }

    #pragma unroll
    for (int ks = 0; ks < 2; ks++) {
        wmma::fragment<wmma::matrix_a, 16, 16, 8, wmma::precision::tf32, wmma::row_major> af[2];
        wmma::fragment<wmma::matrix_b, 16, 16, 8, wmma::precision::tf32, wmma::row_major> bf[2];
        wmma::load_matrix_sync(af[0], &AS(buf, wm * 32,      ks * 8), LDA);
        wmma::load_matrix_sync(af[1], &AS(buf, wm * 32 + 16, ks * 8), LDA);
        wmma::load_matrix_sync(bf[0], &BS(buf, ks * 8, wn * 32),      LDB);
        wmma::load_matrix_sync(bf[1], &BS(buf, ks * 8, wn * 32 + 16), LDB);
        wmma::mma_sync(acc[0][0], af[0], bf[0], acc[0][0]);
        wmma::mma_sync(acc[0][1], af[0], bf[1], acc[0][1]);
        wmma::mma_sync(acc[1][0], af[1], bf[0], acc[1][0]);
        wmma::mma_sync(acc[1][1], af[1], bf[1], acc[1][1]);
    }
    __syncthreads();

    // epilogue: stage 32x32 per warp
    float* stg = smem + warp * 32 * LDS_;
    #pragma unroll
    for (int mm = 0; mm < 2; mm++)
        #pragma unroll
        for (int nn = 0; nn < 2; nn++)
            wmma::store_matrix_sync(stg + mm * 16 * LDS_ + nn * 16,
                                    acc[mm][nn], LDS_, wmma::mem_row_major);
    __syncwarp();

    const int growb = tm + wm * 32;
    const int gcolb = tn + wn * 32;
    #pragma unroll
    for (int it = 0; it < 8; it++) {
        int idx = it * 32 + lane;         // 0..255
        int rr = idx >> 3;                // 0..31
        int cc = (idx & 7) * 4;           // 0..28
        int col = gcolb + cc;
        float4 v = *(float4*)(stg + rr * LDS_ + cc);
        if (bias) {
            float4 bb4 = *(const float4*)(bias + col);
            v.x += bb4.x; v.y += bb4.y; v.z += bb4.z; v.w += bb4.w;
        }
        if (act) {
            v.x = v.x > 0.f ? v.x : 0.1f * v.x;
            v.y = v.y > 0.f ? v.y : 0.1f * v.y;
            v.z = v.z > 0.f ? v.z : 0.1f * v.z;
            v.w = v.w > 0.f ? v.w : 0.1f * v.w;
        }
        size_t row = (size_t)(growb + rr);
        if (res) {
            float4 r4 = *(const float4*)(res + row * Nc + col);
            v.x += r4.x; v.y += r4.y; v.z += r4.z; v.w += r4.w;
        }
        *(float4*)(C + row * Nc + col) = v;
    }
    #undef AS
    #undef BS
}

// Strided-batch variant (z = batch index)
__global__ void __launch_bounds__(256, 2)
gemm_tc(const float* __restrict__ A, const float* __restrict__ W,
        const float* __restrict__ bias, const float* __restrict__ res,
        float* __restrict__ C, int Nc, int K,
        long sA, long sW, long sC, int act) {
    __shared__ __align__(16) float smem[SMEM_FLOATS];
    const float* rp = res ? res + (size_t)blockIdx.z * sC : nullptr;
    gemm_body(A + (size_t)blockIdx.z * sA, W + (size_t)blockIdx.z * sW,
              bias, rp, C + (size_t)blockIdx.z * sC, Nc, K, act, smem);
}

// Fused QKV (z = which projection)
__global__ void __launch_bounds__(256, 2)
gemm_qkv(const float* __restrict__ A,
         const float* __restrict__ W0, const float* __restrict__ W1,
         const float* __restrict__ W2,
         const float* __restrict__ b0, const float* __restrict__ b1,
         const float* __restrict__ b2,
         float* __restrict__ C0, float* __restrict__ C1,
         float* __restrict__ C2, int Nc, int K) {
    __shared__ __align__(16) float smem[SMEM_FLOATS];
    const float* W = (blockIdx.z == 0) ? W0 : (blockIdx.z == 1) ? W1 : W2;
    const float* bb = (blockIdx.z == 0) ? b0 : (blockIdx.z == 1) ? b1 : b2;
    float* C = (blockIdx.z == 0) ? C0 : (blockIdx.z == 1) ? C1 : C2;
    gemm_body(A, W, bb, nullptr, C, Nc, K, 0, smem);
}

// ---------------------------------------------------------------------------
// Flash attention: att += 0.3 * softmax(mask(qk^T/s)) @ v
// ---------------------------------------------------------------------------
__global__ void __launch_bounds__(128)
attn_kernel(const float* __restrict__ q,
            const float* __restrict__ k,
            const float* __restrict__ v,
            const int*   __restrict__ mask,
            float* __restrict__ att) {
    const int b = blockIdx.z, h = blockIdx.y;
    const int row = blockIdx.x * 128 + threadIdx.x;

    __shared__ float ks[64][32];
    __shared__ float vs[64][32];
    __shared__ int   ms[64];

    const size_t qoff = ((size_t)(b * Nn) + row) * Dn + h * DKn;
    float qr[32];
    #pragma unroll
    for (int c = 0; c < 8; c++) {
        float4 t = *(const float4*)(q + qoff + c * 4);
        qr[c*4+0] = t.x; qr[c*4+1] = t.y; qr[c*4+2] = t.z; qr[c*4+3] = t.w;
    }

    float acc[32];
    #pragma unroll
    for (int d = 0; d < 32; d++) acc[d] = 0.f;
    float m = -INFINITY, l = 0.f;
    const float scale = 0.17677669529663687f;

    for (int kt = 0; kt < Nn / 64; kt++) {
        __syncthreads();
        for (int t = threadIdx.x; t < 512; t += 128) {
            int r = t >> 3, c = (t & 7) << 2;
            size_t off = ((size_t)(b * Nn) + kt * 64 + r) * Dn + h * DKn + c;
            *(float4*)&ks[r][c] = *(const float4*)(k + off);
            *(float4*)&vs[r][c] = *(const float4*)(v + off);
        }
        if (threadIdx.x < 64) ms[threadIdx.x] = mask[b * Nn + kt * 64 + threadIdx.x];
        __syncthreads();

        #pragma unroll 1
        for (int j0 = 0; j0 < 64; j0 += 8) {
            float s[8];
            #pragma unroll
            for (int jj = 0; jj < 8; jj++) {
                const float* kr = &ks[j0 + jj][0];
                float d0 = 0.f;
                #pragma unroll
                for (int c = 0; c < 8; c++) {
                    float4 k4 = *(const float4*)(kr + c * 4);
                    d0 += qr[c*4+0]*k4.x + qr[c*4+1]*k4.y
                        + qr[c*4+2]*k4.z + qr[c*4+3]*k4.w;
                }
                s[jj] = ms[j0 + jj] ? d0 * scale : -1e12f;
            }
            float tm = s[0];
            #pragma unroll
            for (int jj = 1; jj < 8; jj++) tm = fmaxf(tm, s[jj]);
            float nm = fmaxf(m, tm);
            float sc = __expf(m - nm);
            l *= sc;
            #pragma unroll
            for (int d = 0; d < 32; d++) acc[d] *= sc;
            #pragma unroll
            for (int jj = 0; jj < 8; jj++) {
                float p = __expf(s[jj] - nm);
                l += p;
                const float* vr = &vs[j0 + jj][0];
                #pragma unroll
                for (int c = 0; c < 8; c++) {
                    float4 v4 = *(const float4*)(vr + c * 4);
                    acc[c*4+0] += p * v4.x;
                    acc[c*4+1] += p * v4.y;
                    acc[c*4+2] += p * v4.z;
                    acc[c*4+3] += p * v4.w;
                }
            }
            m = nm;
        }
    }

    const float inv = 0.3f / l;
    float* o = att + qoff;
    #pragma unroll
    for (int c = 0; c < 8; c++) {
        float4 t = *(const float4*)(o + c * 4);
        t.x += acc[c*4+0] * inv;
        t.y += acc[c*4+1] * inv;
        t.z += acc[c*4+2] * inv;
        t.w += acc[c*4+3] * inv;
        *(float4*)(o + c * 4) = t;
    }
}

// ---------------------------------------------------------------------------
// Launch
// ---------------------------------------------------------------------------
extern "C" void kernel_launch(void* const* d_in, const int* in_sizes, int n_in,
                              void* d_out, int out_size) {
    const float* x_in  = (const float*)d_in[0];
    const int*   mask  = (const int*)  d_in[1];
    const float* adj   = (const float*)d_in[2];
    const float* dist  = (const float*)d_in[3];
    const float* Wq    = (const float*)d_in[5];
    const float* bq    = (const float*)d_in[6];
    const float* Wk    = (const float*)d_in[7];
    const float* bk    = (const float*)d_in[8];
    const float* Wv    = (const float*)d_in[9];
    const float* bv    = (const float*)d_in[10];
    const float* Wo    = (const float*)d_in[11];
    const float* bo    = (const float*)d_in[12];
    const float* Wf1   = (const float*)d_in[13];
    const float* bf1   = (const float*)d_in[14];
    const float* Wf2   = (const float*)d_in[15];
    const float* bf2   = (const float*)d_in[16];
    const float* ln1a  = (const float*)d_in[17];
    const float* ln1b  = (const float*)d_in[18];
    const float* ln2a  = (const float*)d_in[19];
    const float* ln2b  = (const float*)d_in[20];
    const float* lnfa  = (const float*)d_in[21];
    const float* lnfb  = (const float*)d_in[22];

    float *px, *ph, *pq, *pk, *pv, *patt, *pt1, *pbase;
    cudaGetSymbolAddress((void**)&px,    g_x);
    cudaGetSymbolAddress((void**)&ph,    g_h);
    cudaGetSymbolAddress((void**)&pq,    g_q);
    cudaGetSymbolAddress((void**)&pk,    g_k);
    cudaGetSymbolAddress((void**)&pv,    g_v);
    cudaGetSymbolAddress((void**)&patt,  g_att);
    cudaGetSymbolAddress((void**)&pt1,   g_t1);
    cudaGetSymbolAddress((void**)&pbase, g_base);

    cudaMemcpyAsync(px, x_in, sizeof(float) * BND, cudaMemcpyDeviceToDevice, 0);

    base_kernel<<<Bn * Nn, 256>>>(dist, adj, mask, pbase);

    const dim3 gProj(Dn / 128, (Bn * Nn) / 64, 1);    // (2,128) = 256 blocks
    const dim3 gQKV (Dn / 128, (Bn * Nn) / 64, 3);    // 768 blocks
    const dim3 gBaseV(Dn / 128, Nn / 64, Bn);         // (2,8,16) = 256 blocks
    const dim3 gAttn(Nn / 128, Hn, Bn);
    const dim3 gLN(Bn * Nn / 8, 1, 1);

    for (int i = 0; i < Ln; i++) {
        const size_t wOff = (size_t)i * Dn * Dn;
        const size_t vOff = (size_t)i * Dn;

        ln_kernel<<<gLN, 256>>>(px, ln1a + vOff, ln1b + vOff, ph);

        gemm_qkv<<<gQKV, 256>>>(ph, Wq + wOff, Wk + wOff, Wv + wOff,
                                bq + vOff, bk + vOff, bv + vOff,
                                pq, pk, pv, Dn, Dn);

        // att = base @ V  (head-independent part of p, pre-scaled)
        gemm_tc<<<gBaseV, 256>>>(pbase, pv, nullptr, nullptr, patt,
                                 Dn, Nn,
                                 (long)Nn * Nn, (long)Nn * Dn, (long)Nn * Dn, 0);

        // att += 0.3 * softmax_attn @ V   (per head)
        attn_kernel<<<gAttn, 128>>>(pq, pk, pv, mask, patt);

        // x = x + att @ Wo + bo
        gemm_tc<<<gProj, 256>>>(patt, Wo + wOff, bo + vOff, px, px,
                                Dn, Dn, 0, 0, 0, 0);

        // FFN
        ln_kernel<<<gLN, 256>>>(px, ln2a + vOff, ln2b + vOff, ph);
        gemm_tc<<<gProj, 256>>>(ph, Wf1 + wOff, bf1 + vOff, nullptr, pt1,
                                Dn, Dn, 0, 0, 0, 1);
        gemm_tc<<<gProj, 256>>>(pt1, Wf2 + wOff, bf2 + vOff, px, px,
                                Dn, Dn, 0, 0, 0, 1);
    }

    ln_kernel<<<gLN, 256>>>(px, lnfa, lnfb, (float*)d_out);
}

// round 5
// speedup vs baseline: 1.7880x; 1.1442x over previous
#include <cuda_runtime.h>
#include <math.h>
#include <mma.h>

using namespace nvcuda;

// Problem constants
#define Bn 16
#define Nn 512
#define Dn 256
#define Hn 8
#define Ln 4
#define DKn 32

#define BND (Bn*Nn*Dn)   // 2,097,152
#define BNN (Bn*Nn*Nn)   // 4,194,304

static __device__ float g_x[BND];
static __device__ float g_h[BND];
static __device__ float g_q[BND];
static __device__ float g_k[BND];
static __device__ float g_v[BND];
static __device__ float g_att[BND];
static __device__ float g_t1[BND];
static __device__ float g_base[BNN];

// ---------------------------------------------------------------------------
// block reductions for base_kernel (256 threads)
// ---------------------------------------------------------------------------
__device__ __forceinline__ float blockSum256(float v) {
    __shared__ float sm[8];
    __syncthreads();
    #pragma unroll
    for (int o = 16; o; o >>= 1) v += __shfl_xor_sync(0xffffffffu, v, o);
    if ((threadIdx.x & 31) == 0) sm[threadIdx.x >> 5] = v;
    __syncthreads();
    float t = 0.f;
    #pragma unroll
    for (int i = 0; i < 8; i++) t += sm[i];
    return t;
}

__device__ __forceinline__ float blockMax256(float v) {
    __shared__ float sm[8];
    __syncthreads();
    #pragma unroll
    for (int o = 16; o; o >>= 1) v = fmaxf(v, __shfl_xor_sync(0xffffffffu, v, o));
    if ((threadIdx.x & 31) == 0) sm[threadIdx.x >> 5] = v;
    __syncthreads();
    float t = sm[0];
    #pragma unroll
    for (int i = 1; i < 8; i++) t = fmaxf(t, sm[i]);
    return t;
}

// ---------------------------------------------------------------------------
// base[b,i,j] = 0.3*softmax_j(mask ? -dist : -inf) + 0.4*adj/(sum_adj+eps)
// ---------------------------------------------------------------------------
__global__ void base_kernel(const float* __restrict__ dist,
                            const float* __restrict__ adj,
                            const int*   __restrict__ mask,
                            float* __restrict__ base) {
    const int bi = blockIdx.x;
    const int b  = bi >> 9;
    const float* dr = dist + (size_t)bi * Nn;
    const float* ar = adj  + (size_t)bi * Nn;
    float*       br = base + (size_t)bi * Nn;
    const int t = threadIdx.x;

    const int m0 = mask[b * Nn + t];
    const int m1 = mask[b * Nn + t + 256];
    float v0 = m0 ? -dr[t]       : -INFINITY;
    float v1 = m1 ? -dr[t + 256] : -INFINITY;

    float mx = blockMax256(fmaxf(v0, v1));
    float e0 = __expf(v0 - mx);
    float e1 = __expf(v1 - mx);
    float ssum = blockSum256(e0 + e1);

    float a0 = ar[t], a1 = ar[t + 256];
    float asum = blockSum256(a0 + a1);

    float cs = 0.3f / ssum;
    float ca = 0.4f / (asum + 1e-6f);
    br[t]       = e0 * cs + a0 * ca;
    br[t + 256] = e1 * cs + a1 * ca;
}

// ---------------------------------------------------------------------------
// LayerNorm (ddof=1), warp per row, shfl-only.
// ---------------------------------------------------------------------------
__global__ void ln_kernel(const float* __restrict__ x,
                          const float* __restrict__ a,
                          const float* __restrict__ bb,
                          float* __restrict__ out) {
    const int warp = threadIdx.x >> 5;
    const int lane = threadIdx.x & 31;
    const size_t row = (size_t)blockIdx.x * 8 + warp;
    const float* xr = x + row * Dn;
    const int c = lane * 8;

    float4 v0 = *(const float4*)(xr + c);
    float4 v1 = *(const float4*)(xr + c + 4);
    float s = v0.x+v0.y+v0.z+v0.w + v1.x+v1.y+v1.z+v1.w;
    #pragma unroll
    for (int o = 16; o; o >>= 1) s += __shfl_xor_sync(0xffffffffu, s, o);
    float mean = s * (1.f / Dn);

    float c0[8] = {v0.x-mean, v0.y-mean, v0.z-mean, v0.w-mean,
                   v1.x-mean, v1.y-mean, v1.z-mean, v1.w-mean};
    float sq = 0.f;
    #pragma unroll
    for (int i = 0; i < 8; i++) sq += c0[i]*c0[i];
    #pragma unroll
    for (int o = 16; o; o >>= 1) sq += __shfl_xor_sync(0xffffffffu, sq, o);
    float inv = 1.f / (sqrtf(sq * (1.f / (Dn - 1))) + 1e-6f);

    float4 a0 = *(const float4*)(a + c);
    float4 a1 = *(const float4*)(a + c + 4);
    float4 b0 = *(const float4*)(bb + c);
    float4 b1 = *(const float4*)(bb + c + 4);
    float4 o0, o1;
    o0.x = a0.x*c0[0]*inv + b0.x;  o0.y = a0.y*c0[1]*inv + b0.y;
    o0.z = a0.z*c0[2]*inv + b0.z;  o0.w = a0.w*c0[3]*inv + b0.w;
    o1.x = a1.x*c0[4]*inv + b1.x;  o1.y = a1.y*c0[5]*inv + b1.y;
    o1.z = a1.z*c0[6]*inv + b1.z;  o1.w = a1.w*c0[7]*inv + b1.w;
    *(float4*)(out + row * Dn + c)     = o0;
    *(float4*)(out + row * Dn + c + 4) = o1;
}

// ---------------------------------------------------------------------------
// TF32 tensor-core GEMM body: 64x128 block tile, BK=16, 8 warps (2x4),
// warp tile 32x32 (wmma m16n16k8), double-buffered.
// ---------------------------------------------------------------------------
#define LDA 20
#define LDB 132
#define LDS_ 36
#define SMEM_FLOATS 9216

__device__ __forceinline__ float4 cvt_tf32_4(float4 v) {
    v.x = wmma::__float_to_tf32(v.x);
    v.y = wmma::__float_to_tf32(v.y);
    v.z = wmma::__float_to_tf32(v.z);
    v.w = wmma::__float_to_tf32(v.w);
    return v;
}

__device__ __forceinline__ void gemm_body(
    const float* __restrict__ A, const float* __restrict__ W,
    const float* __restrict__ bias, const float* __restrict__ res,
    float* __restrict__ C, int Nc, int K, int act, float* smem) {

    const int tm = blockIdx.y * 64;
    const int tn = blockIdx.x * 128;
    const int tid = threadIdx.x;
    const int warp = tid >> 5;
    const int lane = tid & 31;
    const int wm = warp >> 2;
    const int wn = warp & 3;

    #define AS(buf,r,c) smem[(buf)*1280 + (r)*LDA + (c)]
    #define BS(buf,r,c) smem[2560 + (buf)*2112 + (r)*LDB + (c)]

    const int arow = tid >> 2;
    const int acol = (tid & 3) * 4;
    const int brow = tid >> 4;
    const int bcol = (tid & 15) * 8;

    const float* pA = A + (size_t)(tm + arow) * K + acol;
    const float* pB = W + (size_t)brow * Nc + tn + bcol;

    wmma::fragment<wmma::accumulator, 16, 16, 8, float> acc[2][2];
    #pragma unroll
    for (int mm = 0; mm < 2; mm++)
        #pragma unroll
        for (int nn = 0; nn < 2; nn++)
            wmma::fill_fragment(acc[mm][nn], 0.f);

    float4 ra = cvt_tf32_4(*(const float4*)(pA));
    float4 b0 = cvt_tf32_4(*(const float4*)(pB));
    float4 b1 = cvt_tf32_4(*(const float4*)(pB + 4));
    int buf = 0;
    *(float4*)&AS(0, arow, acol) = ra;
    *(float4*)&BS(0, brow, bcol)     = b0;
    *(float4*)&BS(0, brow, bcol + 4) = b1;
    __syncthreads();

    for (int k0 = 16; k0 < K; k0 += 16) {
        ra = cvt_tf32_4(*(const float4*)(pA + k0));
        b0 = cvt_tf32_4(*(const float4*)(pB + (size_t)k0 * Nc));
        b1 = cvt_tf32_4(*(const float4*)(pB + (size_t)k0 * Nc + 4));

        #pragma unroll
        for (int ks = 0; ks < 2; ks++) {
            wmma::fragment<wmma::matrix_a, 16, 16, 8, wmma::precision::tf32, wmma::row_major> af[2];
            wmma::fragment<wmma::matrix_b, 16, 16, 8, wmma::precision::tf32, wmma::row_major> bf[2];
            wmma::load_matrix_sync(af[0], &AS(buf, wm * 32,      ks * 8), LDA);
            wmma::load_matrix_sync(af[1], &AS(buf, wm * 32 + 16, ks * 8), LDA);
            wmma::load_matrix_sync(bf[0], &BS(buf, ks * 8, wn * 32),      LDB);
            wmma::load_matrix_sync(bf[1], &BS(buf, ks * 8, wn * 32 + 16), LDB);
            wmma::mma_sync(acc[0][0], af[0], bf[0], acc[0][0]);
            wmma::mma_sync(acc[0][1], af[0], bf[1], acc[0][1]);
            wmma::mma_sync(acc[1][0], af[1], bf[0], acc[1][0]);
            wmma::mma_sync(acc[1][1], af[1], bf[1], acc[1][1]);
        }

        buf ^= 1;
        *(float4*)&AS(buf, arow, acol) = ra;
        *(float4*)&BS(buf, brow, bcol)     = b0;
        *(float4*)&BS(buf, brow, bcol + 4) = b1;
        __syncthreads();
    }

    #pragma unroll
    for (int ks = 0; ks < 2; ks++) {
        wmma::fragment<wmma::matrix_a, 16, 16, 8, wmma::precision::tf32, wmma::row_major> af[2];
        wmma::fragment<wmma::matrix_b, 16, 16, 8, wmma::precision::tf32, wmma::row_major> bf[2];
        wmma::load_matrix_sync(af[0], &AS(buf, wm * 32,      ks * 8), LDA);
        wmma::load_matrix_sync(af[1], &AS(buf, wm * 32 + 16, ks * 8), LDA);
        wmma::load_matrix_sync(bf[0], &BS(buf, ks * 8, wn * 32),      LDB);
        wmma::load_matrix_sync(bf[1], &BS(buf, ks * 8, wn * 32 + 16), LDB);
        wmma::mma_sync(acc[0][0], af[0], bf[0], acc[0][0]);
        wmma::mma_sync(acc[0][1], af[0], bf[1], acc[0][1]);
        wmma::mma_sync(acc[1][0], af[1], bf[0], acc[1][0]);
        wmma::mma_sync(acc[1][1], af[1], bf[1], acc[1][1]);
    }
    __syncthreads();

    float* stg = smem + warp * 32 * LDS_;
    #pragma unroll
    for (int mm = 0; mm < 2; mm++)
        #pragma unroll
        for (int nn = 0; nn < 2; nn++)
            wmma::store_matrix_sync(stg + mm * 16 * LDS_ + nn * 16,
                                    acc[mm][nn], LDS_, wmma::mem_row_major);
    __syncwarp();

    const int growb = tm + wm * 32;
    const int gcolb = tn + wn * 32;
    #pragma unroll
    for (int it = 0; it < 8; it++) {
        int idx = it * 32 + lane;
        int rr = idx >> 3;
        int cc = (idx & 7) * 4;
        int col = gcolb + cc;
        float4 v = *(float4*)(stg + rr * LDS_ + cc);
        if (bias) {
            float4 bb4 = *(const float4*)(bias + col);
            v.x += bb4.x; v.y += bb4.y; v.z += bb4.z; v.w += bb4.w;
        }
        if (act) {
            v.x = v.x > 0.f ? v.x : 0.1f * v.x;
            v.y = v.y > 0.f ? v.y : 0.1f * v.y;
            v.z = v.z > 0.f ? v.z : 0.1f * v.z;
            v.w = v.w > 0.f ? v.w : 0.1f * v.w;
        }
        size_t row = (size_t)(growb + rr);
        if (res) {
            float4 r4 = *(const float4*)(res + row * Nc + col);
            v.x += r4.x; v.y += r4.y; v.z += r4.z; v.w += r4.w;
        }
        *(float4*)(C + row * Nc + col) = v;
    }
    #undef AS
    #undef BS
}

__global__ void __launch_bounds__(256, 2)
gemm_tc(const float* __restrict__ A, const float* __restrict__ W,
        const float* __restrict__ bias, const float* __restrict__ res,
        float* __restrict__ C, int Nc, int K,
        long sA, long sW, long sC, int act) {
    __shared__ __align__(16) float smem[SMEM_FLOATS];
    const float* rp = res ? res + (size_t)blockIdx.z * sC : nullptr;
    gemm_body(A + (size_t)blockIdx.z * sA, W + (size_t)blockIdx.z * sW,
              bias, rp, C + (size_t)blockIdx.z * sC, Nc, K, act, smem);
}

__global__ void __launch_bounds__(256, 2)
gemm_qkv(const float* __restrict__ A,
         const float* __restrict__ W0, const float* __restrict__ W1,
         const float* __restrict__ W2,
         const float* __restrict__ b0, const float* __restrict__ b1,
         const float* __restrict__ b2,
         float* __restrict__ C0, float* __restrict__ C1,
         float* __restrict__ C2, int Nc, int K) {
    __shared__ __align__(16) float smem[SMEM_FLOATS];
    const float* W = (blockIdx.z == 0) ? W0 : (blockIdx.z == 1) ? W1 : W2;
    const float* bb = (blockIdx.z == 0) ? b0 : (blockIdx.z == 1) ? b1 : b2;
    float* C = (blockIdx.z == 0) ? C0 : (blockIdx.z == 1) ? C1 : C2;
    gemm_body(A, W, bb, nullptr, C, Nc, K, 0, smem);
}

// ---------------------------------------------------------------------------
// Tensor-core flash attention (no running max needed: |scores| is small).
// att += 0.3 * softmax(mask(qk^T/s)) @ v
// Block: one (b,h), 64 q-rows, 4 warps x 16 rows. KV tiles of 64.
// ---------------------------------------------------------------------------
#define ALQ 36
#define ALP 68

__global__ void __launch_bounds__(128)
attn_tc(const float* __restrict__ q,
        const float* __restrict__ k,
        const float* __restrict__ v,
        const int*   __restrict__ mask,
        float* __restrict__ att) {
    __shared__ __align__(16) float Qs[64][ALQ];
    __shared__ __align__(16) float Ks[64][ALQ];
    __shared__ __align__(16) float Vs[64][ALQ];
    __shared__ __align__(16) float Ps[4][16][ALP];
    __shared__ int ms[64];

    const int b = blockIdx.z, h = blockIdx.y;
    const int tid = threadIdx.x;
    const int warp = tid >> 5;
    const int lane = tid & 31;
    const int qrow0 = blockIdx.x * 64;
    const float scale = 0.17677669529663687f;   // 1/sqrt(32)

    // load Q tile (64x32) -> tf32
    for (int i = tid; i < 64 * 8; i += 128) {
        int r = i >> 3, c = (i & 7) * 4;
        float4 t = *(const float4*)(q + ((size_t)(b * Nn + qrow0 + r)) * Dn + h * DKn + c);
        *(float4*)&Qs[r][c] = cvt_tf32_4(t);
    }

    wmma::fragment<wmma::accumulator, 16, 16, 8, float> ao[2];
    wmma::fill_fragment(ao[0], 0.f);
    wmma::fill_fragment(ao[1], 0.f);

    float l_tot = 0.f;
    const int myrow = lane >> 1;            // 0..15
    const int colh = (lane & 1) * 32;       // 0 or 32

    for (int kt = 0; kt < Nn / 64; kt++) {
        __syncthreads();
        for (int i = tid; i < 64 * 8; i += 128) {
            int r = i >> 3, c = (i & 7) * 4;
            size_t off = ((size_t)(b * Nn + kt * 64 + r)) * Dn + h * DKn + c;
            *(float4*)&Ks[r][c] = cvt_tf32_4(*(const float4*)(k + off));
            *(float4*)&Vs[r][c] = cvt_tf32_4(*(const float4*)(v + off));
        }
        if (tid < 64) ms[tid] = mask[b * Nn + kt * 64 + tid];
        __syncthreads();

        // S = Q @ K^T  (warp's 16 rows x 64 cols)
        wmma::fragment<wmma::accumulator, 16, 16, 8, float> sf[4];
        #pragma unroll
        for (int n = 0; n < 4; n++) wmma::fill_fragment(sf[n], 0.f);
        #pragma unroll
        for (int ks = 0; ks < 4; ks++) {
            wmma::fragment<wmma::matrix_a, 16, 16, 8, wmma::precision::tf32, wmma::row_major> af;
            wmma::load_matrix_sync(af, &Qs[warp * 16][ks * 8], ALQ);
            #pragma unroll
            for (int n = 0; n < 4; n++) {
                wmma::fragment<wmma::matrix_b, 16, 16, 8, wmma::precision::tf32, wmma::col_major> bf;
                wmma::load_matrix_sync(bf, &Ks[n * 16][ks * 8], ALQ);
                wmma::mma_sync(sf[n], af, bf, sf[n]);
            }
        }
        #pragma unroll
        for (int n = 0; n < 4; n++)
            wmma::store_matrix_sync(&Ps[warp][0][n * 16], sf[n], ALP, wmma::mem_row_major);
        __syncwarp();

        // p = mask ? exp(s*scale) : 0 ; accumulate row sums
        float lp = 0.f;
        float* prow = &Ps[warp][myrow][colh];
        const int* mrow = ms + colh;
        #pragma unroll
        for (int j = 0; j < 32; j++) {
            float p = mrow[j] ? __expf(prow[j] * scale) : 0.f;
            lp += p;
            prow[j] = wmma::__float_to_tf32(p);
        }
        lp += __shfl_xor_sync(0xffffffffu, lp, 1);
        l_tot += lp;
        __syncwarp();

        // O += P @ V
        #pragma unroll
        for (int ks = 0; ks < 8; ks++) {
            wmma::fragment<wmma::matrix_a, 16, 16, 8, wmma::precision::tf32, wmma::row_major> af;
            wmma::load_matrix_sync(af, &Ps[warp][0][ks * 8], ALP);
            #pragma unroll
            for (int n = 0; n < 2; n++) {
                wmma::fragment<wmma::matrix_b, 16, 16, 8, wmma::precision::tf32, wmma::row_major> bf;
                wmma::load_matrix_sync(bf, &Vs[ks * 8][n * 16], ALQ);
                wmma::mma_sync(ao[n], af, bf, ao[n]);
            }
        }
    }

    // epilogue: stage O (16x32) in warp's P buffer, apply 0.3/l, accumulate
    float* Os = &Ps[warp][0][0];
    wmma::store_matrix_sync(Os,      ao[0], ALP, wmma::mem_row_major);
    wmma::store_matrix_sync(Os + 16, ao[1], ALP, wmma::mem_row_major);
    __syncwarp();

    const float inv = 0.3f / l_tot;
    const int ch = (lane & 1) * 16;
    float* orow = att + ((size_t)(b * Nn + qrow0 + warp * 16 + myrow)) * Dn + h * DKn + ch;
    float* srow = Os + myrow * ALP + ch;
    #pragma unroll
    for (int c = 0; c < 4; c++) {
        float4 t = *(float4*)(orow + c * 4);
        float4 s4 = *(float4*)(srow + c * 4);
        t.x += s4.x * inv; t.y += s4.y * inv;
        t.z += s4.z * inv; t.w += s4.w * inv;
        *(float4*)(orow + c * 4) = t;
    }
}

// ---------------------------------------------------------------------------
// Launch
// ---------------------------------------------------------------------------
extern "C" void kernel_launch(void* const* d_in, const int* in_sizes, int n_in,
                              void* d_out, int out_size) {
    const float* x_in  = (const float*)d_in[0];
    const int*   mask  = (const int*)  d_in[1];
    const float* adj   = (const float*)d_in[2];
    const float* dist  = (const float*)d_in[3];
    const float* Wq    = (const float*)d_in[5];
    const float* bq    = (const float*)d_in[6];
    const float* Wk    = (const float*)d_in[7];
    const float* bk    = (const float*)d_in[8];
    const float* Wv    = (const float*)d_in[9];
    const float* bv    = (const float*)d_in[10];
    const float* Wo    = (const float*)d_in[11];
    const float* bo    = (const float*)d_in[12];
    const float* Wf1   = (const float*)d_in[13];
    const float* bf1   = (const float*)d_in[14];
    const float* Wf2   = (const float*)d_in[15];
    const float* bf2   = (const float*)d_in[16];
    const float* ln1a  = (const float*)d_in[17];
    const float* ln1b  = (const float*)d_in[18];
    const float* ln2a  = (const float*)d_in[19];
    const float* ln2b  = (const float*)d_in[20];
    const float* lnfa  = (const float*)d_in[21];
    const float* lnfb  = (const float*)d_in[22];

    float *px, *ph, *pq, *pk, *pv, *patt, *pt1, *pbase;
    cudaGetSymbolAddress((void**)&px,    g_x);
    cudaGetSymbolAddress((void**)&ph,    g_h);
    cudaGetSymbolAddress((void**)&pq,    g_q);
    cudaGetSymbolAddress((void**)&pk,    g_k);
    cudaGetSymbolAddress((void**)&pv,    g_v);
    cudaGetSymbolAddress((void**)&patt,  g_att);
    cudaGetSymbolAddress((void**)&pt1,   g_t1);
    cudaGetSymbolAddress((void**)&pbase, g_base);

    cudaMemcpyAsync(px, x_in, sizeof(float) * BND, cudaMemcpyDeviceToDevice, 0);

    base_kernel<<<Bn * Nn, 256>>>(dist, adj, mask, pbase);

    const dim3 gProj(Dn / 128, (Bn * Nn) / 64, 1);    // 256 blocks
    const dim3 gQKV (Dn / 128, (Bn * Nn) / 64, 3);    // 768 blocks
    const dim3 gBaseV(Dn / 128, Nn / 64, Bn);         // 256 blocks
    const dim3 gAttn(Nn / 64, Hn, Bn);                // (8,8,16) = 1024 blocks
    const dim3 gLN(Bn * Nn / 8, 1, 1);

    for (int i = 0; i < Ln; i++) {
        const size_t wOff = (size_t)i * Dn * Dn;
        const size_t vOff = (size_t)i * Dn;

        ln_kernel<<<gLN, 256>>>(px, ln1a + vOff, ln1b + vOff, ph);

        gemm_qkv<<<gQKV, 256>>>(ph, Wq + wOff, Wk + wOff, Wv + wOff,
                                bq + vOff, bk + vOff, bv + vOff,
                                pq, pk, pv, Dn, Dn);

        // att = base @ V  (head-independent part, pre-scaled by lambdas)
        gemm_tc<<<gBaseV, 256>>>(pbase, pv, nullptr, nullptr, patt,
                                 Dn, Nn,
                                 (long)Nn * Nn, (long)Nn * Dn, (long)Nn * Dn, 0);

        // att += 0.3 * softmax_attn @ V   (tensor-core flash, no max)
        attn_tc<<<gAttn, 128>>>(pq, pk, pv, mask, patt);

        // x = x + att @ Wo + bo
        gemm_tc<<<gProj, 256>>>(patt, Wo + wOff, bo + vOff, px, px,
                                Dn, Dn, 0, 0, 0, 0);

        // FFN
        ln_kernel<<<gLN, 256>>>(px, ln2a + vOff, ln2b + vOff, ph);
        gemm_tc<<<gProj, 256>>>(ph, Wf1 + wOff, bf1 + vOff, nullptr, pt1,
                                Dn, Dn, 0, 0, 0, 1);
        gemm_tc<<<gProj, 256>>>(pt1, Wf2 + wOff, bf2 + vOff, px, px,
                                Dn, Dn, 0, 0, 0, 1);
    }

    ln_kernel<<<gLN, 256>>>(px, lnfa, lnfb, (float*)d_out);
}

// round 6
// speedup vs baseline: 2.9752x; 1.6640x over previous
#include <cuda_runtime.h>
#include <cuda_fp16.h>
#include <math.h>
#include <mma.h>

using namespace nvcuda;

// Problem constants
#define Bn 16
#define Nn 512
#define Dn 256
#define Hn 8
#define Ln 4
#define DKn 32

#define BND (Bn*Nn*Dn)   // 2,097,152
#define BNN (Bn*Nn*Nn)   // 4,194,304

static __device__ float g_x[BND];
static __device__ float g_h[BND];
static __device__ float g_q[BND];
static __device__ float g_k[BND];
static __device__ float g_v[BND];
static __device__ float g_att[BND];
static __device__ float g_t1[BND];
static __device__ float g_base[BNN];

// ---------------------------------------------------------------------------
// helpers
// ---------------------------------------------------------------------------
__device__ __forceinline__ uint4 pack_h8(float4 a, float4 b) {
    half2 h0 = __floats2half2_rn(a.x, a.y);
    half2 h1 = __floats2half2_rn(a.z, a.w);
    half2 h2 = __floats2half2_rn(b.x, b.y);
    half2 h3 = __floats2half2_rn(b.z, b.w);
    uint4 r;
    r.x = *(unsigned*)&h0; r.y = *(unsigned*)&h1;
    r.z = *(unsigned*)&h2; r.w = *(unsigned*)&h3;
    return r;
}

// ---------------------------------------------------------------------------
// block reductions for base_kernel (256 threads)
// ---------------------------------------------------------------------------
__device__ __forceinline__ float blockSum256(float v) {
    __shared__ float sm[8];
    __syncthreads();
    #pragma unroll
    for (int o = 16; o; o >>= 1) v += __shfl_xor_sync(0xffffffffu, v, o);
    if ((threadIdx.x & 31) == 0) sm[threadIdx.x >> 5] = v;
    __syncthreads();
    float t = 0.f;
    #pragma unroll
    for (int i = 0; i < 8; i++) t += sm[i];
    return t;
}

__device__ __forceinline__ float blockMax256(float v) {
    __shared__ float sm[8];
    __syncthreads();
    #pragma unroll
    for (int o = 16; o; o >>= 1) v = fmaxf(v, __shfl_xor_sync(0xffffffffu, v, o));
    if ((threadIdx.x & 31) == 0) sm[threadIdx.x >> 5] = v;
    __syncthreads();
    float t = sm[0];
    #pragma unroll
    for (int i = 1; i < 8; i++) t = fmaxf(t, sm[i]);
    return t;
}

// ---------------------------------------------------------------------------
// base[b,i,j] = 0.3*softmax_j(mask ? -dist : -inf) + 0.4*adj/(sum_adj+eps)
// ---------------------------------------------------------------------------
__global__ void base_kernel(const float* __restrict__ dist,
                            const float* __restrict__ adj,
                            const int*   __restrict__ mask,
                            float* __restrict__ base) {
    const int bi = blockIdx.x;
    const int b  = bi >> 9;
    const float* dr = dist + (size_t)bi * Nn;
    const float* ar = adj  + (size_t)bi * Nn;
    float*       br = base + (size_t)bi * Nn;
    const int t = threadIdx.x;

    const int m0 = mask[b * Nn + t];
    const int m1 = mask[b * Nn + t + 256];
    float v0 = m0 ? -dr[t]       : -INFINITY;
    float v1 = m1 ? -dr[t + 256] : -INFINITY;

    float mx = blockMax256(fmaxf(v0, v1));
    float e0 = __expf(v0 - mx);
    float e1 = __expf(v1 - mx);
    float ssum = blockSum256(e0 + e1);

    float a0 = ar[t], a1 = ar[t + 256];
    float asum = blockSum256(a0 + a1);

    float cs = 0.3f / ssum;
    float ca = 0.4f / (asum + 1e-6f);
    br[t]       = e0 * cs + a0 * ca;
    br[t + 256] = e1 * cs + a1 * ca;
}

// ---------------------------------------------------------------------------
// LayerNorm (ddof=1), warp per row, shfl-only.
// ---------------------------------------------------------------------------
__global__ void ln_kernel(const float* __restrict__ x,
                          const float* __restrict__ a,
                          const float* __restrict__ bb,
                          float* __restrict__ out) {
    const int warp = threadIdx.x >> 5;
    const int lane = threadIdx.x & 31;
    const size_t row = (size_t)blockIdx.x * 8 + warp;
    const float* xr = x + row * Dn;
    const int c = lane * 8;

    float4 v0 = *(const float4*)(xr + c);
    float4 v1 = *(const float4*)(xr + c + 4);
    float s = v0.x+v0.y+v0.z+v0.w + v1.x+v1.y+v1.z+v1.w;
    #pragma unroll
    for (int o = 16; o; o >>= 1) s += __shfl_xor_sync(0xffffffffu, s, o);
    float mean = s * (1.f / Dn);

    float c0[8] = {v0.x-mean, v0.y-mean, v0.z-mean, v0.w-mean,
                   v1.x-mean, v1.y-mean, v1.z-mean, v1.w-mean};
    float sq = 0.f;
    #pragma unroll
    for (int i = 0; i < 8; i++) sq += c0[i]*c0[i];
    #pragma unroll
    for (int o = 16; o; o >>= 1) sq += __shfl_xor_sync(0xffffffffu, sq, o);
    float inv = 1.f / (sqrtf(sq * (1.f / (Dn - 1))) + 1e-6f);

    float4 a0 = *(const float4*)(a + c);
    float4 a1 = *(const float4*)(a + c + 4);
    float4 b0 = *(const float4*)(bb + c);
    float4 b1 = *(const float4*)(bb + c + 4);
    float4 o0, o1;
    o0.x = a0.x*c0[0]*inv + b0.x;  o0.y = a0.y*c0[1]*inv + b0.y;
    o0.z = a0.z*c0[2]*inv + b0.z;  o0.w = a0.w*c0[3]*inv + b0.w;
    o1.x = a1.x*c0[4]*inv + b1.x;  o1.y = a1.y*c0[5]*inv + b1.y;
    o1.z = a1.z*c0[6]*inv + b1.z;  o1.w = a1.w*c0[7]*inv + b1.w;
    *(float4*)(out + row * Dn + c)     = o0;
    *(float4*)(out + row * Dn + c + 4) = o1;
}

// ---------------------------------------------------------------------------
// FP16 tensor-core GEMM body: 64x128 block tile, BK=32 (halves), 8 warps (2x4),
// warp tile 32x32 (wmma m16n16k16), double-buffered, fp32 accumulate.
// ---------------------------------------------------------------------------
#define LDAH 40     // A row stride in halves (64 rows)
#define LDBH 136    // B row stride in halves (32 rows)
#define LDS_ 36
#define SMEM_BYTES 36864  // max(mainloop 27648, stage 9216 floats)

__device__ __forceinline__ void gemm_body(
    const float* __restrict__ A, const float* __restrict__ W,
    const float* __restrict__ bias, const float* __restrict__ res,
    float* __restrict__ C, int Nc, int K, int act, char* smemc) {

    half*  hs  = (half*)smemc;
    float* fst = (float*)smemc;

    const int tm = blockIdx.y * 64;
    const int tn = blockIdx.x * 128;
    const int tid = threadIdx.x;
    const int warp = tid >> 5;
    const int lane = tid & 31;
    const int wm = warp >> 2;
    const int wn = warp & 3;

    #define ASH(buf,r,c) hs[(buf)*2560 + (r)*LDAH + (c)]
    #define BSH(buf,r,c) hs[5120 + (buf)*4352 + (r)*LDBH + (c)]

    // A: 64x32 floats -> thread loads 8 floats. B: 32x128 -> 16 floats.
    const int arow = tid >> 2;            // 0..63
    const int acol = (tid & 3) * 8;       // 0,8,16,24
    const int brow = tid >> 3;            // 0..31
    const int bcol = (tid & 7) * 16;      // 0..112

    const float* pA = A + (size_t)(tm + arow) * K + acol;
    const float* pB = W + (size_t)brow * Nc + tn + bcol;

    wmma::fragment<wmma::accumulator, 16, 16, 16, float> acc[2][2];
    #pragma unroll
    for (int mm = 0; mm < 2; mm++)
        #pragma unroll
        for (int nn = 0; nn < 2; nn++)
            wmma::fill_fragment(acc[mm][nn], 0.f);

    // prologue
    float4 ra0 = *(const float4*)(pA);
    float4 ra1 = *(const float4*)(pA + 4);
    float4 rb0 = *(const float4*)(pB);
    float4 rb1 = *(const float4*)(pB + 4);
    float4 rb2 = *(const float4*)(pB + 8);
    float4 rb3 = *(const float4*)(pB + 12);
    int buf = 0;
    *(uint4*)&ASH(0, arow, acol)      = pack_h8(ra0, ra1);
    *(uint4*)&BSH(0, brow, bcol)      = pack_h8(rb0, rb1);
    *(uint4*)&BSH(0, brow, bcol + 8)  = pack_h8(rb2, rb3);
    __syncthreads();

    for (int k0 = 32; k0 < K; k0 += 32) {
        ra0 = *(const float4*)(pA + k0);
        ra1 = *(const float4*)(pA + k0 + 4);
        const float* pBk = pB + (size_t)k0 * Nc;
        rb0 = *(const float4*)(pBk);
        rb1 = *(const float4*)(pBk + 4);
        rb2 = *(const float4*)(pBk + 8);
        rb3 = *(const float4*)(pBk + 12);

        #pragma unroll
        for (int ks = 0; ks < 2; ks++) {
            wmma::fragment<wmma::matrix_a, 16, 16, 16, half, wmma::row_major> af[2];
            wmma::fragment<wmma::matrix_b, 16, 16, 16, half, wmma::row_major> bf[2];
            wmma::load_matrix_sync(af[0], &ASH(buf, wm * 32,      ks * 16), LDAH);
            wmma::load_matrix_sync(af[1], &ASH(buf, wm * 32 + 16, ks * 16), LDAH);
            wmma::load_matrix_sync(bf[0], &BSH(buf, ks * 16, wn * 32),      LDBH);
            wmma::load_matrix_sync(bf[1], &BSH(buf, ks * 16, wn * 32 + 16), LDBH);
            wmma::mma_sync(acc[0][0], af[0], bf[0], acc[0][0]);
            wmma::mma_sync(acc[0][1], af[0], bf[1], acc[0][1]);
            wmma::mma_sync(acc[1][0], af[1], bf[0], acc[1][0]);
            wmma::mma_sync(acc[1][1], af[1], bf[1], acc[1][1]);
        }

        buf ^= 1;
        *(uint4*)&ASH(buf, arow, acol)     = pack_h8(ra0, ra1);
        *(uint4*)&BSH(buf, brow, bcol)     = pack_h8(rb0, rb1);
        *(uint4*)&BSH(buf, brow, bcol + 8) = pack_h8(rb2, rb3);
        __syncthreads();
    }

    #pragma unroll
    for (int ks = 0; ks < 2; ks++) {
        wmma::fragment<wmma::matrix_a, 16, 16, 16, half, wmma::row_major> af[2];
        wmma::fragment<wmma::matrix_b, 16, 16, 16, half, wmma::row_major> bf[2];
        wmma::load_matrix_sync(af[0], &ASH(buf, wm * 32,      ks * 16), LDAH);
        wmma::load_matrix_sync(af[1], &ASH(buf, wm * 32 + 16, ks * 16), LDAH);
        wmma::load_matrix_sync(bf[0], &BSH(buf, ks * 16, wn * 32),      LDBH);
        wmma::load_matrix_sync(bf[1], &BSH(buf, ks * 16, wn * 32 + 16), LDBH);
        wmma::mma_sync(acc[0][0], af[0], bf[0], acc[0][0]);
        wmma::mma_sync(acc[0][1], af[0], bf[1], acc[0][1]);
        wmma::mma_sync(acc[1][0], af[1], bf[0], acc[1][0]);
        wmma::mma_sync(acc[1][1], af[1], bf[1], acc[1][1]);
    }
    __syncthreads();   // before stage reuse

    float* stg = fst + warp * 32 * LDS_;
    #pragma unroll
    for (int mm = 0; mm < 2; mm++)
        #pragma unroll
        for (int nn = 0; nn < 2; nn++)
            wmma::store_matrix_sync(stg + mm * 16 * LDS_ + nn * 16,
                                    acc[mm][nn], LDS_, wmma::mem_row_major);
    __syncwarp();

    const int growb = tm + wm * 32;
    const int gcolb = tn + wn * 32;
    #pragma unroll
    for (int it = 0; it < 8; it++) {
        int idx = it * 32 + lane;
        int rr = idx >> 3;
        int cc = (idx & 7) * 4;
        int col = gcolb + cc;
        float4 v = *(float4*)(stg + rr * LDS_ + cc);
        if (bias) {
            float4 bb4 = *(const float4*)(bias + col);
            v.x += bb4.x; v.y += bb4.y; v.z += bb4.z; v.w += bb4.w;
        }
        if (act) {
            v.x = v.x > 0.f ? v.x : 0.1f * v.x;
            v.y = v.y > 0.f ? v.y : 0.1f * v.y;
            v.z = v.z > 0.f ? v.z : 0.1f * v.z;
            v.w = v.w > 0.f ? v.w : 0.1f * v.w;
        }
        size_t row = (size_t)(growb + rr);
        if (res) {
            float4 r4 = *(const float4*)(res + row * Nc + col);
            v.x += r4.x; v.y += r4.y; v.z += r4.z; v.w += r4.w;
        }
        *(float4*)(C + row * Nc + col) = v;
    }
    #undef ASH
    #undef BSH
}

__global__ void __launch_bounds__(256, 2)
gemm_tc(const float* __restrict__ A, const float* __restrict__ W,
        const float* __restrict__ bias, const float* __restrict__ res,
        float* __restrict__ C, int Nc, int K,
        long sA, long sW, long sC, int act) {
    __shared__ __align__(16) char smem[SMEM_BYTES];
    const float* rp = res ? res + (size_t)blockIdx.z * sC : nullptr;
    gemm_body(A + (size_t)blockIdx.z * sA, W + (size_t)blockIdx.z * sW,
              bias, rp, C + (size_t)blockIdx.z * sC, Nc, K, act, smem);
}

__global__ void __launch_bounds__(256, 2)
gemm_qkv(const float* __restrict__ A,
         const float* __restrict__ W0, const float* __restrict__ W1,
         const float* __restrict__ W2,
         const float* __restrict__ b0, const float* __restrict__ b1,
         const float* __restrict__ b2,
         float* __restrict__ C0, float* __restrict__ C1,
         float* __restrict__ C2, int Nc, int K) {
    __shared__ __align__(16) char smem[SMEM_BYTES];
    const float* W = (blockIdx.z == 0) ? W0 : (blockIdx.z == 1) ? W1 : W2;
    const float* bb = (blockIdx.z == 0) ? b0 : (blockIdx.z == 1) ? b1 : b2;
    float* C = (blockIdx.z == 0) ? C0 : (blockIdx.z == 1) ? C1 : C2;
    gemm_body(A, W, bb, nullptr, C, Nc, K, 0, smem);
}

// ---------------------------------------------------------------------------
// FP16 tensor-core flash attention (no running max: scores are bounded).
// att += 0.3 * softmax(mask(qk^T/s)) @ v
// Block: one (b,h), 64 q-rows, 4 warps x 16 rows. KV tiles of 64.
// ---------------------------------------------------------------------------
#define ALQH 40   // halves
#define ALP  68   // floats (score stage)
#define ALPH 72   // halves (P stage)

__global__ void __launch_bounds__(128)
attn_tc(const float* __restrict__ q,
        const float* __restrict__ k,
        const float* __restrict__ v,
        const int*   __restrict__ mask,
        float* __restrict__ att) {
    __shared__ __align__(16) half  Qs[64][ALQH];
    __shared__ __align__(16) half  Ks[64][ALQH];
    __shared__ __align__(16) half  Vs[64][ALQH];
    __shared__ __align__(16) float Ps[4][16][ALP];
    __shared__ __align__(16) half  Ph[4][16][ALPH];
    __shared__ int ms[64];

    const int b = blockIdx.z, h = blockIdx.y;
    const int tid = threadIdx.x;
    const int warp = tid >> 5;
    const int lane = tid & 31;
    const int qrow0 = blockIdx.x * 64;
    const float scale = 0.17677669529663687f;   // 1/sqrt(32)

    // load Q tile (64x32) -> half. thread: row tid>>1, col half (tid&1)*16
    {
        int r = tid >> 1, c = (tid & 1) * 16;
        const float* src = q + ((size_t)(b * Nn + qrow0 + r)) * Dn + h * DKn + c;
        float4 t0 = *(const float4*)(src);
        float4 t1 = *(const float4*)(src + 4);
        float4 t2 = *(const float4*)(src + 8);
        float4 t3 = *(const float4*)(src + 12);
        *(uint4*)&Qs[r][c]     = pack_h8(t0, t1);
        *(uint4*)&Qs[r][c + 8] = pack_h8(t2, t3);
    }

    wmma::fragment<wmma::accumulator, 16, 16, 16, float> ao[2];
    wmma::fill_fragment(ao[0], 0.f);
    wmma::fill_fragment(ao[1], 0.f);

    float l_tot = 0.f;
    const int myrow = lane >> 1;
    const int colh = (lane & 1) * 32;

    for (int kt = 0; kt < Nn / 64; kt++) {
        __syncthreads();
        {
            int r = tid >> 1, c = (tid & 1) * 16;
            size_t off = ((size_t)(b * Nn + kt * 64 + r)) * Dn + h * DKn + c;
            float4 t0 = *(const float4*)(k + off);
            float4 t1 = *(const float4*)(k + off + 4);
            float4 t2 = *(const float4*)(k + off + 8);
            float4 t3 = *(const float4*)(k + off + 12);
            *(uint4*)&Ks[r][c]     = pack_h8(t0, t1);
            *(uint4*)&Ks[r][c + 8] = pack_h8(t2, t3);
            t0 = *(const float4*)(v + off);
            t1 = *(const float4*)(v + off + 4);
            t2 = *(const float4*)(v + off + 8);
            t3 = *(const float4*)(v + off + 12);
            *(uint4*)&Vs[r][c]     = pack_h8(t0, t1);
            *(uint4*)&Vs[r][c + 8] = pack_h8(t2, t3);
        }
        if (tid < 64) ms[tid] = mask[b * Nn + kt * 64 + tid];
        __syncthreads();

        // S = Q @ K^T  (warp's 16 rows x 64 cols), k = 32 via 2 k-steps
        wmma::fragment<wmma::accumulator, 16, 16, 16, float> sf[4];
        #pragma unroll
        for (int n = 0; n < 4; n++) wmma::fill_fragment(sf[n], 0.f);
        #pragma unroll
        for (int ks = 0; ks < 2; ks++) {
            wmma::fragment<wmma::matrix_a, 16, 16, 16, half, wmma::row_major> af;
            wmma::load_matrix_sync(af, &Qs[warp * 16][ks * 16], ALQH);
            #pragma unroll
            for (int n = 0; n < 4; n++) {
                wmma::fragment<wmma::matrix_b, 16, 16, 16, half, wmma::col_major> bf;
                wmma::load_matrix_sync(bf, &Ks[n * 16][ks * 16], ALQH);
                wmma::mma_sync(sf[n], af, bf, sf[n]);
            }
        }
        #pragma unroll
        for (int n = 0; n < 4; n++)
            wmma::store_matrix_sync(&Ps[warp][0][n * 16], sf[n], ALP, wmma::mem_row_major);
        __syncwarp();

        // p = mask ? exp(s*scale) : 0 ; row sums; write half P
        float lp = 0.f;
        const float* srow = &Ps[warp][myrow][colh];
        half* prow = &Ph[warp][myrow][colh];
        const int* mrow = ms + colh;
        #pragma unroll
        for (int j = 0; j < 32; j += 2) {
            float p0 = mrow[j]     ? __expf(srow[j]     * scale) : 0.f;
            float p1 = mrow[j + 1] ? __expf(srow[j + 1] * scale) : 0.f;
            lp += p0 + p1;
            *(half2*)(prow + j) = __floats2half2_rn(p0, p1);
        }
        lp += __shfl_xor_sync(0xffffffffu, lp, 1);
        l_tot += lp;
        __syncwarp();

        // O += P @ V  (k = 64 via 4 k-steps)
        #pragma unroll
        for (int ks = 0; ks < 4; ks++) {
            wmma::fragment<wmma::matrix_a, 16, 16, 16, half, wmma::row_major> af;
            wmma::load_matrix_sync(af, &Ph[warp][0][ks * 16], ALPH);
            #pragma unroll
            for (int n = 0; n < 2; n++) {
                wmma::fragment<wmma::matrix_b, 16, 16, 16, half, wmma::row_major> bf;
                wmma::load_matrix_sync(bf, &Vs[ks * 16][n * 16], ALQH);
                wmma::mma_sync(ao[n], af, bf, ao[n]);
            }
        }
    }

    // epilogue: stage O (16x32) in warp's float buffer, apply 0.3/l, accumulate
    float* Os = &Ps[warp][0][0];
    wmma::store_matrix_sync(Os,      ao[0], ALP, wmma::mem_row_major);
    wmma::store_matrix_sync(Os + 16, ao[1], ALP, wmma::mem_row_major);
    __syncwarp();

    const float inv = 0.3f / l_tot;
    const int ch = (lane & 1) * 16;
    float* orow = att + ((size_t)(b * Nn + qrow0 + warp * 16 + myrow)) * Dn + h * DKn + ch;
    float* sro = Os + myrow * ALP + ch;
    #pragma unroll
    for (int c = 0; c < 4; c++) {
        float4 t = *(float4*)(orow + c * 4);
        float4 s4 = *(float4*)(sro + c * 4);
        t.x += s4.x * inv; t.y += s4.y * inv;
        t.z += s4.z * inv; t.w += s4.w * inv;
        *(float4*)(orow + c * 4) = t;
    }
}

// ---------------------------------------------------------------------------
// Launch
// ---------------------------------------------------------------------------
extern "C" void kernel_launch(void* const* d_in, const int* in_sizes, int n_in,
                              void* d_out, int out_size) {
    const float* x_in  = (const float*)d_in[0];
    const int*   mask  = (const int*)  d_in[1];
    const float* adj   = (const float*)d_in[2];
    const float* dist  = (const float*)d_in[3];
    const float* Wq    = (const float*)d_in[5];
    const float* bq    = (const float*)d_in[6];
    const float* Wk    = (const float*)d_in[7];
    const float* bk    = (const float*)d_in[8];
    const float* Wv    = (const float*)d_in[9];
    const float* bv    = (const float*)d_in[10];
    const float* Wo    = (const float*)d_in[11];
    const float* bo    = (const float*)d_in[12];
    const float* Wf1   = (const float*)d_in[13];
    const float* bf1   = (const float*)d_in[14];
    const float* Wf2   = (const float*)d_in[15];
    const float* bf2   = (const float*)d_in[16];
    const float* ln1a  = (const float*)d_in[17];
    const float* ln1b  = (const float*)d_in[18];
    const float* ln2a  = (const float*)d_in[19];
    const float* ln2b  = (const float*)d_in[20];
    const float* lnfa  = (const float*)d_in[21];
    const float* lnfb  = (const float*)d_in[22];

    float *px, *ph, *pq, *pk, *pv, *patt, *pt1, *pbase;
    cudaGetSymbolAddress((void**)&px,    g_x);
    cudaGetSymbolAddress((void**)&ph,    g_h);
    cudaGetSymbolAddress((void**)&pq,    g_q);
    cudaGetSymbolAddress((void**)&pk,    g_k);
    cudaGetSymbolAddress((void**)&pv,    g_v);
    cudaGetSymbolAddress((void**)&patt,  g_att);
    cudaGetSymbolAddress((void**)&pt1,   g_t1);
    cudaGetSymbolAddress((void**)&pbase, g_base);

    cudaMemcpyAsync(px, x_in, sizeof(float) * BND, cudaMemcpyDeviceToDevice, 0);

    base_kernel<<<Bn * Nn, 256>>>(dist, adj, mask, pbase);

    const dim3 gProj(Dn / 128, (Bn * Nn) / 64, 1);    // 256 blocks
    const dim3 gQKV (Dn / 128, (Bn * Nn) / 64, 3);    // 768 blocks
    const dim3 gBaseV(Dn / 128, Nn / 64, Bn);         // 256 blocks
    const dim3 gAttn(Nn / 64, Hn, Bn);                // 1024 blocks
    const dim3 gLN(Bn * Nn / 8, 1, 1);

    for (int i = 0; i < Ln; i++) {
        const size_t wOff = (size_t)i * Dn * Dn;
        const size_t vOff = (size_t)i * Dn;

        ln_kernel<<<gLN, 256>>>(px, ln1a + vOff, ln1b + vOff, ph);

        gemm_qkv<<<gQKV, 256>>>(ph, Wq + wOff, Wk + wOff, Wv + wOff,
                                bq + vOff, bk + vOff, bv + vOff,
                                pq, pk, pv, Dn, Dn);

        // att = base @ V  (head-independent part, pre-scaled by lambdas)
        gemm_tc<<<gBaseV, 256>>>(pbase, pv, nullptr, nullptr, patt,
                                 Dn, Nn,
                                 (long)Nn * Nn, (long)Nn * Dn, (long)Nn * Dn, 0);

        // att += 0.3 * softmax_attn @ V   (fp16 tensor-core flash, no max)
        attn_tc<<<gAttn, 128>>>(pq, pk, pv, mask, patt);

        // x = x + att @ Wo + bo
        gemm_tc<<<gProj, 256>>>(patt, Wo + wOff, bo + vOff, px, px,
                                Dn, Dn, 0, 0, 0, 0);

        // FFN
        ln_kernel<<<gLN, 256>>>(px, ln2a + vOff, ln2b + vOff, ph);
        gemm_tc<<<gProj, 256>>>(ph, Wf1 + wOff, bf1 + vOff, nullptr, pt1,
                                Dn, Dn, 0, 0, 0, 1);
        gemm_tc<<<gProj, 256>>>(pt1, Wf2 + wOff, bf2 + vOff, px, px,
                                Dn, Dn, 0, 0, 0, 1);
    }

    ln_kernel<<<gLN, 256>>>(px, lnfa, lnfb, (float*)d_out);
}

// round 7
// speedup vs baseline: 3.7193x; 1.2501x over previous
#include <cuda_runtime.h>
#include <cuda_fp16.h>
#include <math.h>
#include <mma.h>

using namespace nvcuda;

// Problem constants
#define Bn 16
#define Nn 512
#define Dn 256
#define Hn 8
#define Ln 4
#define DKn 32

#define BND (Bn*Nn*Dn)   // 2,097,152
#define BNN (Bn*Nn*Nn)   // 4,194,304
#define WSZ (Ln*Dn*Dn)   // 262,144 per weight set

static __device__ float  g_x[BND];
static __device__ float  g_att[BND];
static __device__ float  g_base[BNN];
static __device__ __half g_hh[BND];
static __device__ __half g_qh[BND];
static __device__ __half g_kh[BND];
static __device__ __half g_vh[BND];
static __device__ __half g_t1[BND];
static __device__ __half g_wh[6 * WSZ];

// ---------------------------------------------------------------------------
// helpers
// ---------------------------------------------------------------------------
__device__ __forceinline__ uint4 pack_h8(float4 a, float4 b) {
    half2 h0 = __floats2half2_rn(a.x, a.y);
    half2 h1 = __floats2half2_rn(a.z, a.w);
    half2 h2 = __floats2half2_rn(b.x, b.y);
    half2 h3 = __floats2half2_rn(b.z, b.w);
    uint4 r;
    r.x = *(unsigned*)&h0; r.y = *(unsigned*)&h1;
    r.z = *(unsigned*)&h2; r.w = *(unsigned*)&h3;
    return r;
}

__device__ __forceinline__ uint4 loadA8(const half* p) {
    return *(const uint4*)p;
}
__device__ __forceinline__ uint4 loadA8(const float* p) {
    return pack_h8(*(const float4*)p, *(const float4*)(p + 4));
}

__device__ __forceinline__ void storeC4h(half* p, float4 v) {
    half2 a = __floats2half2_rn(v.x, v.y);
    half2 b = __floats2half2_rn(v.z, v.w);
    uint2 u; u.x = *(unsigned*)&a; u.y = *(unsigned*)&b;
    *(uint2*)p = u;
}

// ---------------------------------------------------------------------------
// weight conversion fp32 -> fp16 (runs once per call, deterministic)
// ---------------------------------------------------------------------------
__global__ void cvt_w(const float* __restrict__ Wq, const float* __restrict__ Wk,
                      const float* __restrict__ Wv, const float* __restrict__ Wo,
                      const float* __restrict__ Wf1, const float* __restrict__ Wf2,
                      __half* __restrict__ out) {
    const int idx = (blockIdx.x * 256 + threadIdx.x) * 4;
    const int w = idx / WSZ;
    const int r = idx - w * WSZ;
    const float* srcs[6] = {Wq, Wk, Wv, Wo, Wf1, Wf2};
    float4 v = *(const float4*)(srcs[w] + r);
    half2 a = __floats2half2_rn(v.x, v.y);
    half2 b = __floats2half2_rn(v.z, v.w);
    uint2 u; u.x = *(unsigned*)&a; u.y = *(unsigned*)&b;
    *(uint2*)(out + idx) = u;
}

// ---------------------------------------------------------------------------
// block reductions for base_kernel (256 threads)
// ---------------------------------------------------------------------------
__device__ __forceinline__ float blockSum256(float v) {
    __shared__ float sm[8];
    __syncthreads();
    #pragma unroll
    for (int o = 16; o; o >>= 1) v += __shfl_xor_sync(0xffffffffu, v, o);
    if ((threadIdx.x & 31) == 0) sm[threadIdx.x >> 5] = v;
    __syncthreads();
    float t = 0.f;
    #pragma unroll
    for (int i = 0; i < 8; i++) t += sm[i];
    return t;
}

__device__ __forceinline__ float blockMax256(float v) {
    __shared__ float sm[8];
    __syncthreads();
    #pragma unroll
    for (int o = 16; o; o >>= 1) v = fmaxf(v, __shfl_xor_sync(0xffffffffu, v, o));
    if ((threadIdx.x & 31) == 0) sm[threadIdx.x >> 5] = v;
    __syncthreads();
    float t = sm[0];
    #pragma unroll
    for (int i = 1; i < 8; i++) t = fmaxf(t, sm[i]);
    return t;
}

// ---------------------------------------------------------------------------
// base[b,i,j] = 0.3*softmax_j(mask ? -dist : -inf) + 0.4*adj/(sum_adj+eps)
// ---------------------------------------------------------------------------
__global__ void base_kernel(const float* __restrict__ dist,
                            const float* __restrict__ adj,
                            const int*   __restrict__ mask,
                            float* __restrict__ base) {
    const int bi = blockIdx.x;
    const int b  = bi >> 9;
    const float* dr = dist + (size_t)bi * Nn;
    const float* ar = adj  + (size_t)bi * Nn;
    float*       br = base + (size_t)bi * Nn;
    const int t = threadIdx.x;

    const int m0 = mask[b * Nn + t];
    const int m1 = mask[b * Nn + t + 256];
    float v0 = m0 ? -dr[t]       : -INFINITY;
    float v1 = m1 ? -dr[t + 256] : -INFINITY;

    float mx = blockMax256(fmaxf(v0, v1));
    float e0 = __expf(v0 - mx);
    float e1 = __expf(v1 - mx);
    float ssum = blockSum256(e0 + e1);

    float a0 = ar[t], a1 = ar[t + 256];
    float asum = blockSum256(a0 + a1);

    float cs = 0.3f / ssum;
    float ca = 0.4f / (asum + 1e-6f);
    br[t]       = e0 * cs + a0 * ca;
    br[t + 256] = e1 * cs + a1 * ca;
}

// ---------------------------------------------------------------------------
// LayerNorm (ddof=1), warp per row, shfl-only. Two variants: half / float out.
// ---------------------------------------------------------------------------
__device__ __forceinline__ void ln_core(const float* __restrict__ xr,
                                        const float* __restrict__ a,
                                        const float* __restrict__ bb,
                                        int c, float4& o0, float4& o1) {
    float4 v0 = *(const float4*)(xr + c);
    float4 v1 = *(const float4*)(xr + c + 4);
    float s = v0.x+v0.y+v0.z+v0.w + v1.x+v1.y+v1.z+v1.w;
    #pragma unroll
    for (int o = 16; o; o >>= 1) s += __shfl_xor_sync(0xffffffffu, s, o);
    float mean = s * (1.f / Dn);

    float c0[8] = {v0.x-mean, v0.y-mean, v0.z-mean, v0.w-mean,
                   v1.x-mean, v1.y-mean, v1.z-mean, v1.w-mean};
    float sq = 0.f;
    #pragma unroll
    for (int i = 0; i < 8; i++) sq += c0[i]*c0[i];
    #pragma unroll
    for (int o = 16; o; o >>= 1) sq += __shfl_xor_sync(0xffffffffu, sq, o);
    float inv = 1.f / (sqrtf(sq * (1.f / (Dn - 1))) + 1e-6f);

    float4 a0 = *(const float4*)(a + c);
    float4 a1 = *(const float4*)(a + c + 4);
    float4 b0 = *(const float4*)(bb + c);
    float4 b1 = *(const float4*)(bb + c + 4);
    o0.x = a0.x*c0[0]*inv + b0.x;  o0.y = a0.y*c0[1]*inv + b0.y;
    o0.z = a0.z*c0[2]*inv + b0.z;  o0.w = a0.w*c0[3]*inv + b0.w;
    o1.x = a1.x*c0[4]*inv + b1.x;  o1.y = a1.y*c0[5]*inv + b1.y;
    o1.z = a1.z*c0[6]*inv + b1.z;  o1.w = a1.w*c0[7]*inv + b1.w;
}

__global__ void ln_f(const float* __restrict__ x, const float* __restrict__ a,
                     const float* __restrict__ bb, float* __restrict__ out) {
    const int warp = threadIdx.x >> 5;
    const int lane = threadIdx.x & 31;
    const size_t row = (size_t)blockIdx.x * 8 + warp;
    const int c = lane * 8;
    float4 o0, o1;
    ln_core(x + row * Dn, a, bb, c, o0, o1);
    *(float4*)(out + row * Dn + c)     = o0;
    *(float4*)(out + row * Dn + c + 4) = o1;
}

__global__ void ln_h(const float* __restrict__ x, const float* __restrict__ a,
                     const float* __restrict__ bb, __half* __restrict__ out) {
    const int warp = threadIdx.x >> 5;
    const int lane = threadIdx.x & 31;
    const size_t row = (size_t)blockIdx.x * 8 + warp;
    const int c = lane * 8;
    float4 o0, o1;
    ln_core(x + row * Dn, a, bb, c, o0, o1);
    *(uint4*)(out + row * Dn + c) = pack_h8(o0, o1);
}

// ---------------------------------------------------------------------------
// FP16 tensor-core GEMM body: 64x128 block tile, BK=32, 8 warps (2x4),
// warp tile 32x32 (m16n16k16), double-buffered, fp32 accumulate.
// A: half or float (converted on load). W: half. C: half or float (+res).
// ---------------------------------------------------------------------------
#define LDAH 40
#define LDBH 136
#define LDS_ 36
#define SMEM_BYTES 36864

template<typename AT, int CHALF>
__device__ __forceinline__ void gemm_body(
    const AT* __restrict__ A, const half* __restrict__ W,
    const float* __restrict__ bias, const float* __restrict__ res,
    void* __restrict__ Cv, int Nc, int K, int act, char* smemc) {

    half*  hs  = (half*)smemc;
    float* fst = (float*)smemc;

    const int tm = blockIdx.y * 64;
    const int tn = blockIdx.x * 128;
    const int tid = threadIdx.x;
    const int warp = tid >> 5;
    const int lane = tid & 31;
    const int wm = warp >> 2;
    const int wn = warp & 3;

    #define ASH(buf,r,c) hs[(buf)*2560 + (r)*LDAH + (c)]
    #define BSH(buf,r,c) hs[5120 + (buf)*4352 + (r)*LDBH + (c)]

    const int arow = tid >> 2;            // 0..63
    const int acol = (tid & 3) * 8;       // 0,8,16,24 (elements)
    const int brow = tid >> 3;            // 0..31
    const int bcol = (tid & 7) * 16;      // 0..112 (halves)

    const AT*   pA = A + (size_t)(tm + arow) * K + acol;
    const half* pB = W + (size_t)brow * Nc + tn + bcol;

    wmma::fragment<wmma::accumulator, 16, 16, 16, float> acc[2][2];
    #pragma unroll
    for (int mm = 0; mm < 2; mm++)
        #pragma unroll
        for (int nn = 0; nn < 2; nn++)
            wmma::fill_fragment(acc[mm][nn], 0.f);

    uint4 ra  = loadA8(pA);
    uint4 rb0 = *(const uint4*)(pB);
    uint4 rb1 = *(const uint4*)(pB + 8);
    int buf = 0;
    *(uint4*)&ASH(0, arow, acol)     = ra;
    *(uint4*)&BSH(0, brow, bcol)     = rb0;
    *(uint4*)&BSH(0, brow, bcol + 8) = rb1;
    __syncthreads();

    for (int k0 = 32; k0 < K; k0 += 32) {
        ra  = loadA8(pA + k0);
        const half* pBk = pB + (size_t)k0 * Nc;
        rb0 = *(const uint4*)(pBk);
        rb1 = *(const uint4*)(pBk + 8);

        #pragma unroll
        for (int ks = 0; ks < 2; ks++) {
            wmma::fragment<wmma::matrix_a, 16, 16, 16, half, wmma::row_major> af[2];
            wmma::fragment<wmma::matrix_b, 16, 16, 16, half, wmma::row_major> bf[2];
            wmma::load_matrix_sync(af[0], &ASH(buf, wm * 32,      ks * 16), LDAH);
            wmma::load_matrix_sync(af[1], &ASH(buf, wm * 32 + 16, ks * 16), LDAH);
            wmma::load_matrix_sync(bf[0], &BSH(buf, ks * 16, wn * 32),      LDBH);
            wmma::load_matrix_sync(bf[1], &BSH(buf, ks * 16, wn * 32 + 16), LDBH);
            wmma::mma_sync(acc[0][0], af[0], bf[0], acc[0][0]);
            wmma::mma_sync(acc[0][1], af[0], bf[1], acc[0][1]);
            wmma::mma_sync(acc[1][0], af[1], bf[0], acc[1][0]);
            wmma::mma_sync(acc[1][1], af[1], bf[1], acc[1][1]);
        }

        buf ^= 1;
        *(uint4*)&ASH(buf, arow, acol)     = ra;
        *(uint4*)&BSH(buf, brow, bcol)     = rb0;
        *(uint4*)&BSH(buf, brow, bcol + 8) = rb1;
        __syncthreads();
    }

    #pragma unroll
    for (int ks = 0; ks < 2; ks++) {
        wmma::fragment<wmma::matrix_a, 16, 16, 16, half, wmma::row_major> af[2];
        wmma::fragment<wmma::matrix_b, 16, 16, 16, half, wmma::row_major> bf[2];
        wmma::load_matrix_sync(af[0], &ASH(buf, wm * 32,      ks * 16), LDAH);
        wmma::load_matrix_sync(af[1], &ASH(buf, wm * 32 + 16, ks * 16), LDAH);
        wmma::load_matrix_sync(bf[0], &BSH(buf, ks * 16, wn * 32),      LDBH);
        wmma::load_matrix_sync(bf[1], &BSH(buf, ks * 16, wn * 32 + 16), LDBH);
        wmma::mma_sync(acc[0][0], af[0], bf[0], acc[0][0]);
        wmma::mma_sync(acc[0][1], af[0], bf[1], acc[0][1]);
        wmma::mma_sync(acc[1][0], af[1], bf[0], acc[1][0]);
        wmma::mma_sync(acc[1][1], af[1], bf[1], acc[1][1]);
    }
    __syncthreads();

    float* stg = fst + warp * 32 * LDS_;
    #pragma unroll
    for (int mm = 0; mm < 2; mm++)
        #pragma unroll
        for (int nn = 0; nn < 2; nn++)
            wmma::store_matrix_sync(stg + mm * 16 * LDS_ + nn * 16,
                                    acc[mm][nn], LDS_, wmma::mem_row_major);
    __syncwarp();

    const int growb = tm + wm * 32;
    const int gcolb = tn + wn * 32;
    #pragma unroll
    for (int it = 0; it < 8; it++) {
        int idx = it * 32 + lane;
        int rr = idx >> 3;
        int cc = (idx & 7) * 4;
        int col = gcolb + cc;
        float4 v = *(float4*)(stg + rr * LDS_ + cc);
        if (bias) {
            float4 bb4 = *(const float4*)(bias + col);
            v.x += bb4.x; v.y += bb4.y; v.z += bb4.z; v.w += bb4.w;
        }
        if (act) {
            v.x = v.x > 0.f ? v.x : 0.1f * v.x;
            v.y = v.y > 0.f ? v.y : 0.1f * v.y;
            v.z = v.z > 0.f ? v.z : 0.1f * v.z;
            v.w = v.w > 0.f ? v.w : 0.1f * v.w;
        }
        size_t row = (size_t)(growb + rr);
        if (CHALF) {
            storeC4h((half*)Cv + row * Nc + col, v);
        } else {
            float* Cf = (float*)Cv;
            if (res) {
                float4 r4 = *(const float4*)(res + row * Nc + col);
                v.x += r4.x; v.y += r4.y; v.z += r4.z; v.w += r4.w;
            }
            *(float4*)(Cf + row * Nc + col) = v;
        }
    }
    #undef ASH
    #undef BSH
}

// A float, C float (+res). Strided batch via z.
__global__ void __launch_bounds__(256, 2)
gemm_ff(const float* __restrict__ A, const half* __restrict__ W,
        const float* __restrict__ bias, const float* __restrict__ res,
        float* __restrict__ C, int Nc, int K,
        long sA, long sW, long sC, int act) {
    __shared__ __align__(16) char smem[SMEM_BYTES];
    const float* rp = res ? res + (size_t)blockIdx.z * sC : nullptr;
    gemm_body<float, 0>(A + (size_t)blockIdx.z * sA, W + (size_t)blockIdx.z * sW,
                        bias, rp, C + (size_t)blockIdx.z * sC, Nc, K, act, smem);
}

// A half, C float (+res)
__global__ void __launch_bounds__(256, 2)
gemm_hf(const half* __restrict__ A, const half* __restrict__ W,
        const float* __restrict__ bias, const float* __restrict__ res,
        float* __restrict__ C, int Nc, int K, int act) {
    __shared__ __align__(16) char smem[SMEM_BYTES];
    gemm_body<half, 0>(A, W, bias, res, C, Nc, K, act, smem);
}

// A half, C half
__global__ void __launch_bounds__(256, 2)
gemm_hh(const half* __restrict__ A, const half* __restrict__ W,
        const float* __restrict__ bias, half* __restrict__ C,
        int Nc, int K, int act) {
    __shared__ __align__(16) char smem[SMEM_BYTES];
    gemm_body<half, 1>(A, W, bias, nullptr, C, Nc, K, act, smem);
}

// Fused QKV: z selects projection. A half, C half.
__global__ void __launch_bounds__(256, 2)
gemm_qkv(const half* __restrict__ A, const half* __restrict__ Wh,
         long wStride,
         const float* __restrict__ b0, const float* __restrict__ b1,
         const float* __restrict__ b2,
         half* __restrict__ C0, half* __restrict__ C1, half* __restrict__ C2,
         int Nc, int K) {
    __shared__ __align__(16) char smem[SMEM_BYTES];
    const half* W = Wh + (size_t)blockIdx.z * wStride;
    const float* bb = (blockIdx.z == 0) ? b0 : (blockIdx.z == 1) ? b1 : b2;
    half* C = (blockIdx.z == 0) ? C0 : (blockIdx.z == 1) ? C1 : C2;
    gemm_body<half, 1>(A, W, bb, nullptr, C, Nc, K, 0, smem);
}

// ---------------------------------------------------------------------------
// FP16 tensor-core flash attention (no running max: scores bounded).
// att += 0.3 * softmax(mask(qk^T/s)) @ v ; q,k,v are half.
// ---------------------------------------------------------------------------
#define ALQH 40   // halves
#define ALP  68   // floats
#define ALPH 72   // halves

__global__ void __launch_bounds__(128)
attn_tc(const __half* __restrict__ q,
        const __half* __restrict__ k,
        const __half* __restrict__ v,
        const int*    __restrict__ mask,
        float* __restrict__ att) {
    __shared__ __align__(16) half  Qs[64][ALQH];
    __shared__ __align__(16) half  Ks[64][ALQH];
    __shared__ __align__(16) half  Vs[64][ALQH];
    __shared__ __align__(16) float Ps[4][16][ALP];
    __shared__ __align__(16) half  Ph[4][16][ALPH];
    __shared__ int ms[64];

    const int b = blockIdx.z, h = blockIdx.y;
    const int tid = threadIdx.x;
    const int warp = tid >> 5;
    const int lane = tid & 31;
    const int qrow0 = blockIdx.x * 64;
    const float scale = 0.17677669529663687f;   // 1/sqrt(32)

    // load Q tile (64x32 halves): thread: row tid>>1, col (tid&1)*16
    {
        int r = tid >> 1, c = (tid & 1) * 16;
        const __half* src = q + ((size_t)(b * Nn + qrow0 + r)) * Dn + h * DKn + c;
        *(uint4*)&Qs[r][c]     = *(const uint4*)(src);
        *(uint4*)&Qs[r][c + 8] = *(const uint4*)(src + 8);
    }

    wmma::fragment<wmma::accumulator, 16, 16, 16, float> ao[2];
    wmma::fill_fragment(ao[0], 0.f);
    wmma::fill_fragment(ao[1], 0.f);

    float l_tot = 0.f;
    const int myrow = lane >> 1;
    const int colh = (lane & 1) * 32;

    for (int kt = 0; kt < Nn / 64; kt++) {
        __syncthreads();
        {
            int r = tid >> 1, c = (tid & 1) * 16;
            size_t off = ((size_t)(b * Nn + kt * 64 + r)) * Dn + h * DKn + c;
            *(uint4*)&Ks[r][c]     = *(const uint4*)(k + off);
            *(uint4*)&Ks[r][c + 8] = *(const uint4*)(k + off + 8);
            *(uint4*)&Vs[r][c]     = *(const uint4*)(v + off);
            *(uint4*)&Vs[r][c + 8] = *(const uint4*)(v + off + 8);
        }
        if (tid < 64) ms[tid] = mask[b * Nn + kt * 64 + tid];
        __syncthreads();

        // S = Q @ K^T
        wmma::fragment<wmma::accumulator, 16, 16, 16, float> sf[4];
        #pragma unroll
        for (int n = 0; n < 4; n++) wmma::fill_fragment(sf[n], 0.f);
        #pragma unroll
        for (int ks = 0; ks < 2; ks++) {
            wmma::fragment<wmma::matrix_a, 16, 16, 16, half, wmma::row_major> af;
            wmma::load_matrix_sync(af, &Qs[warp * 16][ks * 16], ALQH);
            #pragma unroll
            for (int n = 0; n < 4; n++) {
                wmma::fragment<wmma::matrix_b, 16, 16, 16, half, wmma::col_major> bf;
                wmma::load_matrix_sync(bf, &Ks[n * 16][ks * 16], ALQH);
                wmma::mma_sync(sf[n], af, bf, sf[n]);
            }
        }
        #pragma unroll
        for (int n = 0; n < 4; n++)
            wmma::store_matrix_sync(&Ps[warp][0][n * 16], sf[n], ALP, wmma::mem_row_major);
        __syncwarp();

        // p = mask ? exp(s*scale) : 0 ; row sums; half P
        float lp = 0.f;
        const float* srow = &Ps[warp][myrow][colh];
        half* prow = &Ph[warp][myrow][colh];
        const int* mrow = ms + colh;
        #pragma unroll
        for (int j = 0; j < 32; j += 2) {
            float p0 = mrow[j]     ? __expf(srow[j]     * scale) : 0.f;
            float p1 = mrow[j + 1] ? __expf(srow[j + 1] * scale) : 0.f;
            lp += p0 + p1;
            *(half2*)(prow + j) = __floats2half2_rn(p0, p1);
        }
        lp += __shfl_xor_sync(0xffffffffu, lp, 1);
        l_tot += lp;
        __syncwarp();

        // O += P @ V
        #pragma unroll
        for (int ks = 0; ks < 4; ks++) {
            wmma::fragment<wmma::matrix_a, 16, 16, 16, half, wmma::row_major> af;
            wmma::load_matrix_sync(af, &Ph[warp][0][ks * 16], ALPH);
            #pragma unroll
            for (int n = 0; n < 2; n++) {
                wmma::fragment<wmma::matrix_b, 16, 16, 16, half, wmma::row_major> bf;
                wmma::load_matrix_sync(bf, &Vs[ks * 16][n * 16], ALQH);
                wmma::mma_sync(ao[n], af, bf, ao[n]);
            }
        }
    }

    // epilogue
    float* Os = &Ps[warp][0][0];
    wmma::store_matrix_sync(Os,      ao[0], ALP, wmma::mem_row_major);
    wmma::store_matrix_sync(Os + 16, ao[1], ALP, wmma::mem_row_major);
    __syncwarp();

    const float inv = 0.3f / l_tot;
    const int ch = (lane & 1) * 16;
    float* orow = att + ((size_t)(b * Nn + qrow0 + warp * 16 + myrow)) * Dn + h * DKn + ch;
    float* sro = Os + myrow * ALP + ch;
    #pragma unroll
    for (int c = 0; c < 4; c++) {
        float4 t = *(float4*)(orow + c * 4);
        float4 s4 = *(float4*)(sro + c * 4);
        t.x += s4.x * inv; t.y += s4.y * inv;
        t.z += s4.z * inv; t.w += s4.w * inv;
        *(float4*)(orow + c * 4) = t;
    }
}

// ---------------------------------------------------------------------------
// Launch
// ---------------------------------------------------------------------------
extern "C" void kernel_launch(void* const* d_in, const int* in_sizes, int n_in,
                              void* d_out, int out_size) {
    const float* x_in  = (const float*)d_in[0];
    const int*   mask  = (const int*)  d_in[1];
    const float* adj   = (const float*)d_in[2];
    const float* dist  = (const float*)d_in[3];
    const float* Wq    = (const float*)d_in[5];
    const float* bq    = (const float*)d_in[6];
    const float* Wk    = (const float*)d_in[7];
    const float* bk    = (const float*)d_in[8];
    const float* Wv    = (const float*)d_in[9];
    const float* bv    = (const float*)d_in[10];
    const float* Wo    = (const float*)d_in[11];
    const float* bo    = (const float*)d_in[12];
    const float* Wf1   = (const float*)d_in[13];
    const float* bf1   = (const float*)d_in[14];
    const float* Wf2   = (const float*)d_in[15];
    const float* bf2   = (const float*)d_in[16];
    const float* ln1a  = (const float*)d_in[17];
    const float* ln1b  = (const float*)d_in[18];
    const float* ln2a  = (const float*)d_in[19];
    const float* ln2b  = (const float*)d_in[20];
    const float* lnfa  = (const float*)d_in[21];
    const float* lnfb  = (const float*)d_in[22];

    float *px, *patt, *pbase;
    __half *phh, *pqh, *pkh, *pvh, *pt1, *pwh;
    cudaGetSymbolAddress((void**)&px,    g_x);
    cudaGetSymbolAddress((void**)&patt,  g_att);
    cudaGetSymbolAddress((void**)&pbase, g_base);
    cudaGetSymbolAddress((void**)&phh,   g_hh);
    cudaGetSymbolAddress((void**)&pqh,   g_qh);
    cudaGetSymbolAddress((void**)&pkh,   g_kh);
    cudaGetSymbolAddress((void**)&pvh,   g_vh);
    cudaGetSymbolAddress((void**)&pt1,   g_t1);
    cudaGetSymbolAddress((void**)&pwh,   g_wh);

    cudaMemcpyAsync(px, x_in, sizeof(float) * BND, cudaMemcpyDeviceToDevice, 0);

    cvt_w<<<(6 * WSZ) / 1024, 256>>>(Wq, Wk, Wv, Wo, Wf1, Wf2, pwh);
    base_kernel<<<Bn * Nn, 256>>>(dist, adj, mask, pbase);

    const dim3 gProj(Dn / 128, (Bn * Nn) / 64, 1);    // 256 blocks
    const dim3 gQKV (Dn / 128, (Bn * Nn) / 64, 3);    // 768 blocks
    const dim3 gBaseV(Dn / 128, Nn / 64, Bn);         // 256 blocks
    const dim3 gAttn(Nn / 64, Hn, Bn);                // 1024 blocks
    const dim3 gLN(Bn * Nn / 8, 1, 1);

    for (int i = 0; i < Ln; i++) {
        const size_t wOff = (size_t)i * Dn * Dn;
        const size_t vOff = (size_t)i * Dn;

        ln_h<<<gLN, 256>>>(px, ln1a + vOff, ln1b + vOff, phh);

        gemm_qkv<<<gQKV, 256>>>(phh, pwh + wOff, (long)WSZ,
                                bq + vOff, bk + vOff, bv + vOff,
                                pqh, pkh, pvh, Dn, Dn);

        // att = base @ V  (head-independent part, pre-scaled by lambdas)
        gemm_ff<<<gBaseV, 256>>>(pbase, pvh, nullptr, nullptr, patt,
                                 Dn, Nn,
                                 (long)Nn * Nn, (long)Nn * Dn, (long)Nn * Dn, 0);

        // att += 0.3 * softmax_attn @ V
        attn_tc<<<gAttn, 128>>>(pqh, pkh, pvh, mask, patt);

        // x = x + att @ Wo + bo
        gemm_ff<<<gProj, 256>>>(patt, pwh + 3 * WSZ + wOff, bo + vOff, px, px,
                                Dn, Dn, 0, 0, 0, 0);

        // FFN
        ln_h<<<gLN, 256>>>(px, ln2a + vOff, ln2b + vOff, phh);
        gemm_hh<<<gProj, 256>>>(phh, pwh + 4 * WSZ + wOff, bf1 + vOff, pt1,
                                Dn, Dn, 1);
        gemm_hf<<<gProj, 256>>>(pt1, pwh + 5 * WSZ + wOff, bf2 + vOff, px, px,
                                Dn, Dn, 1);
    }

    ln_f<<<gLN, 256>>>(px, lnfa, lnfb, (float*)d_out);
}

// round 9
// speedup vs baseline: 3.7414x; 1.0059x over previous
#include <cuda_runtime.h>
#include <cuda_fp16.h>
#include <math.h>
#include <mma.h>

using namespace nvcuda;

// Problem constants
#define Bn 16
#define Nn 512
#define Dn 256
#define Hn 8
#define Ln 4
#define DKn 32

#define BND (Bn*Nn*Dn)   // 2,097,152
#define BNN (Bn*Nn*Nn)   // 4,194,304
#define WSZ (Ln*Dn*Dn)   // 262,144 per weight set

static __device__ float  g_x[BND];
static __device__ float  g_att[BND];
static __device__ __half g_baseh[BNN];
static __device__ __half g_hh[BND];
static __device__ __half g_qh[BND];
static __device__ __half g_kh[BND];
static __device__ __half g_vh[BND];
static __device__ __half g_t1[BND];
static __device__ __half g_wh[6 * WSZ];

// ---------------------------------------------------------------------------
// helpers
// ---------------------------------------------------------------------------
__device__ __forceinline__ uint4 pack_h8(float4 a, float4 b) {
    half2 h0 = __floats2half2_rn(a.x, a.y);
    half2 h1 = __floats2half2_rn(a.z, a.w);
    half2 h2 = __floats2half2_rn(b.x, b.y);
    half2 h3 = __floats2half2_rn(b.z, b.w);
    uint4 r;
    r.x = *(unsigned*)&h0; r.y = *(unsigned*)&h1;
    r.z = *(unsigned*)&h2; r.w = *(unsigned*)&h3;
    return r;
}

__device__ __forceinline__ uint4 loadA8(const half* p) { return *(const uint4*)p; }
__device__ __forceinline__ uint4 loadA8(const float* p) {
    return pack_h8(*(const float4*)p, *(const float4*)(p + 4));
}

__device__ __forceinline__ void storeC4h(half* p, float4 v) {
    half2 a = __floats2half2_rn(v.x, v.y);
    half2 b = __floats2half2_rn(v.z, v.w);
    uint2 u; u.x = *(unsigned*)&a; u.y = *(unsigned*)&b;
    *(uint2*)p = u;
}

// ---------------------------------------------------------------------------
// weight conversion fp32 -> fp16 (once per call, deterministic)
// ---------------------------------------------------------------------------
__global__ void cvt_w(const float* __restrict__ Wq, const float* __restrict__ Wk,
                      const float* __restrict__ Wv, const float* __restrict__ Wo,
                      const float* __restrict__ Wf1, const float* __restrict__ Wf2,
                      __half* __restrict__ out) {
    const int idx = (blockIdx.x * 256 + threadIdx.x) * 4;
    const int w = idx / WSZ;
    const int r = idx - w * WSZ;
    const float* srcs[6] = {Wq, Wk, Wv, Wo, Wf1, Wf2};
    float4 v = *(const float4*)(srcs[w] + r);
    half2 a = __floats2half2_rn(v.x, v.y);
    half2 b = __floats2half2_rn(v.z, v.w);
    uint2 u; u.x = *(unsigned*)&a; u.y = *(unsigned*)&b;
    *(uint2*)(out + idx) = u;
}

// ---------------------------------------------------------------------------
// block reductions for base_kernel (256 threads)
// ---------------------------------------------------------------------------
__device__ __forceinline__ float blockSum256(float v) {
    __shared__ float sm[8];
    __syncthreads();
    #pragma unroll
    for (int o = 16; o; o >>= 1) v += __shfl_xor_sync(0xffffffffu, v, o);
    if ((threadIdx.x & 31) == 0) sm[threadIdx.x >> 5] = v;
    __syncthreads();
    float t = 0.f;
    #pragma unroll
    for (int i = 0; i < 8; i++) t += sm[i];
    return t;
}

__device__ __forceinline__ float blockMax256(float v) {
    __shared__ float sm[8];
    __syncthreads();
    #pragma unroll
    for (int o = 16; o; o >>= 1) v = fmaxf(v, __shfl_xor_sync(0xffffffffu, v, o));
    if ((threadIdx.x & 31) == 0) sm[threadIdx.x >> 5] = v;
    __syncthreads();
    float t = sm[0];
    #pragma unroll
    for (int i = 1; i < 8; i++) t = fmaxf(t, sm[i]);
    return t;
}

// ---------------------------------------------------------------------------
// base[b,i,j] = 0.3*softmax_j(mask ? -dist : -inf) + 0.4*adj/(sum_adj+eps)
// output HALF (layer-invariant, consumed only as GEMM A-operand)
// ---------------------------------------------------------------------------
__global__ void base_kernel(const float* __restrict__ dist,
                            const float* __restrict__ adj,
                            const int*   __restrict__ mask,
                            __half* __restrict__ base) {
    const int bi = blockIdx.x;
    const int b  = bi >> 9;
    const float* dr = dist + (size_t)bi * Nn;
    const float* ar = adj  + (size_t)bi * Nn;
    __half*      br = base + (size_t)bi * Nn;
    const int t = threadIdx.x;

    const int m0 = mask[b * Nn + t];
    const int m1 = mask[b * Nn + t + 256];
    float v0 = m0 ? -dr[t]       : -INFINITY;
    float v1 = m1 ? -dr[t + 256] : -INFINITY;

    float mx = blockMax256(fmaxf(v0, v1));
    float e0 = __expf(v0 - mx);
    float e1 = __expf(v1 - mx);
    float ssum = blockSum256(e0 + e1);

    float a0 = ar[t], a1 = ar[t + 256];
    float asum = blockSum256(a0 + a1);

    float cs = 0.3f / ssum;
    float ca = 0.4f / (asum + 1e-6f);
    br[t]       = __float2half_rn(e0 * cs + a0 * ca);
    br[t + 256] = __float2half_rn(e1 * cs + a1 * ca);
}

// ---------------------------------------------------------------------------
// LayerNorm (ddof=1), warp per row
// ---------------------------------------------------------------------------
__device__ __forceinline__ void ln_core(const float* __restrict__ xr,
                                        const float* __restrict__ a,
                                        const float* __restrict__ bb,
                                        int c, float4& o0, float4& o1) {
    float4 v0 = *(const float4*)(xr + c);
    float4 v1 = *(const float4*)(xr + c + 4);
    float s = v0.x+v0.y+v0.z+v0.w + v1.x+v1.y+v1.z+v1.w;
    #pragma unroll
    for (int o = 16; o; o >>= 1) s += __shfl_xor_sync(0xffffffffu, s, o);
    float mean = s * (1.f / Dn);

    float c0[8] = {v0.x-mean, v0.y-mean, v0.z-mean, v0.w-mean,
                   v1.x-mean, v1.y-mean, v1.z-mean, v1.w-mean};
    float sq = 0.f;
    #pragma unroll
    for (int i = 0; i < 8; i++) sq += c0[i]*c0[i];
    #pragma unroll
    for (int o = 16; o; o >>= 1) sq += __shfl_xor_sync(0xffffffffu, sq, o);
    float inv = 1.f / (sqrtf(sq * (1.f / (Dn - 1))) + 1e-6f);

    float4 a0 = *(const float4*)(a + c);
    float4 a1 = *(const float4*)(a + c + 4);
    float4 b0 = *(const float4*)(bb + c);
    float4 b1 = *(const float4*)(bb + c + 4);
    o0.x = a0.x*c0[0]*inv + b0.x;  o0.y = a0.y*c0[1]*inv + b0.y;
    o0.z = a0.z*c0[2]*inv + b0.z;  o0.w = a0.w*c0[3]*inv + b0.w;
    o1.x = a1.x*c0[4]*inv + b1.x;  o1.y = a1.y*c0[5]*inv + b1.y;
    o1.z = a1.z*c0[6]*inv + b1.z;  o1.w = a1.w*c0[7]*inv + b1.w;
}

__global__ void ln_f(const float* __restrict__ x, const float* __restrict__ a,
                     const float* __restrict__ bb, float* __restrict__ out) {
    const size_t row = (size_t)blockIdx.x * 8 + (threadIdx.x >> 5);
    const int c = (threadIdx.x & 31) * 8;
    float4 o0, o1;
    ln_core(x + row * Dn, a, bb, c, o0, o1);
    *(float4*)(out + row * Dn + c)     = o0;
    *(float4*)(out + row * Dn + c + 4) = o1;
}

__global__ void ln_h(const float* __restrict__ x, const float* __restrict__ a,
                     const float* __restrict__ bb, __half* __restrict__ out) {
    const size_t row = (size_t)blockIdx.x * 8 + (threadIdx.x >> 5);
    const int c = (threadIdx.x & 31) * 8;
    float4 o0, o1;
    ln_core(x + row * Dn, a, bb, c, o0, o1);
    *(uint4*)(out + row * Dn + c) = pack_h8(o0, o1);
}

// ---------------------------------------------------------------------------
// FP16 tensor-core GEMM body: 64x128 block tile, BK=32, 8 warps (2x4),
// warp tile 32x32 (m16n16k16), double-buffered, fp32 accumulate.
// ---------------------------------------------------------------------------
#define LDAH 40
#define LDBH 136
#define LDS_ 36
#define SMEM_BYTES 36864

template<typename AT, int CHALF>
__device__ __forceinline__ void gemm_body(
    const AT* __restrict__ A, const half* __restrict__ W,
    const float* __restrict__ bias, const float* __restrict__ res,
    void* __restrict__ Cv, int Nc, int K, int act, char* smemc) {

    half*  hs  = (half*)smemc;
    float* fst = (float*)smemc;

    const int tm = blockIdx.y * 64;
    const int tn = blockIdx.x * 128;
    const int tid = threadIdx.x;
    const int warp = tid >> 5;
    const int lane = tid & 31;
    const int wm = warp >> 2;
    const int wn = warp & 3;

    #define ASH(buf,r,c) hs[(buf)*2560 + (r)*LDAH + (c)]
    #define BSH(buf,r,c) hs[5120 + (buf)*4352 + (r)*LDBH + (c)]

    const int arow = tid >> 2;
    const int acol = (tid & 3) * 8;
    const int brow = tid >> 3;
    const int bcol = (tid & 7) * 16;

    const AT*   pA = A + (size_t)(tm + arow) * K + acol;
    const half* pB = W + (size_t)brow * Nc + tn + bcol;

    wmma::fragment<wmma::accumulator, 16, 16, 16, float> acc[2][2];
    #pragma unroll
    for (int mm = 0; mm < 2; mm++)
        #pragma unroll
        for (int nn = 0; nn < 2; nn++)
            wmma::fill_fragment(acc[mm][nn], 0.f);

    uint4 ra  = loadA8(pA);
    uint4 rb0 = *(const uint4*)(pB);
    uint4 rb1 = *(const uint4*)(pB + 8);
    int buf = 0;
    *(uint4*)&ASH(0, arow, acol)     = ra;
    *(uint4*)&BSH(0, brow, bcol)     = rb0;
    *(uint4*)&BSH(0, brow, bcol + 8) = rb1;
    __syncthreads();

    for (int k0 = 32; k0 < K; k0 += 32) {
        ra  = loadA8(pA + k0);
        const half* pBk = pB + (size_t)k0 * Nc;
        rb0 = *(const uint4*)(pBk);
        rb1 = *(const uint4*)(pBk + 8);

        #pragma unroll
        for (int ks = 0; ks < 2; ks++) {
            wmma::fragment<wmma::matrix_a, 16, 16, 16, half, wmma::row_major> af[2];
            wmma::fragment<wmma::matrix_b, 16, 16, 16, half, wmma::row_major> bf[2];
            wmma::load_matrix_sync(af[0], &ASH(buf, wm * 32,      ks * 16), LDAH);
            wmma::load_matrix_sync(af[1], &ASH(buf, wm * 32 + 16, ks * 16), LDAH);
            wmma::load_matrix_sync(bf[0], &BSH(buf, ks * 16, wn * 32),      LDBH);
            wmma::load_matrix_sync(bf[1], &BSH(buf, ks * 16, wn * 32 + 16), LDBH);
            wmma::mma_sync(acc[0][0], af[0], bf[0], acc[0][0]);
            wmma::mma_sync(acc[0][1], af[0], bf[1], acc[0][1]);
            wmma::mma_sync(acc[1][0], af[1], bf[0], acc[1][0]);
            wmma::mma_sync(acc[1][1], af[1], bf[1], acc[1][1]);
        }

        buf ^= 1;
        *(uint4*)&ASH(buf, arow, acol)     = ra;
        *(uint4*)&BSH(buf, brow, bcol)     = rb0;
        *(uint4*)&BSH(buf, brow, bcol + 8) = rb1;
        __syncthreads();
    }

    #pragma unroll
    for (int ks = 0; ks < 2; ks++) {
        wmma::fragment<wmma::matrix_a, 16, 16, 16, half, wmma::row_major> af[2];
        wmma::fragment<wmma::matrix_b, 16, 16, 16, half, wmma::row_major> bf[2];
        wmma::load_matrix_sync(af[0], &ASH(buf, wm * 32,      ks * 16), LDAH);
        wmma::load_matrix_sync(af[1], &ASH(buf, wm * 32 + 16, ks * 16), LDAH);
        wmma::load_matrix_sync(bf[0], &BSH(buf, ks * 16, wn * 32),      LDBH);
        wmma::load_matrix_sync(bf[1], &BSH(buf, ks * 16, wn * 32 + 16), LDBH);
        wmma::mma_sync(acc[0][0], af[0], bf[0], acc[0][0]);
        wmma::mma_sync(acc[0][1], af[0], bf[1], acc[0][1]);
        wmma::mma_sync(acc[1][0], af[1], bf[0], acc[1][0]);
        wmma::mma_sync(acc[1][1], af[1], bf[1], acc[1][1]);
    }
    __syncthreads();

    float* stg = fst + warp * 32 * LDS_;
    #pragma unroll
    for (int mm = 0; mm < 2; mm++)
        #pragma unroll
        for (int nn = 0; nn < 2; nn++)
            wmma::store_matrix_sync(stg + mm * 16 * LDS_ + nn * 16,
                                    acc[mm][nn], LDS_, wmma::mem_row_major);
    __syncwarp();

    const int growb = tm + wm * 32;
    const int gcolb = tn + wn * 32;
    #pragma unroll
    for (int it = 0; it < 8; it++) {
        int idx = it * 32 + lane;
        int rr = idx >> 3;
        int cc = (idx & 7) * 4;
        int col = gcolb + cc;
        float4 v = *(float4*)(stg + rr * LDS_ + cc);
        if (bias) {
            float4 bb4 = *(const float4*)(bias + col);
            v.x += bb4.x; v.y += bb4.y; v.z += bb4.z; v.w += bb4.w;
        }
        if (act) {
            v.x = v.x > 0.f ? v.x : 0.1f * v.x;
            v.y = v.y > 0.f ? v.y : 0.1f * v.y;
            v.z = v.z > 0.f ? v.z : 0.1f * v.z;
            v.w = v.w > 0.f ? v.w : 0.1f * v.w;
        }
        size_t row = (size_t)(growb + rr);
        if (CHALF) {
            storeC4h((half*)Cv + row * Nc + col, v);
        } else {
            float* Cf = (float*)Cv;
            if (res) {
                float4 r4 = *(const float4*)(res + row * Nc + col);
                v.x += r4.x; v.y += r4.y; v.z += r4.z; v.w += r4.w;
            }
            *(float4*)(Cf + row * Nc + col) = v;
        }
    }
    #undef ASH
    #undef BSH
}

// A float, C float (+res)
__global__ void __launch_bounds__(256, 2)
gemm_ff(const float* __restrict__ A, const half* __restrict__ W,
        const float* __restrict__ bias, const float* __restrict__ res,
        float* __restrict__ C, int Nc, int K, int act) {
    __shared__ __align__(16) char smem[SMEM_BYTES];
    gemm_body<float, 0>(A, W, bias, res, C, Nc, K, act, smem);
}

// A half, C float (+res)
__global__ void __launch_bounds__(256, 2)
gemm_hf(const half* __restrict__ A, const half* __restrict__ W,
        const float* __restrict__ bias, const float* __restrict__ res,
        float* __restrict__ C, int Nc, int K, int act) {
    __shared__ __align__(16) char smem[SMEM_BYTES];
    gemm_body<half, 0>(A, W, bias, res, C, Nc, K, act, smem);
}

// A half, C half
__global__ void __launch_bounds__(256, 2)
gemm_hh(const half* __restrict__ A, const half* __restrict__ W,
        const float* __restrict__ bias, half* __restrict__ C,
        int Nc, int K, int act) {
    __shared__ __align__(16) char smem[SMEM_BYTES];
    gemm_body<half, 1>(A, W, bias, nullptr, C, Nc, K, act, smem);
}

// A half z-strided, W half z-strided, C float z-strided (baseV)
__global__ void __launch_bounds__(256, 2)
gemm_hfz(const half* __restrict__ A, const half* __restrict__ W,
         float* __restrict__ C, int Nc, int K,
         long sA, long sW, long sC) {
    __shared__ __align__(16) char smem[SMEM_BYTES];
    gemm_body<half, 0>(A + (size_t)blockIdx.z * sA, W + (size_t)blockIdx.z * sW,
                       nullptr, nullptr, C + (size_t)blockIdx.z * sC, Nc, K, 0, smem);
}

// Fused QKV: z selects projection. A half, C half.
__global__ void __launch_bounds__(256, 2)
gemm_qkv(const half* __restrict__ A, const half* __restrict__ Wh,
         long wStride,
         const float* __restrict__ b0, const float* __restrict__ b1,
         const float* __restrict__ b2,
         half* __restrict__ C0, half* __restrict__ C1, half* __restrict__ C2,
         int Nc, int K) {
    __shared__ __align__(16) char smem[SMEM_BYTES];
    const half* W = Wh + (size_t)blockIdx.z * wStride;
    const float* bb = (blockIdx.z == 0) ? b0 : (blockIdx.z == 1) ? b1 : b2;
    half* C = (blockIdx.z == 0) ? C0 : (blockIdx.z == 1) ? C1 : C2;
    gemm_body<half, 1>(A, W, bb, nullptr, C, Nc, K, 0, smem);
}

// ---------------------------------------------------------------------------
// FP16 tensor-core flash attention (no running max: scores bounded).
// att += 0.3 * softmax(mask(qk^T/s)) @ v ; q,k,v half; att float.
// ---------------------------------------------------------------------------
#define ALQH 40
#define ALP  68
#define ALPH 72

__global__ void __launch_bounds__(128)
attn_tc(const __half* __restrict__ q,
        const __half* __restrict__ k,
        const __half* __restrict__ v,
        const int*    __restrict__ mask,
        float* __restrict__ att) {
    __shared__ __align__(16) half  Qs[64][ALQH];
    __shared__ __align__(16) half  Ks[64][ALQH];
    __shared__ __align__(16) half  Vs[64][ALQH];
    __shared__ __align__(16) float Ps[4][16][ALP];
    __shared__ __align__(16) half  Ph[4][16][ALPH];
    __shared__ int ms[64];

    const int b = blockIdx.z, h = blockIdx.y;
    const int tid = threadIdx.x;
    const int warp = tid >> 5;
    const int lane = tid & 31;
    const int qrow0 = blockIdx.x * 64;
    const float scale = 0.17677669529663687f;

    {
        int r = tid >> 1, c = (tid & 1) * 16;
        const __half* src = q + ((size_t)(b * Nn + qrow0 + r)) * Dn + h * DKn + c;
        *(uint4*)&Qs[r][c]     = *(const uint4*)(src);
        *(uint4*)&Qs[r][c + 8] = *(const uint4*)(src + 8);
    }

    wmma::fragment<wmma::accumulator, 16, 16, 16, float> ao[2];
    wmma::fill_fragment(ao[0], 0.f);
    wmma::fill_fragment(ao[1], 0.f);

    float l_tot = 0.f;
    const int myrow = lane >> 1;
    const int colh = (lane & 1) * 32;

    for (int kt = 0; kt < Nn / 64; kt++) {
        __syncthreads();
        {
            int r = tid >> 1, c = (tid & 1) * 16;
            size_t off = ((size_t)(b * Nn + kt * 64 + r)) * Dn + h * DKn + c;
            *(uint4*)&Ks[r][c]     = *(const uint4*)(k + off);
            *(uint4*)&Ks[r][c + 8] = *(const uint4*)(k + off + 8);
            *(uint4*)&Vs[r][c]     = *(const uint4*)(v + off);
            *(uint4*)&Vs[r][c + 8] = *(const uint4*)(v + off + 8);
        }
        if (tid < 64) ms[tid] = mask[b * Nn + kt * 64 + tid];
        __syncthreads();

        wmma::fragment<wmma::accumulator, 16, 16, 16, float> sf[4];
        #pragma unroll
        for (int n = 0; n < 4; n++) wmma::fill_fragment(sf[n], 0.f);
        #pragma unroll
        for (int ks = 0; ks < 2; ks++) {
            wmma::fragment<wmma::matrix_a, 16, 16, 16, half, wmma::row_major> af;
            wmma::load_matrix_sync(af, &Qs[warp * 16][ks * 16], ALQH);
            #pragma unroll
            for (int n = 0; n < 4; n++) {
                wmma::fragment<wmma::matrix_b, 16, 16, 16, half, wmma::col_major> bf;
                wmma::load_matrix_sync(bf, &Ks[n * 16][ks * 16], ALQH);
                wmma::mma_sync(sf[n], af, bf, sf[n]);
            }
        }
        #pragma unroll
        for (int n = 0; n < 4; n++)
            wmma::store_matrix_sync(&Ps[warp][0][n * 16], sf[n], ALP, wmma::mem_row_major);
        __syncwarp();

        float lp = 0.f;
        const float* srow = &Ps[warp][myrow][colh];
        half* prow = &Ph[warp][myrow][colh];
        const int* mrow = ms + colh;
        #pragma unroll
        for (int j = 0; j < 32; j += 2) {
            float p0 = mrow[j]     ? __expf(srow[j]     * scale) : 0.f;
            float p1 = mrow[j + 1] ? __expf(srow[j + 1] * scale) : 0.f;
            lp += p0 + p1;
            *(half2*)(prow + j) = __floats2half2_rn(p0, p1);
        }
        lp += __shfl_xor_sync(0xffffffffu, lp, 1);
        l_tot += lp;
        __syncwarp();

        #pragma unroll
        for (int ks = 0; ks < 4; ks++) {
            wmma::fragment<wmma::matrix_a, 16, 16, 16, half, wmma::row_major> af;
            wmma::load_matrix_sync(af, &Ph[warp][0][ks * 16], ALPH);
            #pragma unroll
            for (int n = 0; n < 2; n++) {
                wmma::fragment<wmma::matrix_b, 16, 16, 16, half, wmma::row_major> bf;
                wmma::load_matrix_sync(bf, &Vs[ks * 16][n * 16], ALQH);
                wmma::mma_sync(ao[n], af, bf, ao[n]);
            }
        }
    }

    float* Os = &Ps[warp][0][0];
    wmma::store_matrix_sync(Os,      ao[0], ALP, wmma::mem_row_major);
    wmma::store_matrix_sync(Os + 16, ao[1], ALP, wmma::mem_row_major);
    __syncwarp();

    const float inv = 0.3f / l_tot;
    const int ch = (lane & 1) * 16;
    float* orow = att + ((size_t)(b * Nn + qrow0 + warp * 16 + myrow)) * Dn + h * DKn + ch;
    float* sro = Os + myrow * ALP + ch;
    #pragma unroll
    for (int c = 0; c < 4; c++) {
        float4 t = *(float4*)(orow + c * 4);
        float4 s4 = *(float4*)(sro + c * 4);
        t.x += s4.x * inv; t.y += s4.y * inv;
        t.z += s4.z * inv; t.w += s4.w * inv;
        *(float4*)(orow + c * 4) = t;
    }
}

// ---------------------------------------------------------------------------
// Launch
// ---------------------------------------------------------------------------
extern "C" void kernel_launch(void* const* d_in, const int* in_sizes, int n_in,
                              void* d_out, int out_size) {
    const float* x_in  = (const float*)d_in[0];
    const int*   mask  = (const int*)  d_in[1];
    const float* adj   = (const float*)d_in[2];
    const float* dist  = (const float*)d_in[3];
    const float* Wq    = (const float*)d_in[5];
    const float* bq    = (const float*)d_in[6];
    const float* Wk    = (const float*)d_in[7];
    const float* bk    = (const float*)d_in[8];
    const float* Wv    = (const float*)d_in[9];
    const float* bv    = (const float*)d_in[10];
    const float* Wo    = (const float*)d_in[11];
    const float* bo    = (const float*)d_in[12];
    const float* Wf1   = (const float*)d_in[13];
    const float* bf1   = (const float*)d_in[14];
    const float* Wf2   = (const float*)d_in[15];
    const float* bf2   = (const float*)d_in[16];
    const float* ln1a  = (const float*)d_in[17];
    const float* ln1b  = (const float*)d_in[18];
    const float* ln2a  = (const float*)d_in[19];
    const float* ln2b  = (const float*)d_in[20];
    const float* lnfa  = (const float*)d_in[21];
    const float* lnfb  = (const float*)d_in[22];

    float *px, *patt;
    __half *pbaseh, *phh, *pqh, *pkh, *pvh, *pt1, *pwh;
    cudaGetSymbolAddress((void**)&px,     g_x);
    cudaGetSymbolAddress((void**)&patt,   g_att);
    cudaGetSymbolAddress((void**)&pbaseh, g_baseh);
    cudaGetSymbolAddress((void**)&phh,    g_hh);
    cudaGetSymbolAddress((void**)&pqh,    g_qh);
    cudaGetSymbolAddress((void**)&pkh,    g_kh);
    cudaGetSymbolAddress((void**)&pvh,    g_vh);
    cudaGetSymbolAddress((void**)&pt1,    g_t1);
    cudaGetSymbolAddress((void**)&pwh,    g_wh);

    cudaMemcpyAsync(px, x_in, sizeof(float) * BND, cudaMemcpyDeviceToDevice, 0);

    cvt_w<<<(6 * WSZ) / 1024, 256>>>(Wq, Wk, Wv, Wo, Wf1, Wf2, pwh);
    base_kernel<<<Bn * Nn, 256>>>(dist, adj, mask, pbaseh);

    const dim3 gProj(Dn / 128, (Bn * Nn) / 64, 1);    // 256 blocks
    const dim3 gQKV (Dn / 128, (Bn * Nn) / 64, 3);    // 768 blocks
    const dim3 gBaseV(Dn / 128, Nn / 64, Bn);         // 256 blocks
    const dim3 gAttn(Nn / 64, Hn, Bn);                // 1024 blocks
    const dim3 gLN(Bn * Nn / 8, 1, 1);

    for (int i = 0; i < Ln; i++) {
        const size_t wOff = (size_t)i * Dn * Dn;
        const size_t vOff = (size_t)i * Dn;

        ln_h<<<gLN, 256>>>(px, ln1a + vOff, ln1b + vOff, phh);

        gemm_qkv<<<gQKV, 256>>>(phh, pwh + wOff, (long)WSZ,
                                bq + vOff, bk + vOff, bv + vOff,
                                pqh, pkh, pvh, Dn, Dn);

        // att = base @ V  (half base now, K=512)
        gemm_hfz<<<gBaseV, 256>>>(pbaseh, pvh, patt, Dn, Nn,
                                  (long)Nn * Nn, (long)Nn * Dn, (long)Nn * Dn);

        // att += 0.3 * softmax @ V
        attn_tc<<<gAttn, 128>>>(pqh, pkh, pvh, mask, patt);

        // x = x + att @ Wo + bo
        gemm_ff<<<gProj, 256>>>(patt, pwh + 3 * WSZ + wOff, bo + vOff, px, px,
                                Dn, Dn, 0);

        // FFN
        ln_h<<<gLN, 256>>>(px, ln2a + vOff, ln2b + vOff, phh);
        gemm_hh<<<gProj, 256>>>(phh, pwh + 4 * WSZ + wOff, bf1 + vOff, pt1,
                                Dn, Dn, 1);
        gemm_hf<<<gProj, 256>>>(pt1, pwh + 5 * WSZ + wOff, bf2 + vOff, px, px,
                                Dn, Dn, 1);
    }

    ln_f<<<gLN, 256>>>(px, lnfa, lnfb, (float*)d_out);
}

// round 11
// speedup vs baseline: 4.0456x; 1.0813x over previous
#include <cuda_runtime.h>
#include <cuda_fp16.h>
#include <math.h>
#include <mma.h>
#include <stdint.h>

using namespace nvcuda;

// Problem constants
#define Bn 16
#define Nn 512
#define Dn 256
#define Hn 8
#define Ln 4
#define DKn 32

#define BND (Bn*Nn*Dn)   // 2,097,152
#define BNN (Bn*Nn*Nn)   // 4,194,304
#define WSZ (Ln*Dn*Dn)   // 262,144 per weight set

static __device__ float  g_x[BND];
static __device__ float  g_att[BND];
static __device__ __half g_baseh[BNN];
static __device__ __half g_hh[BND];
static __device__ __half g_qh[BND];
static __device__ __half g_kh[BND];
static __device__ __half g_vh[BND];
static __device__ __half g_t1[BND];
static __device__ __half g_wh[6 * WSZ];

// ---------------------------------------------------------------------------
// helpers
// ---------------------------------------------------------------------------
__device__ __forceinline__ uint4 pack_h8(float4 a, float4 b) {
    half2 h0 = __floats2half2_rn(a.x, a.y);
    half2 h1 = __floats2half2_rn(a.z, a.w);
    half2 h2 = __floats2half2_rn(b.x, b.y);
    half2 h3 = __floats2half2_rn(b.z, b.w);
    uint4 r;
    r.x = *(unsigned*)&h0; r.y = *(unsigned*)&h1;
    r.z = *(unsigned*)&h2; r.w = *(unsigned*)&h3;
    return r;
}

__device__ __forceinline__ uint4 loadA8(const half* p) { return *(const uint4*)p; }
__device__ __forceinline__ uint4 loadA8(const float* p) {
    return pack_h8(*(const float4*)p, *(const float4*)(p + 4));
}

__device__ __forceinline__ void storeC4h(half* p, float4 v) {
    half2 a = __floats2half2_rn(v.x, v.y);
    half2 b = __floats2half2_rn(v.z, v.w);
    uint2 u; u.x = *(unsigned*)&a; u.y = *(unsigned*)&b;
    *(uint2*)p = u;
}

// cp.async primitives
__device__ __forceinline__ void cp16(uint32_t s, const void* g) {
    asm volatile("cp.async.cg.shared.global [%0], [%1], 16;" :: "r"(s), "l"(g));
}
__device__ __forceinline__ void cp_commit() {
    asm volatile("cp.async.commit_group;" ::: "memory");
}
__device__ __forceinline__ void cp_wait1() {
    asm volatile("cp.async.wait_group 1;" ::: "memory");
}
__device__ __forceinline__ void cp_wait0() {
    asm volatile("cp.async.wait_group 0;" ::: "memory");
}

// ---------------------------------------------------------------------------
// weight conversion fp32 -> fp16 (once per call, deterministic)
// ---------------------------------------------------------------------------
__global__ void cvt_w(const float* __restrict__ Wq, const float* __restrict__ Wk,
                      const float* __restrict__ Wv, const float* __restrict__ Wo,
                      const float* __restrict__ Wf1, const float* __restrict__ Wf2,
                      __half* __restrict__ out) {
    const int idx = (blockIdx.x * 256 + threadIdx.x) * 4;
    const int w = idx / WSZ;
    const int r = idx - w * WSZ;
    const float* srcs[6] = {Wq, Wk, Wv, Wo, Wf1, Wf2};
    float4 v = *(const float4*)(srcs[w] + r);
    half2 a = __floats2half2_rn(v.x, v.y);
    half2 b = __floats2half2_rn(v.z, v.w);
    uint2 u; u.x = *(unsigned*)&a; u.y = *(unsigned*)&b;
    *(uint2*)(out + idx) = u;
}

// ---------------------------------------------------------------------------
// block reductions (256 threads)
// ---------------------------------------------------------------------------
__device__ __forceinline__ float blockSum256(float v) {
    __shared__ float sm[8];
    __syncthreads();
    #pragma unroll
    for (int o = 16; o; o >>= 1) v += __shfl_xor_sync(0xffffffffu, v, o);
    if ((threadIdx.x & 31) == 0) sm[threadIdx.x >> 5] = v;
    __syncthreads();
    float t = 0.f;
    #pragma unroll
    for (int i = 0; i < 8; i++) t += sm[i];
    return t;
}

__device__ __forceinline__ float blockMax256(float v) {
    __shared__ float sm[8];
    __syncthreads();
    #pragma unroll
    for (int o = 16; o; o >>= 1) v = fmaxf(v, __shfl_xor_sync(0xffffffffu, v, o));
    if ((threadIdx.x & 31) == 0) sm[threadIdx.x >> 5] = v;
    __syncthreads();
    float t = sm[0];
    #pragma unroll
    for (int i = 1; i < 8; i++) t = fmaxf(t, sm[i]);
    return t;
}

// ---------------------------------------------------------------------------
// base (half output)
// ---------------------------------------------------------------------------
__global__ void base_kernel(const float* __restrict__ dist,
                            const float* __restrict__ adj,
                            const int*   __restrict__ mask,
                            __half* __restrict__ base) {
    const int bi = blockIdx.x;
    const int b  = bi >> 9;
    const float* dr = dist + (size_t)bi * Nn;
    const float* ar = adj  + (size_t)bi * Nn;
    __half*      br = base + (size_t)bi * Nn;
    const int t = threadIdx.x;

    const int m0 = mask[b * Nn + t];
    const int m1 = mask[b * Nn + t + 256];
    float v0 = m0 ? -dr[t]       : -INFINITY;
    float v1 = m1 ? -dr[t + 256] : -INFINITY;

    float mx = blockMax256(fmaxf(v0, v1));
    float e0 = __expf(v0 - mx);
    float e1 = __expf(v1 - mx);
    float ssum = blockSum256(e0 + e1);

    float a0 = ar[t], a1 = ar[t + 256];
    float asum = blockSum256(a0 + a1);

    float cs = 0.3f / ssum;
    float ca = 0.4f / (asum + 1e-6f);
    br[t]       = __float2half_rn(e0 * cs + a0 * ca);
    br[t + 256] = __float2half_rn(e1 * cs + a1 * ca);
}

// ---------------------------------------------------------------------------
// LayerNorm (ddof=1), warp per row
// ---------------------------------------------------------------------------
__device__ __forceinline__ void ln_core(const float* __restrict__ xr,
                                        const float* __restrict__ a,
                                        const float* __restrict__ bb,
                                        int c, float4& o0, float4& o1) {
    float4 v0 = *(const float4*)(xr + c);
    float4 v1 = *(const float4*)(xr + c + 4);
    float s = v0.x+v0.y+v0.z+v0.w + v1.x+v1.y+v1.z+v1.w;
    #pragma unroll
    for (int o = 16; o; o >>= 1) s += __shfl_xor_sync(0xffffffffu, s, o);
    float mean = s * (1.f / Dn);

    float c0[8] = {v0.x-mean, v0.y-mean, v0.z-mean, v0.w-mean,
                   v1.x-mean, v1.y-mean, v1.z-mean, v1.w-mean};
    float sq = 0.f;
    #pragma unroll
    for (int i = 0; i < 8; i++) sq += c0[i]*c0[i];
    #pragma unroll
    for (int o = 16; o; o >>= 1) sq += __shfl_xor_sync(0xffffffffu, sq, o);
    float inv = 1.f / (sqrtf(sq * (1.f / (Dn - 1))) + 1e-6f);

    float4 a0 = *(const float4*)(a + c);
    float4 a1 = *(const float4*)(a + c + 4);
    float4 b0 = *(const float4*)(bb + c);
    float4 b1 = *(const float4*)(bb + c + 4);
    o0.x = a0.x*c0[0]*inv + b0.x;  o0.y = a0.y*c0[1]*inv + b0.y;
    o0.z = a0.z*c0[2]*inv + b0.z;  o0.w = a0.w*c0[3]*inv + b0.w;
    o1.x = a1.x*c0[4]*inv + b1.x;  o1.y = a1.y*c0[5]*inv + b1.y;
    o1.z = a1.z*c0[6]*inv + b1.z;  o1.w = a1.w*c0[7]*inv + b1.w;
}

__global__ void ln_f(const float* __restrict__ x, const float* __restrict__ a,
                     const float* __restrict__ bb, float* __restrict__ out) {
    const size_t row = (size_t)blockIdx.x * 8 + (threadIdx.x >> 5);
    const int c = (threadIdx.x & 31) * 8;
    float4 o0, o1;
    ln_core(x + row * Dn, a, bb, c, o0, o1);
    *(float4*)(out + row * Dn + c)     = o0;
    *(float4*)(out + row * Dn + c + 4) = o1;
}

__global__ void ln_h(const float* __restrict__ x, const float* __restrict__ a,
                     const float* __restrict__ bb, __half* __restrict__ out) {
    const size_t row = (size_t)blockIdx.x * 8 + (threadIdx.x >> 5);
    const int c = (threadIdx.x & 31) * 8;
    float4 o0, o1;
    ln_core(x + row * Dn, a, bb, c, o0, o1);
    *(uint4*)(out + row * Dn + c) = pack_h8(o0, o1);
}

// ---------------------------------------------------------------------------
// Shared GEMM epilogue: stage accs through smem, bias/act/res, store
// ---------------------------------------------------------------------------
#define LDS_ 36

template<int CHALF>
__device__ __forceinline__ void gemm_epilogue(
    wmma::fragment<wmma::accumulator, 16, 16, 16, float> acc[2][2],
    float* fst, const float* bias, const float* res, void* Cv,
    int Nc, int act, int tm, int tn, int warp, int lane, int wm, int wn) {

    float* stg = fst + warp * 32 * LDS_;
    #pragma unroll
    for (int mm = 0; mm < 2; mm++)
        #pragma unroll
        for (int nn = 0; nn < 2; nn++)
            wmma::store_matrix_sync(stg + mm * 16 * LDS_ + nn * 16,
                                    acc[mm][nn], LDS_, wmma::mem_row_major);
    __syncwarp();

    const int growb = tm + wm * 32;
    const int gcolb = tn + wn * 32;
    #pragma unroll
    for (int it = 0; it < 8; it++) {
        int idx = it * 32 + lane;
        int rr = idx >> 3;
        int cc = (idx & 7) * 4;
        int col = gcolb + cc;
        float4 v = *(float4*)(stg + rr * LDS_ + cc);
        if (bias) {
            float4 bb4 = *(const float4*)(bias + col);
            v.x += bb4.x; v.y += bb4.y; v.z += bb4.z; v.w += bb4.w;
        }
        if (act) {
            v.x = v.x > 0.f ? v.x : 0.1f * v.x;
            v.y = v.y > 0.f ? v.y : 0.1f * v.y;
            v.z = v.z > 0.f ? v.z : 0.1f * v.z;
            v.w = v.w > 0.f ? v.w : 0.1f * v.w;
        }
        size_t row = (size_t)(growb + rr);
        if (CHALF) {
            storeC4h((half*)Cv + row * Nc + col, v);
        } else {
            float* Cf = (float*)Cv;
            if (res) {
                float4 r4 = *(const float4*)(res + row * Nc + col);
                v.x += r4.x; v.y += r4.y; v.z += r4.z; v.w += r4.w;
            }
            *(float4*)(Cf + row * Nc + col) = v;
        }
    }
}

// ---------------------------------------------------------------------------
// cp.async 3-stage GEMM (half A): 64x128 tile, BK=32, 8 warps (2x4), 32x32 warp
// smem (halves): A stages [3][64][40] at 0; B stages [3][32][136] at 7680
// total 20736 halves = 41472 B. Epilogue reuses as float (36864 B).
// ---------------------------------------------------------------------------
#define CA_SMEM_BYTES 41472

template<int CHALF>
__device__ __forceinline__ void gemm_body_ca(
    const half* __restrict__ A, const half* __restrict__ W,
    const float* __restrict__ bias, const float* __restrict__ res,
    void* __restrict__ Cv, int Nc, int K, int act, char* smemc) {

    half*  hs  = (half*)smemc;
    float* fst = (float*)smemc;

    const int tm = blockIdx.y * 64;
    const int tn = blockIdx.x * 128;
    const int tid = threadIdx.x;
    const int warp = tid >> 5;
    const int lane = tid & 31;
    const int wm = warp >> 2;
    const int wn = warp & 3;

    const int arow = tid >> 2;            // 0..63
    const int acol = (tid & 3) * 8;       // 0,8,16,24
    const uint32_t sbase = (uint32_t)__cvta_generic_to_shared(hs);

    const half* gA = A + (size_t)(tm + arow) * K + acol;

    wmma::fragment<wmma::accumulator, 16, 16, 16, float> acc[2][2];
    #pragma unroll
    for (int mm = 0; mm < 2; mm++)
        #pragma unroll
        for (int nn = 0; nn < 2; nn++)
            wmma::fill_fragment(acc[mm][nn], 0.f);

    const int nIter = K >> 5;

    // prefetch stages 0,1
    #pragma unroll
    for (int p = 0; p < 2; p++) {
        int k0 = p * 32;
        cp16(sbase + (uint32_t)(p * 2560 + arow * 40 + acol) * 2, gA + k0);
        #pragma unroll
        for (int i = 0; i < 2; i++) {
            int idx = tid + i * 256;
            int r = idx >> 4, c = (idx & 15) * 8;
            cp16(sbase + (uint32_t)(7680 + p * 4352 + r * 136 + c) * 2,
                 W + (size_t)(k0 + r) * Nc + tn + c);
        }
        cp_commit();
    }

    int s = 0;
    for (int it = 0; it < nIter; it++) {
        if (it + 1 < nIter) cp_wait1(); else cp_wait0();
        __syncthreads();

        if (it + 2 < nIter) {
            int ps = (it + 2) % 3;
            int k0 = (it + 2) * 32;
            cp16(sbase + (uint32_t)(ps * 2560 + arow * 40 + acol) * 2, gA + k0);
            #pragma unroll
            for (int i = 0; i < 2; i++) {
                int idx = tid + i * 256;
                int r = idx >> 4, c = (idx & 15) * 8;
                cp16(sbase + (uint32_t)(7680 + ps * 4352 + r * 136 + c) * 2,
                     W + (size_t)(k0 + r) * Nc + tn + c);
            }
            cp_commit();
        }

        const half* As = hs + s * 2560;
        const half* Bs = hs + 7680 + s * 4352;
        #pragma unroll
        for (int ks = 0; ks < 2; ks++) {
            wmma::fragment<wmma::matrix_a, 16, 16, 16, half, wmma::row_major> af[2];
            wmma::fragment<wmma::matrix_b, 16, 16, 16, half, wmma::row_major> bf[2];
            wmma::load_matrix_sync(af[0], As + (wm * 32)      * 40 + ks * 16, 40);
            wmma::load_matrix_sync(af[1], As + (wm * 32 + 16) * 40 + ks * 16, 40);
            wmma::load_matrix_sync(bf[0], Bs + (ks * 16) * 136 + wn * 32,      136);
            wmma::load_matrix_sync(bf[1], Bs + (ks * 16) * 136 + wn * 32 + 16, 136);
            wmma::mma_sync(acc[0][0], af[0], bf[0], acc[0][0]);
            wmma::mma_sync(acc[0][1], af[0], bf[1], acc[0][1]);
            wmma::mma_sync(acc[1][0], af[1], bf[0], acc[1][0]);
            wmma::mma_sync(acc[1][1], af[1], bf[1], acc[1][1]);
        }
        s = (s == 2) ? 0 : s + 1;
    }
    __syncthreads();

    gemm_epilogue<CHALF>(acc, fst, bias, res, Cv, Nc, act, tm, tn, warp, lane, wm, wn);
}

// A half, C half
__global__ void __launch_bounds__(256, 2)
gemm_hh(const half* __restrict__ A, const half* __restrict__ W,
        const float* __restrict__ bias, half* __restrict__ C,
        int Nc, int K, int act) {
    __shared__ __align__(16) char smem[CA_SMEM_BYTES];
    gemm_body_ca<1>(A, W, bias, nullptr, C, Nc, K, act, smem);
}

// A half, C float (+res)
__global__ void __launch_bounds__(256, 2)
gemm_hf(const half* __restrict__ A, const half* __restrict__ W,
        const float* __restrict__ bias, const float* __restrict__ res,
        float* __restrict__ C, int Nc, int K, int act) {
    __shared__ __align__(16) char smem[CA_SMEM_BYTES];
    gemm_body_ca<0>(A, W, bias, res, C, Nc, K, act, smem);
}

// baseV: A half z-strided, W(V) half z-strided, C float z-strided
__global__ void __launch_bounds__(256, 2)
gemm_hfz(const half* __restrict__ A, const half* __restrict__ W,
         float* __restrict__ C, int Nc, int K,
         long sA, long sW, long sC) {
    __shared__ __align__(16) char smem[CA_SMEM_BYTES];
    gemm_body_ca<0>(A + (size_t)blockIdx.z * sA, W + (size_t)blockIdx.z * sW,
                    nullptr, nullptr, C + (size_t)blockIdx.z * sC, Nc, K, 0, smem);
}

// Fused QKV: z selects projection. A half, C half.
__global__ void __launch_bounds__(256, 2)
gemm_qkv(const half* __restrict__ A, const half* __restrict__ Wh,
         long wStride,
         const float* __restrict__ b0, const float* __restrict__ b1,
         const float* __restrict__ b2,
         half* __restrict__ C0, half* __restrict__ C1, half* __restrict__ C2,
         int Nc, int K) {
    __shared__ __align__(16) char smem[CA_SMEM_BYTES];
    const half* W = Wh + (size_t)blockIdx.z * wStride;
    const float* bb = (blockIdx.z == 0) ? b0 : (blockIdx.z == 1) ? b1 : b2;
    half* C = (blockIdx.z == 0) ? C0 : (blockIdx.z == 1) ? C1 : C2;
    gemm_body_ca<1>(A, W, bb, nullptr, C, Nc, K, 0, smem);
}

// ---------------------------------------------------------------------------
// Legacy double-buffered body for fp32-A (Wo GEMM only)
// ---------------------------------------------------------------------------
#define LDAH 40
#define LDBH 136
#define SMEM_BYTES 36864

__global__ void __launch_bounds__(256, 2)
gemm_ff(const float* __restrict__ A, const half* __restrict__ W,
        const float* __restrict__ bias, const float* __restrict__ res,
        float* __restrict__ C, int Nc, int K, int act) {
    __shared__ __align__(16) char smemc[SMEM_BYTES];
    half*  hs  = (half*)smemc;
    float* fst = (float*)smemc;

    const int tm = blockIdx.y * 64;
    const int tn = blockIdx.x * 128;
    const int tid = threadIdx.x;
    const int warp = tid >> 5;
    const int lane = tid & 31;
    const int wm = warp >> 2;
    const int wn = warp & 3;

    #define ASH(buf,r,c) hs[(buf)*2560 + (r)*LDAH + (c)]
    #define BSH(buf,r,c) hs[5120 + (buf)*4352 + (r)*LDBH + (c)]

    const int arow = tid >> 2;
    const int acol = (tid & 3) * 8;
    const int brow = tid >> 3;
    const int bcol = (tid & 7) * 16;

    const float* pA = A + (size_t)(tm + arow) * K + acol;
    const half*  pB = W + (size_t)brow * Nc + tn + bcol;

    wmma::fragment<wmma::accumulator, 16, 16, 16, float> acc[2][2];
    #pragma unroll
    for (int mm = 0; mm < 2; mm++)
        #pragma unroll
        for (int nn = 0; nn < 2; nn++)
            wmma::fill_fragment(acc[mm][nn], 0.f);

    uint4 ra  = loadA8(pA);
    uint4 rb0 = *(const uint4*)(pB);
    uint4 rb1 = *(const uint4*)(pB + 8);
    int buf = 0;
    *(uint4*)&ASH(0, arow, acol)     = ra;
    *(uint4*)&BSH(0, brow, bcol)     = rb0;
    *(uint4*)&BSH(0, brow, bcol + 8) = rb1;
    __syncthreads();

    for (int k0 = 32; k0 < K; k0 += 32) {
        ra  = loadA8(pA + k0);
        const half* pBk = pB + (size_t)k0 * Nc;
        rb0 = *(const uint4*)(pBk);
        rb1 = *(const uint4*)(pBk + 8);

        #pragma unroll
        for (int ks = 0; ks < 2; ks++) {
            wmma::fragment<wmma::matrix_a, 16, 16, 16, half, wmma::row_major> af[2];
            wmma::fragment<wmma::matrix_b, 16, 16, 16, half, wmma::row_major> bf[2];
            wmma::load_matrix_sync(af[0], &ASH(buf, wm * 32,      ks * 16), LDAH);
            wmma::load_matrix_sync(af[1], &ASH(buf, wm * 32 + 16, ks * 16), LDAH);
            wmma::load_matrix_sync(bf[0], &BSH(buf, ks * 16, wn * 32),      LDBH);
            wmma::load_matrix_sync(bf[1], &BSH(buf, ks * 16, wn * 32 + 16), LDBH);
            wmma::mma_sync(acc[0][0], af[0], bf[0], acc[0][0]);
            wmma::mma_sync(acc[0][1], af[0], bf[1], acc[0][1]);
            wmma::mma_sync(acc[1][0], af[1], bf[0], acc[1][0]);
            wmma::mma_sync(acc[1][1], af[1], bf[1], acc[1][1]);
        }

        buf ^= 1;
        *(uint4*)&ASH(buf, arow, acol)     = ra;
        *(uint4*)&BSH(buf, brow, bcol)     = rb0;
        *(uint4*)&BSH(buf, brow, bcol + 8) = rb1;
        __syncthreads();
    }

    #pragma unroll
    for (int ks = 0; ks < 2; ks++) {
        wmma::fragment<wmma::matrix_a, 16, 16, 16, half, wmma::row_major> af[2];
        wmma::fragment<wmma::matrix_b, 16, 16, 16, half, wmma::row_major> bf[2];
        wmma::load_matrix_sync(af[0], &ASH(buf, wm * 32,      ks * 16), LDAH);
        wmma::load_matrix_sync(af[1], &ASH(buf, wm * 32 + 16, ks * 16), LDAH);
        wmma::load_matrix_sync(bf[0], &BSH(buf, ks * 16, wn * 32),      LDBH);
        wmma::load_matrix_sync(bf[1], &BSH(buf, ks * 16, wn * 32 + 16), LDBH);
        wmma::mma_sync(acc[0][0], af[0], bf[0], acc[0][0]);
        wmma::mma_sync(acc[0][1], af[0], bf[1], acc[0][1]);
        wmma::mma_sync(acc[1][0], af[1], bf[0], acc[1][0]);
        wmma::mma_sync(acc[1][1], af[1], bf[1], acc[1][1]);
    }
    __syncthreads();

    gemm_epilogue<0>(acc, fst, bias, res, C, Nc, act, tm, tn, warp, lane, wm, wn);
    #undef ASH
    #undef BSH
}

// ---------------------------------------------------------------------------
// FP16 tensor-core flash attention (no running max: scores bounded).
// att += 0.3 * softmax(mask(qk^T/s)) @ v ; q,k,v half; att float.
// ---------------------------------------------------------------------------
#define ALQH 40
#define ALP  68
#define ALPH 72

__global__ void __launch_bounds__(128)
attn_tc(const __half* __restrict__ q,
        const __half* __restrict__ k,
        const __half* __restrict__ v,
        const int*    __restrict__ mask,
        float* __restrict__ att) {
    __shared__ __align__(16) half  Qs[64][ALQH];
    __shared__ __align__(16) half  Ks[64][ALQH];
    __shared__ __align__(16) half  Vs[64][ALQH];
    __shared__ __align__(16) float Ps[4][16][ALP];
    __shared__ __align__(16) half  Ph[4][16][ALPH];
    __shared__ int ms[64];

    const int b = blockIdx.z, h = blockIdx.y;
    const int tid = threadIdx.x;
    const int warp = tid >> 5;
    const int lane = tid & 31;
    const int qrow0 = blockIdx.x * 64;
    const float scale = 0.17677669529663687f;

    {
        int r = tid >> 1, c = (tid & 1) * 16;
        const __half* src = q + ((size_t)(b * Nn + qrow0 + r)) * Dn + h * DKn + c;
        *(uint4*)&Qs[r][c]     = *(const uint4*)(src);
        *(uint4*)&Qs[r][c + 8] = *(const uint4*)(src + 8);
    }

    wmma::fragment<wmma::accumulator, 16, 16, 16, float> ao[2];
    wmma::fill_fragment(ao[0], 0.f);
    wmma::fill_fragment(ao[1], 0.f);

    float l_tot = 0.f;
    const int myrow = lane >> 1;
    const int colh = (lane & 1) * 32;

    for (int kt = 0; kt < Nn / 64; kt++) {
        __syncthreads();
        {
            int r = tid >> 1, c = (tid & 1) * 16;
            size_t off = ((size_t)(b * Nn + kt * 64 + r)) * Dn + h * DKn + c;
            *(uint4*)&Ks[r][c]     = *(const uint4*)(k + off);
            *(uint4*)&Ks[r][c + 8] = *(const uint4*)(k + off + 8);
            *(uint4*)&Vs[r][c]     = *(const uint4*)(v + off);
            *(uint4*)&Vs[r][c + 8] = *(const uint4*)(v + off + 8);
        }
        if (tid < 64) ms[tid] = mask[b * Nn + kt * 64 + tid];
        __syncthreads();

        wmma::fragment<wmma::accumulator, 16, 16, 16, float> sf[4];
        #pragma unroll
        for (int n = 0; n < 4; n++) wmma::fill_fragment(sf[n], 0.f);
        #pragma unroll
        for (int ks = 0; ks < 2; ks++) {
            wmma::fragment<wmma::matrix_a, 16, 16, 16, half, wmma::row_major> af;
            wmma::load_matrix_sync(af, &Qs[warp * 16][ks * 16], ALQH);
            #pragma unroll
            for (int n = 0; n < 4; n++) {
                wmma::fragment<wmma::matrix_b, 16, 16, 16, half, wmma::col_major> bf;
                wmma::load_matrix_sync(bf, &Ks[n * 16][ks * 16], ALQH);
                wmma::mma_sync(sf[n], af, bf, sf[n]);
            }
        }
        #pragma unroll
        for (int n = 0; n < 4; n++)
            wmma::store_matrix_sync(&Ps[warp][0][n * 16], sf[n], ALP, wmma::mem_row_major);
        __syncwarp();

        float lp = 0.f;
        const float* srow = &Ps[warp][myrow][colh];
        half* prow = &Ph[warp][myrow][colh];
        const int* mrow = ms + colh;
        #pragma unroll
        for (int j = 0; j < 32; j += 2) {
            float p0 = mrow[j]     ? __expf(srow[j]     * scale) : 0.f;
            float p1 = mrow[j + 1] ? __expf(srow[j + 1] * scale) : 0.f;
            lp += p0 + p1;
            *(half2*)(prow + j) = __floats2half2_rn(p0, p1);
        }
        lp += __shfl_xor_sync(0xffffffffu, lp, 1);
        l_tot += lp;
        __syncwarp();

        #pragma unroll
        for (int ks = 0; ks < 4; ks++) {
            wmma::fragment<wmma::matrix_a, 16, 16, 16, half, wmma::row_major> af;
            wmma::load_matrix_sync(af, &Ph[warp][0][ks * 16], ALPH);
            #pragma unroll
            for (int n = 0; n < 2; n++) {
                wmma::fragment<wmma::matrix_b, 16, 16, 16, half, wmma::row_major> bf;
                wmma::load_matrix_sync(bf, &Vs[ks * 16][n * 16], ALQH);
                wmma::mma_sync(ao[n], af, bf, ao[n]);
            }
        }
    }

    float* Os = &Ps[warp][0][0];
    wmma::store_matrix_sync(Os,      ao[0], ALP, wmma::mem_row_major);
    wmma::store_matrix_sync(Os + 16, ao[1], ALP, wmma::mem_row_major);
    __syncwarp();

    const float inv = 0.3f / l_tot;
    const int ch = (lane & 1) * 16;
    float* orow = att + ((size_t)(b * Nn + qrow0 + warp * 16 + myrow)) * Dn + h * DKn + ch;
    float* sro = Os + myrow * ALP + ch;
    #pragma unroll
    for (int c = 0; c < 4; c++) {
        float4 t = *(float4*)(orow + c * 4);
        float4 s4 = *(float4*)(sro + c * 4);
        t.x += s4.x * inv; t.y += s4.y * inv;
        t.z += s4.z * inv; t.w += s4.w * inv;
        *(float4*)(orow + c * 4) = t;
    }
}

// ---------------------------------------------------------------------------
// Launch
// ---------------------------------------------------------------------------
extern "C" void kernel_launch(void* const* d_in, const int* in_sizes, int n_in,
                              void* d_out, int out_size) {
    const float* x_in  = (const float*)d_in[0];
    const int*   mask  = (const int*)  d_in[1];
    const float* adj   = (const float*)d_in[2];
    const float* dist  = (const float*)d_in[3];
    const float* Wq    = (const float*)d_in[5];
    const float* bq    = (const float*)d_in[6];
    const float* Wk    = (const float*)d_in[7];
    const float* bk    = (const float*)d_in[8];
    const float* Wv    = (const float*)d_in[9];
    const float* bv    = (const float*)d_in[10];
    const float* Wo    = (const float*)d_in[11];
    const float* bo    = (const float*)d_in[12];
    const float* Wf1   = (const float*)d_in[13];
    const float* bf1   = (const float*)d_in[14];
    const float* Wf2   = (const float*)d_in[15];
    const float* bf2   = (const float*)d_in[16];
    const float* ln1a  = (const float*)d_in[17];
    const float* ln1b  = (const float*)d_in[18];
    const float* ln2a  = (const float*)d_in[19];
    const float* ln2b  = (const float*)d_in[20];
    const float* lnfa  = (const float*)d_in[21];
    const float* lnfb  = (const float*)d_in[22];

    float *px, *patt;
    __half *pbaseh, *phh, *pqh, *pkh, *pvh, *pt1, *pwh;
    cudaGetSymbolAddress((void**)&px,     g_x);
    cudaGetSymbolAddress((void**)&patt,   g_att);
    cudaGetSymbolAddress((void**)&pbaseh, g_baseh);
    cudaGetSymbolAddress((void**)&phh,    g_hh);
    cudaGetSymbolAddress((void**)&pqh,    g_qh);
    cudaGetSymbolAddress((void**)&pkh,    g_kh);
    cudaGetSymbolAddress((void**)&pvh,    g_vh);
    cudaGetSymbolAddress((void**)&pt1,    g_t1);
    cudaGetSymbolAddress((void**)&pwh,    g_wh);

    cudaMemcpyAsync(px, x_in, sizeof(float) * BND, cudaMemcpyDeviceToDevice, 0);

    cvt_w<<<(6 * WSZ) / 1024, 256>>>(Wq, Wk, Wv, Wo, Wf1, Wf2, pwh);
    base_kernel<<<Bn * Nn, 256>>>(dist, adj, mask, pbaseh);

    const dim3 gProj(Dn / 128, (Bn * Nn) / 64, 1);    // 256 blocks
    const dim3 gQKV (Dn / 128, (Bn * Nn) / 64, 3);    // 768 blocks
    const dim3 gBaseV(Dn / 128, Nn / 64, Bn);         // 256 blocks
    const dim3 gAttn(Nn / 64, Hn, Bn);                // 1024 blocks
    const dim3 gLN(Bn * Nn / 8, 1, 1);

    for (int i = 0; i < Ln; i++) {
        const size_t wOff = (size_t)i * Dn * Dn;
        const size_t vOff = (size_t)i * Dn;

        ln_h<<<gLN, 256>>>(px, ln1a + vOff, ln1b + vOff, phh);

        gemm_qkv<<<gQKV, 256>>>(phh, pwh + wOff, (long)WSZ,
                                bq + vOff, bk + vOff, bv + vOff,
                                pqh, pkh, pvh, Dn, Dn);

        // att = base @ V  (half base, K=512, cp.async)
        gemm_hfz<<<gBaseV, 256>>>(pbaseh, pvh, patt, Dn, Nn,
                                  (long)Nn * Nn, (long)Nn * Dn, (long)Nn * Dn);

        // att += 0.3 * softmax @ V
        attn_tc<<<gAttn, 128>>>(pqh, pkh, pvh, mask, patt);

        // x = x + att @ Wo + bo   (fp32 A path)
        gemm_ff<<<gProj, 256>>>(patt, pwh + 3 * WSZ + wOff, bo + vOff, px, px,
                                Dn, Dn, 0);

        // FFN (cp.async)
        ln_h<<<gLN, 256>>>(px, ln2a + vOff, ln2b + vOff, phh);
        gemm_hh<<<gProj, 256>>>(phh, pwh + 4 * WSZ + wOff, bf1 + vOff, pt1,
                                Dn, Dn, 1);
        gemm_hf<<<gProj, 256>>>(pt1, pwh + 5 * WSZ + wOff, bf2 + vOff, px, px,
                                Dn, Dn, 1);
    }

    ln_f<<<gLN, 256>>>(px, lnfa, lnfb, (float*)d_out);
}

// round 12
// speedup vs baseline: 4.0880x; 1.0105x over previous
#include <cuda_runtime.h>
#include <cuda_fp16.h>
#include <math.h>
#include <mma.h>
#include <stdint.h>

using namespace nvcuda;

// Problem constants
#define Bn 16
#define Nn 512
#define Dn 256
#define Hn 8
#define Ln 4
#define DKn 32

#define BND (Bn*Nn*Dn)   // 2,097,152
#define BNN (Bn*Nn*Nn)   // 4,194,304
#define WSZ (Ln*Dn*Dn)   // 262,144 per weight set

static __device__ float  g_x[BND];
static __device__ __half g_baseh[BNN];
static __device__ __half g_hh[BND];
static __device__ __half g_qh[BND];
static __device__ __half g_kh[BND];
static __device__ __half g_vh[BND];
static __device__ __half g_t1[BND];
static __device__ __half g_ph[BND];      // attention output (half)
static __device__ __half g_wh[6 * WSZ];

// ---------------------------------------------------------------------------
// helpers
// ---------------------------------------------------------------------------
__device__ __forceinline__ uint4 pack_h8(float4 a, float4 b) {
    half2 h0 = __floats2half2_rn(a.x, a.y);
    half2 h1 = __floats2half2_rn(a.z, a.w);
    half2 h2 = __floats2half2_rn(b.x, b.y);
    half2 h3 = __floats2half2_rn(b.z, b.w);
    uint4 r;
    r.x = *(unsigned*)&h0; r.y = *(unsigned*)&h1;
    r.z = *(unsigned*)&h2; r.w = *(unsigned*)&h3;
    return r;
}

__device__ __forceinline__ void storeC4h(half* p, float4 v) {
    half2 a = __floats2half2_rn(v.x, v.y);
    half2 b = __floats2half2_rn(v.z, v.w);
    uint2 u; u.x = *(unsigned*)&a; u.y = *(unsigned*)&b;
    *(uint2*)p = u;
}

// cp.async primitives
__device__ __forceinline__ void cp16(uint32_t s, const void* g) {
    asm volatile("cp.async.cg.shared.global [%0], [%1], 16;" :: "r"(s), "l"(g));
}
__device__ __forceinline__ void cp_commit() {
    asm volatile("cp.async.commit_group;" ::: "memory");
}
__device__ __forceinline__ void cp_wait1() {
    asm volatile("cp.async.wait_group 1;" ::: "memory");
}
__device__ __forceinline__ void cp_wait0() {
    asm volatile("cp.async.wait_group 0;" ::: "memory");
}

// ---------------------------------------------------------------------------
// weight conversion fp32 -> fp16
// ---------------------------------------------------------------------------
__global__ void cvt_w(const float* __restrict__ Wq, const float* __restrict__ Wk,
                      const float* __restrict__ Wv, const float* __restrict__ Wo,
                      const float* __restrict__ Wf1, const float* __restrict__ Wf2,
                      __half* __restrict__ out) {
    const int idx = (blockIdx.x * 256 + threadIdx.x) * 4;
    const int w = idx / WSZ;
    const int r = idx - w * WSZ;
    const float* srcs[6] = {Wq, Wk, Wv, Wo, Wf1, Wf2};
    float4 v = *(const float4*)(srcs[w] + r);
    half2 a = __floats2half2_rn(v.x, v.y);
    half2 b = __floats2half2_rn(v.z, v.w);
    uint2 u; u.x = *(unsigned*)&a; u.y = *(unsigned*)&b;
    *(uint2*)(out + idx) = u;
}

// ---------------------------------------------------------------------------
// block reductions (256 threads)
// ---------------------------------------------------------------------------
__device__ __forceinline__ float blockSum256(float v) {
    __shared__ float sm[8];
    __syncthreads();
    #pragma unroll
    for (int o = 16; o; o >>= 1) v += __shfl_xor_sync(0xffffffffu, v, o);
    if ((threadIdx.x & 31) == 0) sm[threadIdx.x >> 5] = v;
    __syncthreads();
    float t = 0.f;
    #pragma unroll
    for (int i = 0; i < 8; i++) t += sm[i];
    return t;
}

__device__ __forceinline__ float blockMax256(float v) {
    __shared__ float sm[8];
    __syncthreads();
    #pragma unroll
    for (int o = 16; o; o >>= 1) v = fmaxf(v, __shfl_xor_sync(0xffffffffu, v, o));
    if ((threadIdx.x & 31) == 0) sm[threadIdx.x >> 5] = v;
    __syncthreads();
    float t = sm[0];
    #pragma unroll
    for (int i = 1; i < 8; i++) t = fmaxf(t, sm[i]);
    return t;
}

// ---------------------------------------------------------------------------
// base (half output)
// ---------------------------------------------------------------------------
__global__ void base_kernel(const float* __restrict__ dist,
                            const float* __restrict__ adj,
                            const int*   __restrict__ mask,
                            __half* __restrict__ base) {
    const int bi = blockIdx.x;
    const int b  = bi >> 9;
    const float* dr = dist + (size_t)bi * Nn;
    const float* ar = adj  + (size_t)bi * Nn;
    __half*      br = base + (size_t)bi * Nn;
    const int t = threadIdx.x;

    const int m0 = mask[b * Nn + t];
    const int m1 = mask[b * Nn + t + 256];
    float v0 = m0 ? -dr[t]       : -INFINITY;
    float v1 = m1 ? -dr[t + 256] : -INFINITY;

    float mx = blockMax256(fmaxf(v0, v1));
    float e0 = __expf(v0 - mx);
    float e1 = __expf(v1 - mx);
    float ssum = blockSum256(e0 + e1);

    float a0 = ar[t], a1 = ar[t + 256];
    float asum = blockSum256(a0 + a1);

    float cs = 0.3f / ssum;
    float ca = 0.4f / (asum + 1e-6f);
    br[t]       = __float2half_rn(e0 * cs + a0 * ca);
    br[t + 256] = __float2half_rn(e1 * cs + a1 * ca);
}

// ---------------------------------------------------------------------------
// LayerNorm (ddof=1), warp per row
// ---------------------------------------------------------------------------
__device__ __forceinline__ void ln_core(const float* __restrict__ xr,
                                        const float* __restrict__ a,
                                        const float* __restrict__ bb,
                                        int c, float4& o0, float4& o1) {
    float4 v0 = *(const float4*)(xr + c);
    float4 v1 = *(const float4*)(xr + c + 4);
    float s = v0.x+v0.y+v0.z+v0.w + v1.x+v1.y+v1.z+v1.w;
    #pragma unroll
    for (int o = 16; o; o >>= 1) s += __shfl_xor_sync(0xffffffffu, s, o);
    float mean = s * (1.f / Dn);

    float c0[8] = {v0.x-mean, v0.y-mean, v0.z-mean, v0.w-mean,
                   v1.x-mean, v1.y-mean, v1.z-mean, v1.w-mean};
    float sq = 0.f;
    #pragma unroll
    for (int i = 0; i < 8; i++) sq += c0[i]*c0[i];
    #pragma unroll
    for (int o = 16; o; o >>= 1) sq += __shfl_xor_sync(0xffffffffu, sq, o);
    float inv = 1.f / (sqrtf(sq * (1.f / (Dn - 1))) + 1e-6f);

    float4 a0 = *(const float4*)(a + c);
    float4 a1 = *(const float4*)(a + c + 4);
    float4 b0 = *(const float4*)(bb + c);
    float4 b1 = *(const float4*)(bb + c + 4);
    o0.x = a0.x*c0[0]*inv + b0.x;  o0.y = a0.y*c0[1]*inv + b0.y;
    o0.z = a0.z*c0[2]*inv + b0.z;  o0.w = a0.w*c0[3]*inv + b0.w;
    o1.x = a1.x*c0[4]*inv + b1.x;  o1.y = a1.y*c0[5]*inv + b1.y;
    o1.z = a1.z*c0[6]*inv + b1.z;  o1.w = a1.w*c0[7]*inv + b1.w;
}

__global__ void ln_f(const float* __restrict__ x, const float* __restrict__ a,
                     const float* __restrict__ bb, float* __restrict__ out) {
    const size_t row = (size_t)blockIdx.x * 8 + (threadIdx.x >> 5);
    const int c = (threadIdx.x & 31) * 8;
    float4 o0, o1;
    ln_core(x + row * Dn, a, bb, c, o0, o1);
    *(float4*)(out + row * Dn + c)     = o0;
    *(float4*)(out + row * Dn + c + 4) = o1;
}

__global__ void ln_h(const float* __restrict__ x, const float* __restrict__ a,
                     const float* __restrict__ bb, __half* __restrict__ out) {
    const size_t row = (size_t)blockIdx.x * 8 + (threadIdx.x >> 5);
    const int c = (threadIdx.x & 31) * 8;
    float4 o0, o1;
    ln_core(x + row * Dn, a, bb, c, o0, o1);
    *(uint4*)(out + row * Dn + c) = pack_h8(o0, o1);
}

// ---------------------------------------------------------------------------
// cp.async 3-stage GEMM, 128x128 block tile, BK=32, 8 warps (4x2), warp 32x64.
// smem (halves): A stages [3][128][40] at 0 (stride 5120);
//                B stages [3][32][136] at 15360 (stride 4352). Total 28416 h.
// Epilogue reuses smem as float: 8 warps * 16*68 floats (2 passes).
// Dynamic smem = 56832 bytes.
// ---------------------------------------------------------------------------
#define CA2_SMEM 56832

template<int CHALF>
__device__ __forceinline__ void gemm_body2(
    const half* __restrict__ A, const half* __restrict__ W,
    const float* __restrict__ bias, const float* __restrict__ res,
    void* __restrict__ Cv, int Nc, int K, int act, half* hs) {

    float* fst = (float*)hs;

    const int tm = blockIdx.y * 128;
    const int tn = blockIdx.x * 128;
    const int tid = threadIdx.x;
    const int warp = tid >> 5;
    const int lane = tid & 31;
    const int wm = warp >> 1;          // 0..3 -> 32-row band
    const int wn = warp & 1;           // 0..1 -> 64-col band

    const int ar0 = tid >> 2;          // 0..63
    const int ac0 = (tid & 3) * 8;     // 0,8,16,24
    const uint32_t sbase = (uint32_t)__cvta_generic_to_shared(hs);

    const half* gA0 = A + (size_t)(tm + ar0) * K + ac0;
    const half* gA1 = gA0 + (size_t)64 * K;

    wmma::fragment<wmma::accumulator, 16, 16, 16, float> acc[2][4];
    #pragma unroll
    for (int mm = 0; mm < 2; mm++)
        #pragma unroll
        for (int nn = 0; nn < 4; nn++)
            wmma::fill_fragment(acc[mm][nn], 0.f);

    const int nIter = K >> 5;

    // prefetch stages 0,1
    #pragma unroll
    for (int p = 0; p < 2; p++) {
        int k0 = p * 32;
        cp16(sbase + (uint32_t)(p * 5120 + ar0 * 40 + ac0) * 2, gA0 + k0);
        cp16(sbase + (uint32_t)(p * 5120 + (ar0 + 64) * 40 + ac0) * 2, gA1 + k0);
        #pragma unroll
        for (int i = 0; i < 2; i++) {
            int idx = tid + i * 256;
            int r = idx >> 4, c = (idx & 15) * 8;
            cp16(sbase + (uint32_t)(15360 + p * 4352 + r * 136 + c) * 2,
                 W + (size_t)(k0 + r) * Nc + tn + c);
        }
        cp_commit();
    }

    int s = 0;
    for (int it = 0; it < nIter; it++) {
        if (it + 1 < nIter) cp_wait1(); else cp_wait0();
        __syncthreads();

        if (it + 2 < nIter) {
            int ps = (it + 2) % 3;
            int k0 = (it + 2) * 32;
            cp16(sbase + (uint32_t)(ps * 5120 + ar0 * 40 + ac0) * 2, gA0 + k0);
            cp16(sbase + (uint32_t)(ps * 5120 + (ar0 + 64) * 40 + ac0) * 2, gA1 + k0);
            #pragma unroll
            for (int i = 0; i < 2; i++) {
                int idx = tid + i * 256;
                int r = idx >> 4, c = (idx & 15) * 8;
                cp16(sbase + (uint32_t)(15360 + ps * 4352 + r * 136 + c) * 2,
                     W + (size_t)(k0 + r) * Nc + tn + c);
            }
            cp_commit();
        }

        const half* As = hs + s * 5120;
        const half* Bs = hs + 15360 + s * 4352;
        #pragma unroll
        for (int ks = 0; ks < 2; ks++) {
            wmma::fragment<wmma::matrix_a, 16, 16, 16, half, wmma::row_major> af[2];
            wmma::load_matrix_sync(af[0], As + (wm * 32)      * 40 + ks * 16, 40);
            wmma::load_matrix_sync(af[1], As + (wm * 32 + 16) * 40 + ks * 16, 40);
            #pragma unroll
            for (int nn = 0; nn < 4; nn++) {
                wmma::fragment<wmma::matrix_b, 16, 16, 16, half, wmma::row_major> bf;
                wmma::load_matrix_sync(bf, Bs + (ks * 16) * 136 + wn * 64 + nn * 16, 136);
                wmma::mma_sync(acc[0][nn], af[0], bf, acc[0][nn]);
                wmma::mma_sync(acc[1][nn], af[1], bf, acc[1][nn]);
            }
        }
        s = (s == 2) ? 0 : s + 1;
    }
    __syncthreads();

    // epilogue: two 16-row passes per warp through smem stage
    float* stg = fst + warp * 16 * 68;
    const int gcolb = tn + wn * 64;
    #pragma unroll
    for (int mm = 0; mm < 2; mm++) {
        #pragma unroll
        for (int nn = 0; nn < 4; nn++)
            wmma::store_matrix_sync(stg + nn * 16, acc[mm][nn], 68, wmma::mem_row_major);
        __syncwarp();
        const int growb = tm + wm * 32 + mm * 16;
        #pragma unroll
        for (int it = 0; it < 8; it++) {
            int e = it * 32 + lane;            // 0..255
            int rr = e >> 4;                    // 0..15
            int cc = (e & 15) * 4;              // 0..60
            int col = gcolb + cc;
            float4 v = *(float4*)(stg + rr * 68 + cc);
            if (bias) {
                float4 bb4 = *(const float4*)(bias + col);
                v.x += bb4.x; v.y += bb4.y; v.z += bb4.z; v.w += bb4.w;
            }
            if (act) {
                v.x = v.x > 0.f ? v.x : 0.1f * v.x;
                v.y = v.y > 0.f ? v.y : 0.1f * v.y;
                v.z = v.z > 0.f ? v.z : 0.1f * v.z;
                v.w = v.w > 0.f ? v.w : 0.1f * v.w;
            }
            size_t row = (size_t)(growb + rr);
            if (CHALF) {
                storeC4h((half*)Cv + row * Nc + col, v);
            } else {
                float* Cf = (float*)Cv;
                if (res) {
                    float4 r4 = *(const float4*)(res + row * Nc + col);
                    v.x += r4.x; v.y += r4.y; v.z += r4.z; v.w += r4.w;
                }
                *(float4*)(Cf + row * Nc + col) = v;
            }
        }
        __syncwarp();
    }
}

// A half -> C half (f1)
__global__ void __launch_bounds__(256, 2)
gemm_hh(const half* __restrict__ A, const half* __restrict__ W,
        const float* __restrict__ bias, half* __restrict__ C,
        int Nc, int K, int act) {
    extern __shared__ __align__(16) half dynsm[];
    gemm_body2<1>(A, W, bias, nullptr, C, Nc, K, act, dynsm);
}

// A half -> C float + res (Wo, f2)
__global__ void __launch_bounds__(256, 2)
gemm_hf(const half* __restrict__ A, const half* __restrict__ W,
        const float* __restrict__ bias, const float* __restrict__ res,
        float* __restrict__ C, int Nc, int K, int act) {
    extern __shared__ __align__(16) half dynsm[];
    gemm_body2<0>(A, W, bias, res, C, Nc, K, act, dynsm);
}

// baseV: z-strided, A half, C half
__global__ void __launch_bounds__(256, 2)
gemm_hhz(const half* __restrict__ A, const half* __restrict__ W,
         half* __restrict__ C, int Nc, int K,
         long sA, long sW, long sC) {
    extern __shared__ __align__(16) half dynsm[];
    gemm_body2<1>(A + (size_t)blockIdx.z * sA, W + (size_t)blockIdx.z * sW,
                  nullptr, nullptr, C + (size_t)blockIdx.z * sC, Nc, K, 0, dynsm);
}

// Fused QKV
__global__ void __launch_bounds__(256, 2)
gemm_qkv(const half* __restrict__ A, const half* __restrict__ Wh,
         long wStride,
         const float* __restrict__ b0, const float* __restrict__ b1,
         const float* __restrict__ b2,
         half* __restrict__ C0, half* __restrict__ C1, half* __restrict__ C2,
         int Nc, int K) {
    extern __shared__ __align__(16) half dynsm[];
    const half* W = Wh + (size_t)blockIdx.z * wStride;
    const float* bb = (blockIdx.z == 0) ? b0 : (blockIdx.z == 1) ? b1 : b2;
    half* C = (blockIdx.z == 0) ? C0 : (blockIdx.z == 1) ? C1 : C2;
    gemm_body2<1>(A, W, bb, nullptr, C, Nc, K, 0, dynsm);
}

// ---------------------------------------------------------------------------
// FP16 flash attention (no running max); att(half) += 0.3*softmax@V
// ---------------------------------------------------------------------------
#define ALQH 40
#define ALP  68
#define ALPH 72

__global__ void __launch_bounds__(128)
attn_tc(const __half* __restrict__ q,
        const __half* __restrict__ k,
        const __half* __restrict__ v,
        const int*    __restrict__ mask,
        __half* __restrict__ att) {
    __shared__ __align__(16) half  Qs[64][ALQH];
    __shared__ __align__(16) half  Ks[64][ALQH];
    __shared__ __align__(16) half  Vs[64][ALQH];
    __shared__ __align__(16) float Ps[4][16][ALP];
    __shared__ __align__(16) half  Ph[4][16][ALPH];
    __shared__ int ms[64];

    const int b = blockIdx.z, h = blockIdx.y;
    const int tid = threadIdx.x;
    const int warp = tid >> 5;
    const int lane = tid & 31;
    const int qrow0 = blockIdx.x * 64;
    const float scale = 0.17677669529663687f;

    {
        int r = tid >> 1, c = (tid & 1) * 16;
        const __half* src = q + ((size_t)(b * Nn + qrow0 + r)) * Dn + h * DKn + c;
        *(uint4*)&Qs[r][c]     = *(const uint4*)(src);
        *(uint4*)&Qs[r][c + 8] = *(const uint4*)(src + 8);
    }

    wmma::fragment<wmma::accumulator, 16, 16, 16, float> ao[2];
    wmma::fill_fragment(ao[0], 0.f);
    wmma::fill_fragment(ao[1], 0.f);

    float l_tot = 0.f;
    const int myrow = lane >> 1;
    const int colh = (lane & 1) * 32;

    for (int kt = 0; kt < Nn / 64; kt++) {
        __syncthreads();
        {
            int r = tid >> 1, c = (tid & 1) * 16;
            size_t off = ((size_t)(b * Nn + kt * 64 + r)) * Dn + h * DKn + c;
            *(uint4*)&Ks[r][c]     = *(const uint4*)(k + off);
            *(uint4*)&Ks[r][c + 8] = *(const uint4*)(k + off + 8);
            *(uint4*)&Vs[r][c]     = *(const uint4*)(v + off);
            *(uint4*)&Vs[r][c + 8] = *(const uint4*)(v + off + 8);
        }
        if (tid < 64) ms[tid] = mask[b * Nn + kt * 64 + tid];
        __syncthreads();

        wmma::fragment<wmma::accumulator, 16, 16, 16, float> sf[4];
        #pragma unroll
        for (int n = 0; n < 4; n++) wmma::fill_fragment(sf[n], 0.f);
        #pragma unroll
        for (int ks = 0; ks < 2; ks++) {
            wmma::fragment<wmma::matrix_a, 16, 16, 16, half, wmma::row_major> af;
            wmma::load_matrix_sync(af, &Qs[warp * 16][ks * 16], ALQH);
            #pragma unroll
            for (int n = 0; n < 4; n++) {
                wmma::fragment<wmma::matrix_b, 16, 16, 16, half, wmma::col_major> bf;
                wmma::load_matrix_sync(bf, &Ks[n * 16][ks * 16], ALQH);
                wmma::mma_sync(sf[n], af, bf, sf[n]);
            }
        }
        #pragma unroll
        for (int n = 0; n < 4; n++)
            wmma::store_matrix_sync(&Ps[warp][0][n * 16], sf[n], ALP, wmma::mem_row_major);
        __syncwarp();

        float lp = 0.f;
        const float* srow = &Ps[warp][myrow][colh];
        half* prow = &Ph[warp][myrow][colh];
        const int* mrow = ms + colh;
        #pragma unroll
        for (int j = 0; j < 32; j += 2) {
            float p0 = mrow[j]     ? __expf(srow[j]     * scale) : 0.f;
            float p1 = mrow[j + 1] ? __expf(srow[j + 1] * scale) : 0.f;
            lp += p0 + p1;
            *(half2*)(prow + j) = __floats2half2_rn(p0, p1);
        }
        lp += __shfl_xor_sync(0xffffffffu, lp, 1);
        l_tot += lp;
        __syncwarp();

        #pragma unroll
        for (int ks = 0; ks < 4; ks++) {
            wmma::fragment<wmma::matrix_a, 16, 16, 16, half, wmma::row_major> af;
            wmma::load_matrix_sync(af, &Ph[warp][0][ks * 16], ALPH);
            #pragma unroll
            for (int n = 0; n < 2; n++) {
                wmma::fragment<wmma::matrix_b, 16, 16, 16, half, wmma::row_major> bf;
                wmma::load_matrix_sync(bf, &Vs[ks * 16][n * 16], ALQH);
                wmma::mma_sync(ao[n], af, bf, ao[n]);
            }
        }
    }

    float* Os = &Ps[warp][0][0];
    wmma::store_matrix_sync(Os,      ao[0], ALP, wmma::mem_row_major);
    wmma::store_matrix_sync(Os + 16, ao[1], ALP, wmma::mem_row_major);
    __syncwarp();

    const float inv = 0.3f / l_tot;
    const int ch = (lane & 1) * 16;
    __half* orow = att + ((size_t)(b * Nn + qrow0 + warp * 16 + myrow)) * Dn + h * DKn + ch;
    float* sro = Os + myrow * ALP + ch;
    #pragma unroll
    for (int c = 0; c < 8; c++) {
        half2 o2 = *(half2*)(orow + c * 2);
        float2 of = __half22float2(o2);
        of.x += sro[c * 2]     * inv;
        of.y += sro[c * 2 + 1] * inv;
        *(half2*)(orow + c * 2) = __floats2half2_rn(of.x, of.y);
    }
}

// ---------------------------------------------------------------------------
// Launch
// ---------------------------------------------------------------------------
extern "C" void kernel_launch(void* const* d_in, const int* in_sizes, int n_in,
                              void* d_out, int out_size) {
    const float* x_in  = (const float*)d_in[0];
    const int*   mask  = (const int*)  d_in[1];
    const float* adj   = (const float*)d_in[2];
    const float* dist  = (const float*)d_in[3];
    const float* Wq    = (const float*)d_in[5];
    const float* bq    = (const float*)d_in[6];
    const float* Wk    = (const float*)d_in[7];
    const float* bk    = (const float*)d_in[8];
    const float* Wv    = (const float*)d_in[9];
    const float* bv    = (const float*)d_in[10];
    const float* Wo    = (const float*)d_in[11];
    const float* bo    = (const float*)d_in[12];
    const float* Wf1   = (const float*)d_in[13];
    const float* bf1   = (const float*)d_in[14];
    const float* Wf2   = (const float*)d_in[15];
    const float* bf2   = (const float*)d_in[16];
    const float* ln1a  = (const float*)d_in[17];
    const float* ln1b  = (const float*)d_in[18];
    const float* ln2a  = (const float*)d_in[19];
    const float* ln2b  = (const float*)d_in[20];
    const float* lnfa  = (const float*)d_in[21];
    const float* lnfb  = (const float*)d_in[22];

    float *px;
    __half *pbaseh, *phh, *pqh, *pkh, *pvh, *pt1, *pph, *pwh;
    cudaGetSymbolAddress((void**)&px,     g_x);
    cudaGetSymbolAddress((void**)&pbaseh, g_baseh);
    cudaGetSymbolAddress((void**)&phh,    g_hh);
    cudaGetSymbolAddress((void**)&pqh,    g_qh);
    cudaGetSymbolAddress((void**)&pkh,    g_kh);
    cudaGetSymbolAddress((void**)&pvh,    g_vh);
    cudaGetSymbolAddress((void**)&pt1,    g_t1);
    cudaGetSymbolAddress((void**)&pph,    g_ph);
    cudaGetSymbolAddress((void**)&pwh,    g_wh);

    static bool attrDone = false;
    if (!attrDone) {
        cudaFuncSetAttribute(gemm_hh,  cudaFuncAttributeMaxDynamicSharedMemorySize, CA2_SMEM);
        cudaFuncSetAttribute(gemm_hf,  cudaFuncAttributeMaxDynamicSharedMemorySize, CA2_SMEM);
        cudaFuncSetAttribute(gemm_hhz, cudaFuncAttributeMaxDynamicSharedMemorySize, CA2_SMEM);
        cudaFuncSetAttribute(gemm_qkv, cudaFuncAttributeMaxDynamicSharedMemorySize, CA2_SMEM);
        attrDone = true;
    }

    cudaMemcpyAsync(px, x_in, sizeof(float) * BND, cudaMemcpyDeviceToDevice, 0);

    cvt_w<<<(6 * WSZ) / 1024, 256>>>(Wq, Wk, Wv, Wo, Wf1, Wf2, pwh);
    base_kernel<<<Bn * Nn, 256>>>(dist, adj, mask, pbaseh);

    const dim3 gProj(Dn / 128, (Bn * Nn) / 128, 1);   // (2,64) = 128 blocks
    const dim3 gQKV (Dn / 128, (Bn * Nn) / 128, 3);   // 384 blocks
    const dim3 gBaseV(Dn / 128, Nn / 128, Bn);        // (2,4,16) = 128 blocks
    const dim3 gAttn(Nn / 64, Hn, Bn);                // 1024 blocks
    const dim3 gLN(Bn * Nn / 8, 1, 1);

    for (int i = 0; i < Ln; i++) {
        const size_t wOff = (size_t)i * Dn * Dn;
        const size_t vOff = (size_t)i * Dn;

        ln_h<<<gLN, 256>>>(px, ln1a + vOff, ln1b + vOff, phh);

        gemm_qkv<<<gQKV, 256, CA2_SMEM>>>(phh, pwh + wOff, (long)WSZ,
                                          bq + vOff, bk + vOff, bv + vOff,
                                          pqh, pkh, pvh, Dn, Dn);

        // att = base @ V  (half, K=512)
        gemm_hhz<<<gBaseV, 256, CA2_SMEM>>>(pbaseh, pvh, pph, Dn, Nn,
                                            (long)Nn * Nn, (long)Nn * Dn, (long)Nn * Dn);

        // att += 0.3 * softmax @ V
        attn_tc<<<gAttn, 128>>>(pqh, pkh, pvh, mask, pph);

        // x = x + att @ Wo + bo
        gemm_hf<<<gProj, 256, CA2_SMEM>>>(pph, pwh + 3 * WSZ + wOff, bo + vOff, px, px,
                                          Dn, Dn, 0);

        // FFN
        ln_h<<<gLN, 256>>>(px, ln2a + vOff, ln2b + vOff, phh);
        gemm_hh<<<gProj, 256, CA2_SMEM>>>(phh, pwh + 4 * WSZ + wOff, bf1 + vOff, pt1,
                                          Dn, Dn, 1);
        gemm_hf<<<gProj, 256, CA2_SMEM>>>(pt1, pwh + 5 * WSZ + wOff, bf2 + vOff, px, px,
                                          Dn, Dn, 1);
    }

    ln_f<<<gLN, 256>>>(px, lnfa, lnfb, (float*)d_out);
}

// round 13
// speedup vs baseline: 4.7669x; 1.1661x over previous
#include <cuda_runtime.h>
#include <cuda_fp16.h>
#include <math.h>
#include <mma.h>
#include <stdint.h>

using namespace nvcuda;

// Problem constants
#define Bn 16
#define Nn 512
#define Dn 256
#define Hn 8
#define Ln 4
#define DKn 32

#define BND (Bn*Nn*Dn)   // 2,097,152
#define BNN (Bn*Nn*Nn)   // 4,194,304
#define WSZ (Ln*Dn*Dn)   // 262,144 per weight set

static __device__ float  g_x[BND];
static __device__ __half g_baseh[BNN];
static __device__ __half g_hh[BND];
static __device__ __half g_qh[BND];
static __device__ __half g_kh[BND];
static __device__ __half g_vh[BND];
static __device__ __half g_t1[BND];
static __device__ __half g_ph[BND];      // attention output (half)
static __device__ __half g_wh[6 * WSZ];
static __device__ int    g_idx[Bn * Nn]; // compacted valid-column indices
static __device__ int    g_cnt[Bn];      // valid counts per batch

// ---------------------------------------------------------------------------
// helpers
// ---------------------------------------------------------------------------
__device__ __forceinline__ uint4 pack_h8(float4 a, float4 b) {
    half2 h0 = __floats2half2_rn(a.x, a.y);
    half2 h1 = __floats2half2_rn(a.z, a.w);
    half2 h2 = __floats2half2_rn(b.x, b.y);
    half2 h3 = __floats2half2_rn(b.z, b.w);
    uint4 r;
    r.x = *(unsigned*)&h0; r.y = *(unsigned*)&h1;
    r.z = *(unsigned*)&h2; r.w = *(unsigned*)&h3;
    return r;
}

__device__ __forceinline__ void storeC4h(half* p, float4 v) {
    half2 a = __floats2half2_rn(v.x, v.y);
    half2 b = __floats2half2_rn(v.z, v.w);
    uint2 u; u.x = *(unsigned*)&a; u.y = *(unsigned*)&b;
    *(uint2*)p = u;
}

// cp.async primitives
__device__ __forceinline__ void cp16(uint32_t s, const void* g) {
    asm volatile("cp.async.cg.shared.global [%0], [%1], 16;" :: "r"(s), "l"(g));
}
__device__ __forceinline__ void cp_commit() {
    asm volatile("cp.async.commit_group;" ::: "memory");
}
__device__ __forceinline__ void cp_wait1() {
    asm volatile("cp.async.wait_group 1;" ::: "memory");
}
__device__ __forceinline__ void cp_wait0() {
    asm volatile("cp.async.wait_group 0;" ::: "memory");
}

// ---------------------------------------------------------------------------
// weight conversion fp32 -> fp16
// ---------------------------------------------------------------------------
__global__ void cvt_w(const float* __restrict__ Wq, const float* __restrict__ Wk,
                      const float* __restrict__ Wv, const float* __restrict__ Wo,
                      const float* __restrict__ Wf1, const float* __restrict__ Wf2,
                      __half* __restrict__ out) {
    const int idx = (blockIdx.x * 256 + threadIdx.x) * 4;
    const int w = idx / WSZ;
    const int r = idx - w * WSZ;
    const float* srcs[6] = {Wq, Wk, Wv, Wo, Wf1, Wf2};
    float4 v = *(const float4*)(srcs[w] + r);
    half2 a = __floats2half2_rn(v.x, v.y);
    half2 b = __floats2half2_rn(v.z, v.w);
    uint2 u; u.x = *(unsigned*)&a; u.y = *(unsigned*)&b;
    *(uint2*)(out + idx) = u;
}

// ---------------------------------------------------------------------------
// mask compaction: per batch, idx[] = ascending valid columns, cnt = count
// ---------------------------------------------------------------------------
__global__ void mask_idx_kernel(const int* __restrict__ mask,
                                int* __restrict__ idx, int* __restrict__ cnt) {
    __shared__ int sc[512];
    const int b = blockIdx.x, t = threadIdx.x;
    const int m = (mask[b * Nn + t] != 0) ? 1 : 0;
    sc[t] = m;
    __syncthreads();
    for (int o = 1; o < 512; o <<= 1) {
        int v = (t >= o) ? sc[t - o] : 0;
        __syncthreads();
        sc[t] += v;
        __syncthreads();
    }
    if (m) idx[b * Nn + sc[t] - 1] = t;
    if (t == 511) cnt[b] = sc[511];
}

// ---------------------------------------------------------------------------
// block reductions (256 threads)
// ---------------------------------------------------------------------------
__device__ __forceinline__ float blockSum256(float v) {
    __shared__ float sm[8];
    __syncthreads();
    #pragma unroll
    for (int o = 16; o; o >>= 1) v += __shfl_xor_sync(0xffffffffu, v, o);
    if ((threadIdx.x & 31) == 0) sm[threadIdx.x >> 5] = v;
    __syncthreads();
    float t = 0.f;
    #pragma unroll
    for (int i = 0; i < 8; i++) t += sm[i];
    return t;
}

__device__ __forceinline__ float blockMax256(float v) {
    __shared__ float sm[8];
    __syncthreads();
    #pragma unroll
    for (int o = 16; o; o >>= 1) v = fmaxf(v, __shfl_xor_sync(0xffffffffu, v, o));
    if ((threadIdx.x & 31) == 0) sm[threadIdx.x >> 5] = v;
    __syncthreads();
    float t = sm[0];
    #pragma unroll
    for (int i = 1; i < 8; i++) t = fmaxf(t, sm[i]);
    return t;
}

// ---------------------------------------------------------------------------
// base (half output)
// ---------------------------------------------------------------------------
__global__ void base_kernel(const float* __restrict__ dist,
                            const float* __restrict__ adj,
                            const int*   __restrict__ mask,
                            __half* __restrict__ base) {
    const int bi = blockIdx.x;
    const int b  = bi >> 9;
    const float* dr = dist + (size_t)bi * Nn;
    const float* ar = adj  + (size_t)bi * Nn;
    __half*      br = base + (size_t)bi * Nn;
    const int t = threadIdx.x;

    const int m0 = mask[b * Nn + t];
    const int m1 = mask[b * Nn + t + 256];
    float v0 = m0 ? -dr[t]       : -INFINITY;
    float v1 = m1 ? -dr[t + 256] : -INFINITY;

    float mx = blockMax256(fmaxf(v0, v1));
    float e0 = __expf(v0 - mx);
    float e1 = __expf(v1 - mx);
    float ssum = blockSum256(e0 + e1);

    float a0 = ar[t], a1 = ar[t + 256];
    float asum = blockSum256(a0 + a1);

    float cs = 0.3f / ssum;
    float ca = 0.4f / (asum + 1e-6f);
    br[t]       = __float2half_rn(e0 * cs + a0 * ca);
    br[t + 256] = __float2half_rn(e1 * cs + a1 * ca);
}

// ---------------------------------------------------------------------------
// LayerNorm (ddof=1), warp per row
// ---------------------------------------------------------------------------
__device__ __forceinline__ void ln_core(const float* __restrict__ xr,
                                        const float* __restrict__ a,
                                        const float* __restrict__ bb,
                                        int c, float4& o0, float4& o1) {
    float4 v0 = *(const float4*)(xr + c);
    float4 v1 = *(const float4*)(xr + c + 4);
    float s = v0.x+v0.y+v0.z+v0.w + v1.x+v1.y+v1.z+v1.w;
    #pragma unroll
    for (int o = 16; o; o >>= 1) s += __shfl_xor_sync(0xffffffffu, s, o);
    float mean = s * (1.f / Dn);

    float c0[8] = {v0.x-mean, v0.y-mean, v0.z-mean, v0.w-mean,
                   v1.x-mean, v1.y-mean, v1.z-mean, v1.w-mean};
    float sq = 0.f;
    #pragma unroll
    for (int i = 0; i < 8; i++) sq += c0[i]*c0[i];
    #pragma unroll
    for (int o = 16; o; o >>= 1) sq += __shfl_xor_sync(0xffffffffu, sq, o);
    float inv = 1.f / (sqrtf(sq * (1.f / (Dn - 1))) + 1e-6f);

    float4 a0 = *(const float4*)(a + c);
    float4 a1 = *(const float4*)(a + c + 4);
    float4 b0 = *(const float4*)(bb + c);
    float4 b1 = *(const float4*)(bb + c + 4);
    o0.x = a0.x*c0[0]*inv + b0.x;  o0.y = a0.y*c0[1]*inv + b0.y;
    o0.z = a0.z*c0[2]*inv + b0.z;  o0.w = a0.w*c0[3]*inv + b0.w;
    o1.x = a1.x*c0[4]*inv + b1.x;  o1.y = a1.y*c0[5]*inv + b1.y;
    o1.z = a1.z*c0[6]*inv + b1.z;  o1.w = a1.w*c0[7]*inv + b1.w;
}

__global__ void ln_f(const float* __restrict__ x, const float* __restrict__ a,
                     const float* __restrict__ bb, float* __restrict__ out) {
    const size_t row = (size_t)blockIdx.x * 8 + (threadIdx.x >> 5);
    const int c = (threadIdx.x & 31) * 8;
    float4 o0, o1;
    ln_core(x + row * Dn, a, bb, c, o0, o1);
    *(float4*)(out + row * Dn + c)     = o0;
    *(float4*)(out + row * Dn + c + 4) = o1;
}

__global__ void ln_h(const float* __restrict__ x, const float* __restrict__ a,
                     const float* __restrict__ bb, __half* __restrict__ out) {
    const size_t row = (size_t)blockIdx.x * 8 + (threadIdx.x >> 5);
    const int c = (threadIdx.x & 31) * 8;
    float4 o0, o1;
    ln_core(x + row * Dn, a, bb, c, o0, o1);
    *(uint4*)(out + row * Dn + c) = pack_h8(o0, o1);
}

// ---------------------------------------------------------------------------
// cp.async 3-stage GEMM, 128x128 block tile, BK=32, 8 warps (4x2), warp 32x64.
// Dynamic smem = 56832 bytes.
// ---------------------------------------------------------------------------
#define CA2_SMEM 56832

template<int CHALF>
__device__ __forceinline__ void gemm_body2(
    const half* __restrict__ A, const half* __restrict__ W,
    const float* __restrict__ bias, const float* __restrict__ res,
    void* __restrict__ Cv, int Nc, int K, int act, half* hs) {

    float* fst = (float*)hs;

    const int tm = blockIdx.y * 128;
    const int tn = blockIdx.x * 128;
    const int tid = threadIdx.x;
    const int warp = tid >> 5;
    const int lane = tid & 31;
    const int wm = warp >> 1;
    const int wn = warp & 1;

    const int ar0 = tid >> 2;
    const int ac0 = (tid & 3) * 8;
    const uint32_t sbase = (uint32_t)__cvta_generic_to_shared(hs);

    const half* gA0 = A + (size_t)(tm + ar0) * K + ac0;
    const half* gA1 = gA0 + (size_t)64 * K;

    wmma::fragment<wmma::accumulator, 16, 16, 16, float> acc[2][4];
    #pragma unroll
    for (int mm = 0; mm < 2; mm++)
        #pragma unroll
        for (int nn = 0; nn < 4; nn++)
            wmma::fill_fragment(acc[mm][nn], 0.f);

    const int nIter = K >> 5;

    #pragma unroll
    for (int p = 0; p < 2; p++) {
        int k0 = p * 32;
        cp16(sbase + (uint32_t)(p * 5120 + ar0 * 40 + ac0) * 2, gA0 + k0);
        cp16(sbase + (uint32_t)(p * 5120 + (ar0 + 64) * 40 + ac0) * 2, gA1 + k0);
        #pragma unroll
        for (int i = 0; i < 2; i++) {
            int idx = tid + i * 256;
            int r = idx >> 4, c = (idx & 15) * 8;
            cp16(sbase + (uint32_t)(15360 + p * 4352 + r * 136 + c) * 2,
                 W + (size_t)(k0 + r) * Nc + tn + c);
        }
        cp_commit();
    }

    int s = 0;
    for (int it = 0; it < nIter; it++) {
        if (it + 1 < nIter) cp_wait1(); else cp_wait0();
        __syncthreads();

        if (it + 2 < nIter) {
            int ps = (it + 2) % 3;
            int k0 = (it + 2) * 32;
            cp16(sbase + (uint32_t)(ps * 5120 + ar0 * 40 + ac0) * 2, gA0 + k0);
            cp16(sbase + (uint32_t)(ps * 5120 + (ar0 + 64) * 40 + ac0) * 2, gA1 + k0);
            #pragma unroll
            for (int i = 0; i < 2; i++) {
                int idx = tid + i * 256;
                int r = idx >> 4, c = (idx & 15) * 8;
                cp16(sbase + (uint32_t)(15360 + ps * 4352 + r * 136 + c) * 2,
                     W + (size_t)(k0 + r) * Nc + tn + c);
            }
            cp_commit();
        }

        const half* As = hs + s * 5120;
        const half* Bs = hs + 15360 + s * 4352;
        #pragma unroll
        for (int ks = 0; ks < 2; ks++) {
            wmma::fragment<wmma::matrix_a, 16, 16, 16, half, wmma::row_major> af[2];
            wmma::load_matrix_sync(af[0], As + (wm * 32)      * 40 + ks * 16, 40);
            wmma::load_matrix_sync(af[1], As + (wm * 32 + 16) * 40 + ks * 16, 40);
            #pragma unroll
            for (int nn = 0; nn < 4; nn++) {
                wmma::fragment<wmma::matrix_b, 16, 16, 16, half, wmma::row_major> bf;
                wmma::load_matrix_sync(bf, Bs + (ks * 16) * 136 + wn * 64 + nn * 16, 136);
                wmma::mma_sync(acc[0][nn], af[0], bf, acc[0][nn]);
                wmma::mma_sync(acc[1][nn], af[1], bf, acc[1][nn]);
            }
        }
        s = (s == 2) ? 0 : s + 1;
    }
    __syncthreads();

    float* stg = fst + warp * 16 * 68;
    const int gcolb = tn + wn * 64;
    #pragma unroll
    for (int mm = 0; mm < 2; mm++) {
        #pragma unroll
        for (int nn = 0; nn < 4; nn++)
            wmma::store_matrix_sync(stg + nn * 16, acc[mm][nn], 68, wmma::mem_row_major);
        __syncwarp();
        const int growb = tm + wm * 32 + mm * 16;
        #pragma unroll
        for (int it = 0; it < 8; it++) {
            int e = it * 32 + lane;
            int rr = e >> 4;
            int cc = (e & 15) * 4;
            int col = gcolb + cc;
            float4 v = *(float4*)(stg + rr * 68 + cc);
            if (bias) {
                float4 bb4 = *(const float4*)(bias + col);
                v.x += bb4.x; v.y += bb4.y; v.z += bb4.z; v.w += bb4.w;
            }
            if (act) {
                v.x = v.x > 0.f ? v.x : 0.1f * v.x;
                v.y = v.y > 0.f ? v.y : 0.1f * v.y;
                v.z = v.z > 0.f ? v.z : 0.1f * v.z;
                v.w = v.w > 0.f ? v.w : 0.1f * v.w;
            }
            size_t row = (size_t)(growb + rr);
            if (CHALF) {
                storeC4h((half*)Cv + row * Nc + col, v);
            } else {
                float* Cf = (float*)Cv;
                if (res) {
                    float4 r4 = *(const float4*)(res + row * Nc + col);
                    v.x += r4.x; v.y += r4.y; v.z += r4.z; v.w += r4.w;
                }
                *(float4*)(Cf + row * Nc + col) = v;
            }
        }
        __syncwarp();
    }
}

__global__ void __launch_bounds__(256, 2)
gemm_hh(const half* __restrict__ A, const half* __restrict__ W,
        const float* __restrict__ bias, half* __restrict__ C,
        int Nc, int K, int act) {
    extern __shared__ __align__(16) half dynsm[];
    gemm_body2<1>(A, W, bias, nullptr, C, Nc, K, act, dynsm);
}

__global__ void __launch_bounds__(256, 2)
gemm_hf(const half* __restrict__ A, const half* __restrict__ W,
        const float* __restrict__ bias, const float* __restrict__ res,
        float* __restrict__ C, int Nc, int K, int act) {
    extern __shared__ __align__(16) half dynsm[];
    gemm_body2<0>(A, W, bias, res, C, Nc, K, act, dynsm);
}

__global__ void __launch_bounds__(256, 2)
gemm_hhz(const half* __restrict__ A, const half* __restrict__ W,
         half* __restrict__ C, int Nc, int K,
         long sA, long sW, long sC) {
    extern __shared__ __align__(16) half dynsm[];
    gemm_body2<1>(A + (size_t)blockIdx.z * sA, W + (size_t)blockIdx.z * sW,
                  nullptr, nullptr, C + (size_t)blockIdx.z * sC, Nc, K, 0, dynsm);
}

__global__ void __launch_bounds__(256, 2)
gemm_qkv(const half* __restrict__ A, const half* __restrict__ Wh,
         long wStride,
         const float* __restrict__ b0, const float* __restrict__ b1,
         const float* __restrict__ b2,
         half* __restrict__ C0, half* __restrict__ C1, half* __restrict__ C2,
         int Nc, int K) {
    extern __shared__ __align__(16) half dynsm[];
    const half* W = Wh + (size_t)blockIdx.z * wStride;
    const float* bb = (blockIdx.z == 0) ? b0 : (blockIdx.z == 1) ? b1 : b2;
    half* C = (blockIdx.z == 0) ? C0 : (blockIdx.z == 1) ? C1 : C2;
    gemm_body2<1>(A, W, bb, nullptr, C, Nc, K, 0, dynsm);
}

// ---------------------------------------------------------------------------
// Mask-compacted FP16 flash attention: only valid key columns are processed.
// att(half) += 0.3 * softmax @ V over gathered KV tiles; count from g_cnt.
// ---------------------------------------------------------------------------
#define ALQH 40
#define ALP  68
#define ALPH 72

__global__ void __launch_bounds__(128)
attn_tc(const __half* __restrict__ q,
        const __half* __restrict__ k,
        const __half* __restrict__ v,
        const int*    __restrict__ idxs,
        const int*    __restrict__ cnts,
        __half* __restrict__ att) {
    __shared__ __align__(16) half  Qs[64][ALQH];
    __shared__ __align__(16) half  Ks[64][ALQH];
    __shared__ __align__(16) half  Vs[64][ALQH];
    __shared__ __align__(16) float Ps[4][16][ALP];
    __shared__ __align__(16) half  Ph[4][16][ALPH];

    const int b = blockIdx.z, h = blockIdx.y;
    const int tid = threadIdx.x;
    const int warp = tid >> 5;
    const int lane = tid & 31;
    const int qrow0 = blockIdx.x * 64;
    const float scale = 0.17677669529663687f;

    const int count = cnts[b];
    const int nTiles = (count + 63) >> 6;

    {
        int r = tid >> 1, c = (tid & 1) * 16;
        const __half* src = q + ((size_t)(b * Nn + qrow0 + r)) * Dn + h * DKn + c;
        *(uint4*)&Qs[r][c]     = *(const uint4*)(src);
        *(uint4*)&Qs[r][c + 8] = *(const uint4*)(src + 8);
    }

    wmma::fragment<wmma::accumulator, 16, 16, 16, float> ao[2];
    wmma::fill_fragment(ao[0], 0.f);
    wmma::fill_fragment(ao[1], 0.f);

    float l_tot = 0.f;
    const int myrow = lane >> 1;
    const int colh = (lane & 1) * 32;

    for (int kt = 0; kt < nTiles; kt++) {
        __syncthreads();
        {
            int r = tid >> 1, c = (tid & 1) * 16;
            int g = kt * 64 + r;
            int col = (g < count) ? idxs[b * Nn + g] : 0;
            size_t off = ((size_t)(b * Nn + col)) * Dn + h * DKn + c;
            *(uint4*)&Ks[r][c]     = *(const uint4*)(k + off);
            *(uint4*)&Ks[r][c + 8] = *(const uint4*)(k + off + 8);
            *(uint4*)&Vs[r][c]     = *(const uint4*)(v + off);
            *(uint4*)&Vs[r][c + 8] = *(const uint4*)(v + off + 8);
        }
        __syncthreads();

        wmma::fragment<wmma::accumulator, 16, 16, 16, float> sf[4];
        #pragma unroll
        for (int n = 0; n < 4; n++) wmma::fill_fragment(sf[n], 0.f);
        #pragma unroll
        for (int ks = 0; ks < 2; ks++) {
            wmma::fragment<wmma::matrix_a, 16, 16, 16, half, wmma::row_major> af;
            wmma::load_matrix_sync(af, &Qs[warp * 16][ks * 16], ALQH);
            #pragma unroll
            for (int n = 0; n < 4; n++) {
                wmma::fragment<wmma::matrix_b, 16, 16, 16, half, wmma::col_major> bf;
                wmma::load_matrix_sync(bf, &Ks[n * 16][ks * 16], ALQH);
                wmma::mma_sync(sf[n], af, bf, sf[n]);
            }
        }
        #pragma unroll
        for (int n = 0; n < 4; n++)
            wmma::store_matrix_sync(&Ps[warp][0][n * 16], sf[n], ALP, wmma::mem_row_major);
        __syncwarp();

        float lp = 0.f;
        const float* srow = &Ps[warp][myrow][colh];
        half* prow = &Ph[warp][myrow][colh];
        const int jbase = kt * 64 + colh;
        const int nvalid = count - jbase;   // p=0 for j >= nvalid
        #pragma unroll
        for (int j = 0; j < 32; j += 2) {
            float p0 = (j     < nvalid) ? __expf(srow[j]     * scale) : 0.f;
            float p1 = (j + 1 < nvalid) ? __expf(srow[j + 1] * scale) : 0.f;
            lp += p0 + p1;
            *(half2*)(prow + j) = __floats2half2_rn(p0, p1);
        }
        lp += __shfl_xor_sync(0xffffffffu, lp, 1);
        l_tot += lp;
        __syncwarp();

        #pragma unroll
        for (int ks = 0; ks < 4; ks++) {
            wmma::fragment<wmma::matrix_a, 16, 16, 16, half, wmma::row_major> af;
            wmma::load_matrix_sync(af, &Ph[warp][0][ks * 16], ALPH);
            #pragma unroll
            for (int n = 0; n < 2; n++) {
                wmma::fragment<wmma::matrix_b, 16, 16, 16, half, wmma::row_major> bf;
                wmma::load_matrix_sync(bf, &Vs[ks * 16][n * 16], ALQH);
                wmma::mma_sync(ao[n], af, bf, ao[n]);
            }
        }
    }

    float* Os = &Ps[warp][0][0];
    wmma::store_matrix_sync(Os,      ao[0], ALP, wmma::mem_row_major);
    wmma::store_matrix_sync(Os + 16, ao[1], ALP, wmma::mem_row_major);
    __syncwarp();

    const float inv = 0.3f / l_tot;
    const int ch = (lane & 1) * 16;
    __half* orow = att + ((size_t)(b * Nn + qrow0 + warp * 16 + myrow)) * Dn + h * DKn + ch;
    float* sro = Os + myrow * ALP + ch;
    #pragma unroll
    for (int c = 0; c < 8; c++) {
        half2 o2 = *(half2*)(orow + c * 2);
        float2 of = __half22float2(o2);
        of.x += sro[c * 2]     * inv;
        of.y += sro[c * 2 + 1] * inv;
        *(half2*)(orow + c * 2) = __floats2half2_rn(of.x, of.y);
    }
}

// ---------------------------------------------------------------------------
// Launch
// ---------------------------------------------------------------------------
extern "C" void kernel_launch(void* const* d_in, const int* in_sizes, int n_in,
                              void* d_out, int out_size) {
    const float* x_in  = (const float*)d_in[0];
    const int*   mask  = (const int*)  d_in[1];
    const float* adj   = (const float*)d_in[2];
    const float* dist  = (const float*)d_in[3];
    const float* Wq    = (const float*)d_in[5];
    const float* bq    = (const float*)d_in[6];
    const float* Wk    = (const float*)d_in[7];
    const float* bk    = (const float*)d_in[8];
    const float* Wv    = (const float*)d_in[9];
    const float* bv    = (const float*)d_in[10];
    const float* Wo    = (const float*)d_in[11];
    const float* bo    = (const float*)d_in[12];
    const float* Wf1   = (const float*)d_in[13];
    const float* bf1   = (const float*)d_in[14];
    const float* Wf2   = (const float*)d_in[15];
    const float* bf2   = (const float*)d_in[16];
    const float* ln1a  = (const float*)d_in[17];
    const float* ln1b  = (const float*)d_in[18];
    const float* ln2a  = (const float*)d_in[19];
    const float* ln2b  = (const float*)d_in[20];
    const float* lnfa  = (const float*)d_in[21];
    const float* lnfb  = (const float*)d_in[22];

    float *px;
    __half *pbaseh, *phh, *pqh, *pkh, *pvh, *pt1, *pph, *pwh;
    int *pidx, *pcnt;
    cudaGetSymbolAddress((void**)&px,     g_x);
    cudaGetSymbolAddress((void**)&pbaseh, g_baseh);
    cudaGetSymbolAddress((void**)&phh,    g_hh);
    cudaGetSymbolAddress((void**)&pqh,    g_qh);
    cudaGetSymbolAddress((void**)&pkh,    g_kh);
    cudaGetSymbolAddress((void**)&pvh,    g_vh);
    cudaGetSymbolAddress((void**)&pt1,    g_t1);
    cudaGetSymbolAddress((void**)&pph,    g_ph);
    cudaGetSymbolAddress((void**)&pwh,    g_wh);
    cudaGetSymbolAddress((void**)&pidx,   g_idx);
    cudaGetSymbolAddress((void**)&pcnt,   g_cnt);

    static bool attrDone = false;
    if (!attrDone) {
        cudaFuncSetAttribute(gemm_hh,  cudaFuncAttributeMaxDynamicSharedMemorySize, CA2_SMEM);
        cudaFuncSetAttribute(gemm_hf,  cudaFuncAttributeMaxDynamicSharedMemorySize, CA2_SMEM);
        cudaFuncSetAttribute(gemm_hhz, cudaFuncAttributeMaxDynamicSharedMemorySize, CA2_SMEM);
        cudaFuncSetAttribute(gemm_qkv, cudaFuncAttributeMaxDynamicSharedMemorySize, CA2_SMEM);
        attrDone = true;
    }

    cudaMemcpyAsync(px, x_in, sizeof(float) * BND, cudaMemcpyDeviceToDevice, 0);

    cvt_w<<<(6 * WSZ) / 1024, 256>>>(Wq, Wk, Wv, Wo, Wf1, Wf2, pwh);
    base_kernel<<<Bn * Nn, 256>>>(dist, adj, mask, pbaseh);
    mask_idx_kernel<<<Bn, 512>>>(mask, pidx, pcnt);

    const dim3 gProj(Dn / 128, (Bn * Nn) / 128, 1);   // 128 blocks
    const dim3 gQKV (Dn / 128, (Bn * Nn) / 128, 3);   // 384 blocks
    const dim3 gBaseV(Dn / 128, Nn / 128, Bn);        // 128 blocks
    const dim3 gAttn(Nn / 64, Hn, Bn);                // 1024 blocks
    const dim3 gLN(Bn * Nn / 8, 1, 1);

    for (int i = 0; i < Ln; i++) {
        const size_t wOff = (size_t)i * Dn * Dn;
        const size_t vOff = (size_t)i * Dn;

        ln_h<<<gLN, 256>>>(px, ln1a + vOff, ln1b + vOff, phh);

        gemm_qkv<<<gQKV, 256, CA2_SMEM>>>(phh, pwh + wOff, (long)WSZ,
                                          bq + vOff, bk + vOff, bv + vOff,
                                          pqh, pkh, pvh, Dn, Dn);

        // att = base @ V  (half, K=512)
        gemm_hhz<<<gBaseV, 256, CA2_SMEM>>>(pbaseh, pvh, pph, Dn, Nn,
                                            (long)Nn * Nn, (long)Nn * Dn, (long)Nn * Dn);

        // att += 0.3 * softmax @ V  (mask-compacted KV tiles)
        attn_tc<<<gAttn, 128>>>(pqh, pkh, pvh, pidx, pcnt, pph);

        // x = x + att @ Wo + bo
        gemm_hf<<<gProj, 256, CA2_SMEM>>>(pph, pwh + 3 * WSZ + wOff, bo + vOff, px, px,
                                          Dn, Dn, 0);

        // FFN
        ln_h<<<gLN, 256>>>(px, ln2a + vOff, ln2b + vOff, phh);
        gemm_hh<<<gProj, 256, CA2_SMEM>>>(phh, pwh + 4 * WSZ + wOff, bf1 + vOff, pt1,
                                          Dn, Dn, 1);
        gemm_hf<<<gProj, 256, CA2_SMEM>>>(pt1, pwh + 5 * WSZ + wOff, bf2 + vOff, px, px,
                                          Dn, Dn, 1);
    }

    ln_f<<<gLN, 256>>>(px, lnfa, lnfb, (float*)d_out);
}

// round 14
// speedup vs baseline: 4.7808x; 1.0029x over previous
#include <cuda_runtime.h>
#include <cuda_fp16.h>
#include <math.h>
#include <mma.h>
#include <stdint.h>

using namespace nvcuda;

// Problem constants
#define Bn 16
#define Nn 512
#define Dn 256
#define Hn 8
#define Ln 4
#define DKn 32

#define BND (Bn*Nn*Dn)   // 2,097,152
#define BNN (Bn*Nn*Nn)   // 4,194,304
#define WSZ (Ln*Dn*Dn)   // 262,144 per weight set

static __device__ float  g_x[BND];
static __device__ __half g_baseh[BNN];
static __device__ __half g_hh[BND];
static __device__ __half g_qh[BND];
static __device__ __half g_kh[BND];
static __device__ __half g_vh[BND];
static __device__ __half g_t1[BND];
static __device__ __half g_ph[BND];      // attention output (half)
static __device__ __half g_wh[6 * WSZ];
static __device__ int    g_idx[Bn * Nn]; // compacted valid-column indices
static __device__ int    g_cnt[Bn];      // valid counts per batch

// ---------------------------------------------------------------------------
// helpers
// ---------------------------------------------------------------------------
__device__ __forceinline__ uint4 pack_h8(float4 a, float4 b) {
    half2 h0 = __floats2half2_rn(a.x, a.y);
    half2 h1 = __floats2half2_rn(a.z, a.w);
    half2 h2 = __floats2half2_rn(b.x, b.y);
    half2 h3 = __floats2half2_rn(b.z, b.w);
    uint4 r;
    r.x = *(unsigned*)&h0; r.y = *(unsigned*)&h1;
    r.z = *(unsigned*)&h2; r.w = *(unsigned*)&h3;
    return r;
}

__device__ __forceinline__ void storeC4h(half* p, float4 v) {
    half2 a = __floats2half2_rn(v.x, v.y);
    half2 b = __floats2half2_rn(v.z, v.w);
    uint2 u; u.x = *(unsigned*)&a; u.y = *(unsigned*)&b;
    *(uint2*)p = u;
}

// cp.async primitives
__device__ __forceinline__ void cp16(uint32_t s, const void* g) {
    asm volatile("cp.async.cg.shared.global [%0], [%1], 16;" :: "r"(s), "l"(g));
}
__device__ __forceinline__ void cp_commit() {
    asm volatile("cp.async.commit_group;" ::: "memory");
}
__device__ __forceinline__ void cp_wait1() {
    asm volatile("cp.async.wait_group 1;" ::: "memory");
}
__device__ __forceinline__ void cp_wait0() {
    asm volatile("cp.async.wait_group 0;" ::: "memory");
}

// ---------------------------------------------------------------------------
// weight conversion fp32 -> fp16
// ---------------------------------------------------------------------------
__global__ void cvt_w(const float* __restrict__ Wq, const float* __restrict__ Wk,
                      const float* __restrict__ Wv, const float* __restrict__ Wo,
                      const float* __restrict__ Wf1, const float* __restrict__ Wf2,
                      __half* __restrict__ out) {
    const int idx = (blockIdx.x * 256 + threadIdx.x) * 4;
    const int w = idx / WSZ;
    const int r = idx - w * WSZ;
    const float* srcs[6] = {Wq, Wk, Wv, Wo, Wf1, Wf2};
    float4 v = *(const float4*)(srcs[w] + r);
    half2 a = __floats2half2_rn(v.x, v.y);
    half2 b = __floats2half2_rn(v.z, v.w);
    uint2 u; u.x = *(unsigned*)&a; u.y = *(unsigned*)&b;
    *(uint2*)(out + idx) = u;
}

// ---------------------------------------------------------------------------
// mask compaction: per batch, idx[] = ascending valid columns, cnt = count
// ---------------------------------------------------------------------------
__global__ void mask_idx_kernel(const int* __restrict__ mask,
                                int* __restrict__ idx, int* __restrict__ cnt) {
    __shared__ int sc[512];
    const int b = blockIdx.x, t = threadIdx.x;
    const int m = (mask[b * Nn + t] != 0) ? 1 : 0;
    sc[t] = m;
    __syncthreads();
    for (int o = 1; o < 512; o <<= 1) {
        int v = (t >= o) ? sc[t - o] : 0;
        __syncthreads();
        sc[t] += v;
        __syncthreads();
    }
    if (m) idx[b * Nn + sc[t] - 1] = t;
    if (t == 511) cnt[b] = sc[511];
}

// ---------------------------------------------------------------------------
// block reductions (256 threads)
// ---------------------------------------------------------------------------
__device__ __forceinline__ float blockSum256(float v) {
    __shared__ float sm[8];
    __syncthreads();
    #pragma unroll
    for (int o = 16; o; o >>= 1) v += __shfl_xor_sync(0xffffffffu, v, o);
    if ((threadIdx.x & 31) == 0) sm[threadIdx.x >> 5] = v;
    __syncthreads();
    float t = 0.f;
    #pragma unroll
    for (int i = 0; i < 8; i++) t += sm[i];
    return t;
}

__device__ __forceinline__ float blockMax256(float v) {
    __shared__ float sm[8];
    __syncthreads();
    #pragma unroll
    for (int o = 16; o; o >>= 1) v = fmaxf(v, __shfl_xor_sync(0xffffffffu, v, o));
    if ((threadIdx.x & 31) == 0) sm[threadIdx.x >> 5] = v;
    __syncthreads();
    float t = sm[0];
    #pragma unroll
    for (int i = 1; i < 8; i++) t = fmaxf(t, sm[i]);
    return t;
}

// ---------------------------------------------------------------------------
// base (half output)
// ---------------------------------------------------------------------------
__global__ void base_kernel(const float* __restrict__ dist,
                            const float* __restrict__ adj,
                            const int*   __restrict__ mask,
                            __half* __restrict__ base) {
    const int bi = blockIdx.x;
    const int b  = bi >> 9;
    const float* dr = dist + (size_t)bi * Nn;
    const float* ar = adj  + (size_t)bi * Nn;
    __half*      br = base + (size_t)bi * Nn;
    const int t = threadIdx.x;

    const int m0 = mask[b * Nn + t];
    const int m1 = mask[b * Nn + t + 256];
    float v0 = m0 ? -dr[t]       : -INFINITY;
    float v1 = m1 ? -dr[t + 256] : -INFINITY;

    float mx = blockMax256(fmaxf(v0, v1));
    float e0 = __expf(v0 - mx);
    float e1 = __expf(v1 - mx);
    float ssum = blockSum256(e0 + e1);

    float a0 = ar[t], a1 = ar[t + 256];
    float asum = blockSum256(a0 + a1);

    float cs = 0.3f / ssum;
    float ca = 0.4f / (asum + 1e-6f);
    br[t]       = __float2half_rn(e0 * cs + a0 * ca);
    br[t + 256] = __float2half_rn(e1 * cs + a1 * ca);
}

// ---------------------------------------------------------------------------
// LayerNorm (ddof=1), warp per row
// ---------------------------------------------------------------------------
__device__ __forceinline__ void ln_core(const float* __restrict__ xr,
                                        const float* __restrict__ a,
                                        const float* __restrict__ bb,
                                        int c, float4& o0, float4& o1) {
    float4 v0 = *(const float4*)(xr + c);
    float4 v1 = *(const float4*)(xr + c + 4);
    float s = v0.x+v0.y+v0.z+v0.w + v1.x+v1.y+v1.z+v1.w;
    #pragma unroll
    for (int o = 16; o; o >>= 1) s += __shfl_xor_sync(0xffffffffu, s, o);
    float mean = s * (1.f / Dn);

    float c0[8] = {v0.x-mean, v0.y-mean, v0.z-mean, v0.w-mean,
                   v1.x-mean, v1.y-mean, v1.z-mean, v1.w-mean};
    float sq = 0.f;
    #pragma unroll
    for (int i = 0; i < 8; i++) sq += c0[i]*c0[i];
    #pragma unroll
    for (int o = 16; o; o >>= 1) sq += __shfl_xor_sync(0xffffffffu, sq, o);
    float inv = 1.f / (sqrtf(sq * (1.f / (Dn - 1))) + 1e-6f);

    float4 a0 = *(const float4*)(a + c);
    float4 a1 = *(const float4*)(a + c + 4);
    float4 b0 = *(const float4*)(bb + c);
    float4 b1 = *(const float4*)(bb + c + 4);
    o0.x = a0.x*c0[0]*inv + b0.x;  o0.y = a0.y*c0[1]*inv + b0.y;
    o0.z = a0.z*c0[2]*inv + b0.z;  o0.w = a0.w*c0[3]*inv + b0.w;
    o1.x = a1.x*c0[4]*inv + b1.x;  o1.y = a1.y*c0[5]*inv + b1.y;
    o1.z = a1.z*c0[6]*inv + b1.z;  o1.w = a1.w*c0[7]*inv + b1.w;
}

__global__ void ln_f(const float* __restrict__ x, const float* __restrict__ a,
                     const float* __restrict__ bb, float* __restrict__ out) {
    const size_t row = (size_t)blockIdx.x * 8 + (threadIdx.x >> 5);
    const int c = (threadIdx.x & 31) * 8;
    float4 o0, o1;
    ln_core(x + row * Dn, a, bb, c, o0, o1);
    *(float4*)(out + row * Dn + c)     = o0;
    *(float4*)(out + row * Dn + c + 4) = o1;
}

__global__ void ln_h(const float* __restrict__ x, const float* __restrict__ a,
                     const float* __restrict__ bb, __half* __restrict__ out) {
    const size_t row = (size_t)blockIdx.x * 8 + (threadIdx.x >> 5);
    const int c = (threadIdx.x & 31) * 8;
    float4 o0, o1;
    ln_core(x + row * Dn, a, bb, c, o0, o1);
    *(uint4*)(out + row * Dn + c) = pack_h8(o0, o1);
}

// ---------------------------------------------------------------------------
// cp.async 3-stage GEMM, 128x128 block tile, BK=32, 8 warps (4x2), warp 32x64.
// Dynamic smem = 56832 bytes.
// ---------------------------------------------------------------------------
#define CA2_SMEM 56832

template<int CHALF>
__device__ __forceinline__ void gemm_body2(
    const half* __restrict__ A, const half* __restrict__ W,
    const float* __restrict__ bias, const float* __restrict__ res,
    void* __restrict__ Cv, int Nc, int K, int act, half* hs) {

    float* fst = (float*)hs;

    const int tm = blockIdx.y * 128;
    const int tn = blockIdx.x * 128;
    const int tid = threadIdx.x;
    const int warp = tid >> 5;
    const int lane = tid & 31;
    const int wm = warp >> 1;
    const int wn = warp & 1;

    const int ar0 = tid >> 2;
    const int ac0 = (tid & 3) * 8;
    const uint32_t sbase = (uint32_t)__cvta_generic_to_shared(hs);

    const half* gA0 = A + (size_t)(tm + ar0) * K + ac0;
    const half* gA1 = gA0 + (size_t)64 * K;

    wmma::fragment<wmma::accumulator, 16, 16, 16, float> acc[2][4];
    #pragma unroll
    for (int mm = 0; mm < 2; mm++)
        #pragma unroll
        for (int nn = 0; nn < 4; nn++)
            wmma::fill_fragment(acc[mm][nn], 0.f);

    const int nIter = K >> 5;

    #pragma unroll
    for (int p = 0; p < 2; p++) {
        int k0 = p * 32;
        cp16(sbase + (uint32_t)(p * 5120 + ar0 * 40 + ac0) * 2, gA0 + k0);
        cp16(sbase + (uint32_t)(p * 5120 + (ar0 + 64) * 40 + ac0) * 2, gA1 + k0);
        #pragma unroll
        for (int i = 0; i < 2; i++) {
            int idx = tid + i * 256;
            int r = idx >> 4, c = (idx & 15) * 8;
            cp16(sbase + (uint32_t)(15360 + p * 4352 + r * 136 + c) * 2,
                 W + (size_t)(k0 + r) * Nc + tn + c);
        }
        cp_commit();
    }

    int s = 0;
    for (int it = 0; it < nIter; it++) {
        if (it + 1 < nIter) cp_wait1(); else cp_wait0();
        __syncthreads();

        if (it + 2 < nIter) {
            int ps = (it + 2) % 3;
            int k0 = (it + 2) * 32;
            cp16(sbase + (uint32_t)(ps * 5120 + ar0 * 40 + ac0) * 2, gA0 + k0);
            cp16(sbase + (uint32_t)(ps * 5120 + (ar0 + 64) * 40 + ac0) * 2, gA1 + k0);
            #pragma unroll
            for (int i = 0; i < 2; i++) {
                int idx = tid + i * 256;
                int r = idx >> 4, c = (idx & 15) * 8;
                cp16(sbase + (uint32_t)(15360 + ps * 4352 + r * 136 + c) * 2,
                     W + (size_t)(k0 + r) * Nc + tn + c);
            }
            cp_commit();
        }

        const half* As = hs + s * 5120;
        const half* Bs = hs + 15360 + s * 4352;
        #pragma unroll
        for (int ks = 0; ks < 2; ks++) {
            wmma::fragment<wmma::matrix_a, 16, 16, 16, half, wmma::row_major> af[2];
            wmma::load_matrix_sync(af[0], As + (wm * 32)      * 40 + ks * 16, 40);
            wmma::load_matrix_sync(af[1], As + (wm * 32 + 16) * 40 + ks * 16, 40);
            #pragma unroll
            for (int nn = 0; nn < 4; nn++) {
                wmma::fragment<wmma::matrix_b, 16, 16, 16, half, wmma::row_major> bf;
                wmma::load_matrix_sync(bf, Bs + (ks * 16) * 136 + wn * 64 + nn * 16, 136);
                wmma::mma_sync(acc[0][nn], af[0], bf, acc[0][nn]);
                wmma::mma_sync(acc[1][nn], af[1], bf, acc[1][nn]);
            }
        }
        s = (s == 2) ? 0 : s + 1;
    }
    __syncthreads();

    float* stg = fst + warp * 16 * 68;
    const int gcolb = tn + wn * 64;
    #pragma unroll
    for (int mm = 0; mm < 2; mm++) {
        #pragma unroll
        for (int nn = 0; nn < 4; nn++)
            wmma::store_matrix_sync(stg + nn * 16, acc[mm][nn], 68, wmma::mem_row_major);
        __syncwarp();
        const int growb = tm + wm * 32 + mm * 16;
        #pragma unroll
        for (int it = 0; it < 8; it++) {
            int e = it * 32 + lane;
            int rr = e >> 4;
            int cc = (e & 15) * 4;
            int col = gcolb + cc;
            float4 v = *(float4*)(stg + rr * 68 + cc);
            if (bias) {
                float4 bb4 = *(const float4*)(bias + col);
                v.x += bb4.x; v.y += bb4.y; v.z += bb4.z; v.w += bb4.w;
            }
            if (act) {
                v.x = v.x > 0.f ? v.x : 0.1f * v.x;
                v.y = v.y > 0.f ? v.y : 0.1f * v.y;
                v.z = v.z > 0.f ? v.z : 0.1f * v.z;
                v.w = v.w > 0.f ? v.w : 0.1f * v.w;
            }
            size_t row = (size_t)(growb + rr);
            if (CHALF) {
                storeC4h((half*)Cv + row * Nc + col, v);
            } else {
                float* Cf = (float*)Cv;
                if (res) {
                    float4 r4 = *(const float4*)(res + row * Nc + col);
                    v.x += r4.x; v.y += r4.y; v.z += r4.z; v.w += r4.w;
                }
                *(float4*)(Cf + row * Nc + col) = v;
            }
        }
        __syncwarp();
    }
}

__global__ void __launch_bounds__(256, 2)
gemm_hh(const half* __restrict__ A, const half* __restrict__ W,
        const float* __restrict__ bias, half* __restrict__ C,
        int Nc, int K, int act) {
    extern __shared__ __align__(16) half dynsm[];
    gemm_body2<1>(A, W, bias, nullptr, C, Nc, K, act, dynsm);
}

__global__ void __launch_bounds__(256, 2)
gemm_hf(const half* __restrict__ A, const half* __restrict__ W,
        const float* __restrict__ bias, const float* __restrict__ res,
        float* __restrict__ C, int Nc, int K, int act) {
    extern __shared__ __align__(16) half dynsm[];
    gemm_body2<0>(A, W, bias, res, C, Nc, K, act, dynsm);
}

__global__ void __launch_bounds__(256, 2)
gemm_hhz(const half* __restrict__ A, const half* __restrict__ W,
         half* __restrict__ C, int Nc, int K,
         long sA, long sW, long sC) {
    extern __shared__ __align__(16) half dynsm[];
    gemm_body2<1>(A + (size_t)blockIdx.z * sA, W + (size_t)blockIdx.z * sW,
                  nullptr, nullptr, C + (size_t)blockIdx.z * sC, Nc, K, 0, dynsm);
}

__global__ void __launch_bounds__(256, 2)
gemm_qkv(const half* __restrict__ A, const half* __restrict__ Wh,
         long wStride,
         const float* __restrict__ b0, const float* __restrict__ b1,
         const float* __restrict__ b2,
         half* __restrict__ C0, half* __restrict__ C1, half* __restrict__ C2,
         int Nc, int K) {
    extern __shared__ __align__(16) half dynsm[];
    const half* W = Wh + (size_t)blockIdx.z * wStride;
    const float* bb = (blockIdx.z == 0) ? b0 : (blockIdx.z == 1) ? b1 : b2;
    half* C = (blockIdx.z == 0) ? C0 : (blockIdx.z == 1) ? C1 : C2;
    gemm_body2<1>(A, W, bb, nullptr, C, Nc, K, 0, dynsm);
}

// ---------------------------------------------------------------------------
// Mask-compacted FP16 flash attention with f16x2 exp (half the MUFU ops).
// att(half) += 0.3 * softmax @ V over gathered KV tiles; count from g_cnt.
// ---------------------------------------------------------------------------
#define ALQH 40
#define ALP  68
#define ALPH 72

__global__ void __launch_bounds__(128)
attn_tc(const __half* __restrict__ q,
        const __half* __restrict__ k,
        const __half* __restrict__ v,
        const int*    __restrict__ idxs,
        const int*    __restrict__ cnts,
        __half* __restrict__ att) {
    __shared__ __align__(16) half  Qs[64][ALQH];
    __shared__ __align__(16) half  Ks[64][ALQH];
    __shared__ __align__(16) half  Vs[64][ALQH];
    __shared__ __align__(16) float Ps[4][16][ALP];
    __shared__ __align__(16) half  Ph[4][16][ALPH];

    const int b = blockIdx.z, h = blockIdx.y;
    const int tid = threadIdx.x;
    const int warp = tid >> 5;
    const int lane = tid & 31;
    const int qrow0 = blockIdx.x * 64;
    // scale * log2(e): exp(s*scale) = 2^(s * sc2)
    const float sc2 = 0.17677669529663687f * 1.4426950408889634f;

    const int count = cnts[b];
    const int nTiles = (count + 63) >> 6;

    {
        int r = tid >> 1, c = (tid & 1) * 16;
        const __half* src = q + ((size_t)(b * Nn + qrow0 + r)) * Dn + h * DKn + c;
        *(uint4*)&Qs[r][c]     = *(const uint4*)(src);
        *(uint4*)&Qs[r][c + 8] = *(const uint4*)(src + 8);
    }

    wmma::fragment<wmma::accumulator, 16, 16, 16, float> ao[2];
    wmma::fill_fragment(ao[0], 0.f);
    wmma::fill_fragment(ao[1], 0.f);

    float l_tot = 0.f;
    const int myrow = lane >> 1;
    const int colh = (lane & 1) * 32;

    for (int kt = 0; kt < nTiles; kt++) {
        __syncthreads();
        {
            int r = tid >> 1, c = (tid & 1) * 16;
            int g = kt * 64 + r;
            int col = (g < count) ? idxs[b * Nn + g] : 0;
            size_t off = ((size_t)(b * Nn + col)) * Dn + h * DKn + c;
            *(uint4*)&Ks[r][c]     = *(const uint4*)(k + off);
            *(uint4*)&Ks[r][c + 8] = *(const uint4*)(k + off + 8);
            *(uint4*)&Vs[r][c]     = *(const uint4*)(v + off);
            *(uint4*)&Vs[r][c + 8] = *(const uint4*)(v + off + 8);
        }
        __syncthreads();

        wmma::fragment<wmma::accumulator, 16, 16, 16, float> sf[4];
        #pragma unroll
        for (int n = 0; n < 4; n++) wmma::fill_fragment(sf[n], 0.f);
        #pragma unroll
        for (int ks = 0; ks < 2; ks++) {
            wmma::fragment<wmma::matrix_a, 16, 16, 16, half, wmma::row_major> af;
            wmma::load_matrix_sync(af, &Qs[warp * 16][ks * 16], ALQH);
            #pragma unroll
            for (int n = 0; n < 4; n++) {
                wmma::fragment<wmma::matrix_b, 16, 16, 16, half, wmma::col_major> bf;
                wmma::load_matrix_sync(bf, &Ks[n * 16][ks * 16], ALQH);
                wmma::mma_sync(sf[n], af, bf, sf[n]);
            }
        }
        #pragma unroll
        for (int n = 0; n < 4; n++)
            wmma::store_matrix_sync(&Ps[warp][0][n * 16], sf[n], ALP, wmma::mem_row_major);
        __syncwarp();

        // p = 2^(s*sc2) via f16x2 MUFU; invalid columns get arg -1e4 -> p = 0
        float lp = 0.f;
        const float* srow = &Ps[warp][myrow][colh];
        half* prow = &Ph[warp][myrow][colh];
        const int jbase = kt * 64 + colh;
        const int nvalid = count - jbase;
        #pragma unroll
        for (int j = 0; j < 32; j += 2) {
            float a0 = (j     < nvalid) ? srow[j]     * sc2 : -1e4f;
            float a1 = (j + 1 < nvalid) ? srow[j + 1] * sc2 : -1e4f;
            half2 p2 = h2exp2(__floats2half2_rn(a0, a1));
            *(half2*)(prow + j) = p2;
            float2 pf = __half22float2(p2);
            lp += pf.x + pf.y;
        }
        lp += __shfl_xor_sync(0xffffffffu, lp, 1);
        l_tot += lp;
        __syncwarp();

        #pragma unroll
        for (int ks = 0; ks < 4; ks++) {
            wmma::fragment<wmma::matrix_a, 16, 16, 16, half, wmma::row_major> af;
            wmma::load_matrix_sync(af, &Ph[warp][0][ks * 16], ALPH);
            #pragma unroll
            for (int n = 0; n < 2; n++) {
                wmma::fragment<wmma::matrix_b, 16, 16, 16, half, wmma::row_major> bf;
                wmma::load_matrix_sync(bf, &Vs[ks * 16][n * 16], ALQH);
                wmma::mma_sync(ao[n], af, bf, ao[n]);
            }
        }
    }

    float* Os = &Ps[warp][0][0];
    wmma::store_matrix_sync(Os,      ao[0], ALP, wmma::mem_row_major);
    wmma::store_matrix_sync(Os + 16, ao[1], ALP, wmma::mem_row_major);
    __syncwarp();

    const float inv = 0.3f / l_tot;
    const int ch = (lane & 1) * 16;
    __half* orow = att + ((size_t)(b * Nn + qrow0 + warp * 16 + myrow)) * Dn + h * DKn + ch;
    float* sro = Os + myrow * ALP + ch;
    #pragma unroll
    for (int c = 0; c < 8; c++) {
        half2 o2 = *(half2*)(orow + c * 2);
        float2 of = __half22float2(o2);
        of.x += sro[c * 2]     * inv;
        of.y += sro[c * 2 + 1] * inv;
        *(half2*)(orow + c * 2) = __floats2half2_rn(of.x, of.y);
    }
}

// ---------------------------------------------------------------------------
// Launch
// ---------------------------------------------------------------------------
extern "C" void kernel_launch(void* const* d_in, const int* in_sizes, int n_in,
                              void* d_out, int out_size) {
    const float* x_in  = (const float*)d_in[0];
    const int*   mask  = (const int*)  d_in[1];
    const float* adj   = (const float*)d_in[2];
    const float* dist  = (const float*)d_in[3];
    const float* Wq    = (const float*)d_in[5];
    const float* bq    = (const float*)d_in[6];
    const float* Wk    = (const float*)d_in[7];
    const float* bk    = (const float*)d_in[8];
    const float* Wv    = (const float*)d_in[9];
    const float* bv    = (const float*)d_in[10];
    const float* Wo    = (const float*)d_in[11];
    const float* bo    = (const float*)d_in[12];
    const float* Wf1   = (const float*)d_in[13];
    const float* bf1   = (const float*)d_in[14];
    const float* Wf2   = (const float*)d_in[15];
    const float* bf2   = (const float*)d_in[16];
    const float* ln1a  = (const float*)d_in[17];
    const float* ln1b  = (const float*)d_in[18];
    const float* ln2a  = (const float*)d_in[19];
    const float* ln2b  = (const float*)d_in[20];
    const float* lnfa  = (const float*)d_in[21];
    const float* lnfb  = (const float*)d_in[22];

    float *px;
    __half *pbaseh, *phh, *pqh, *pkh, *pvh, *pt1, *pph, *pwh;
    int *pidx, *pcnt;
    cudaGetSymbolAddress((void**)&px,     g_x);
    cudaGetSymbolAddress((void**)&pbaseh, g_baseh);
    cudaGetSymbolAddress((void**)&phh,    g_hh);
    cudaGetSymbolAddress((void**)&pqh,    g_qh);
    cudaGetSymbolAddress((void**)&pkh,    g_kh);
    cudaGetSymbolAddress((void**)&pvh,    g_vh);
    cudaGetSymbolAddress((void**)&pt1,    g_t1);
    cudaGetSymbolAddress((void**)&pph,    g_ph);
    cudaGetSymbolAddress((void**)&pwh,    g_wh);
    cudaGetSymbolAddress((void**)&pidx,   g_idx);
    cudaGetSymbolAddress((void**)&pcnt,   g_cnt);

    static bool attrDone = false;
    if (!attrDone) {
        cudaFuncSetAttribute(gemm_hh,  cudaFuncAttributeMaxDynamicSharedMemorySize, CA2_SMEM);
        cudaFuncSetAttribute(gemm_hf,  cudaFuncAttributeMaxDynamicSharedMemorySize, CA2_SMEM);
        cudaFuncSetAttribute(gemm_hhz, cudaFuncAttributeMaxDynamicSharedMemorySize, CA2_SMEM);
        cudaFuncSetAttribute(gemm_qkv, cudaFuncAttributeMaxDynamicSharedMemorySize, CA2_SMEM);
        attrDone = true;
    }

    cudaMemcpyAsync(px, x_in, sizeof(float) * BND, cudaMemcpyDeviceToDevice, 0);

    cvt_w<<<(6 * WSZ) / 1024, 256>>>(Wq, Wk, Wv, Wo, Wf1, Wf2, pwh);
    base_kernel<<<Bn * Nn, 256>>>(dist, adj, mask, pbaseh);
    mask_idx_kernel<<<Bn, 512>>>(mask, pidx, pcnt);

    const dim3 gProj(Dn / 128, (Bn * Nn) / 128, 1);   // 128 blocks
    const dim3 gQKV (Dn / 128, (Bn * Nn) / 128, 3);   // 384 blocks
    const dim3 gBaseV(Dn / 128, Nn / 128, Bn);        // 128 blocks
    const dim3 gAttn(Nn / 64, Hn, Bn);                // 1024 blocks
    const dim3 gLN(Bn * Nn / 8, 1, 1);

    for (int i = 0; i < Ln; i++) {
        const size_t wOff = (size_t)i * Dn * Dn;
        const size_t vOff = (size_t)i * Dn;

        ln_h<<<gLN, 256>>>(px, ln1a + vOff, ln1b + vOff, phh);

        gemm_qkv<<<gQKV, 256, CA2_SMEM>>>(phh, pwh + wOff, (long)WSZ,
                                          bq + vOff, bk + vOff, bv + vOff,
                                          pqh, pkh, pvh, Dn, Dn);

        // att = base @ V  (half, K=512)
        gemm_hhz<<<gBaseV, 256, CA2_SMEM>>>(pbaseh, pvh, pph, Dn, Nn,
                                            (long)Nn * Nn, (long)Nn * Dn, (long)Nn * Dn);

        // att += 0.3 * softmax @ V  (mask-compacted, f16x2 exp)
        attn_tc<<<gAttn, 128>>>(pqh, pkh, pvh, pidx, pcnt, pph);

        // x = x + att @ Wo + bo
        gemm_hf<<<gProj, 256, CA2_SMEM>>>(pph, pwh + 3 * WSZ + wOff, bo + vOff, px, px,
                                          Dn, Dn, 0);

        // FFN
        ln_h<<<gLN, 256>>>(px, ln2a + vOff, ln2b + vOff, phh);
        gemm_hh<<<gProj, 256, CA2_SMEM>>>(phh, pwh + 4 * WSZ + wOff, bf1 + vOff, pt1,
                                          Dn, Dn, 1);
        gemm_hf<<<gProj, 256, CA2_SMEM>>>(pt1, pwh + 5 * WSZ + wOff, bf2 + vOff, px, px,
                                          Dn, Dn, 1);
    }

    ln_f<<<gLN, 256>>>(px, lnfa, lnfb, (float*)d_out);
}